// round 1
// baseline (speedup 1.0000x reference)
#include <cuda_runtime.h>
#include <math.h>

#define NQ 8192
#define NS 32768
#define NE 131072
#define DD 256
#define NH 8
#define HDIM 32
#define NGEO 128
#define NFFN 512

// ---------------- scratch (device globals; no allocation) ----------------
__device__ float g_raw[NQ * 12];
__device__ float g_geoh[NQ * NGEO];
__device__ float g_geo[NQ * NGEO];
__device__ float g_qt[NQ * DD];     // LN1 output; reused for LN2 output
__device__ float g_Qf[NQ * DD];
__device__ float g_Kf[NS * DD];
__device__ float g_Vf[NS * DD];
__device__ float g_Gf[NQ * DD];
__device__ float g_ex[NE * NH];     // scores, then exp(score - smax)
__device__ float g_sinv[NQ * NH];
__device__ float g_out[NQ * DD];
__device__ float g_x[NQ * DD];
__device__ float g_h1[NQ * NFFN];
__device__ int   g_rowptr[NQ + 1];

__device__ __forceinline__ float gelu_f(float x) {
    return 0.5f * x * (1.0f + erff(x * 0.7071067811865475f));
}

// ---------------- row_ptr via binary search (q_idx is sorted) ----------------
__global__ void k_rowptr(const int* __restrict__ qidx) {
    int q = blockIdx.x * blockDim.x + threadIdx.x;
    if (q > NQ) return;
    int lo = 0, hi = NE;
    while (lo < hi) {
        int mid = (lo + hi) >> 1;
        if (qidx[mid] < q) lo = mid + 1; else hi = mid;
    }
    g_rowptr[q] = lo;
}

// ---------------- geo stats: warp per query ----------------
__global__ void k_geostats(const float* __restrict__ qpos,
                           const float* __restrict__ spos,
                           const int* __restrict__ sidx) {
    int warp = (blockIdx.x * blockDim.x + threadIdx.x) >> 5;
    int lane = threadIdx.x & 31;
    if (warp >= NQ) return;
    int q = warp;
    int st = g_rowptr[q], en = g_rowptr[q + 1];
    float qp0 = qpos[q * 3 + 0], qp1 = qpos[q * 3 + 1], qp2 = qpos[q * 3 + 2];
    float s0 = 0.f, s1 = 0.f, s2 = 0.f;
    float ss0 = 0.f, ss1 = 0.f, ss2 = 0.f;
    float mn0 = 1e30f, mn1 = 1e30f, mn2 = 1e30f;
    float mx0 = -1e30f, mx1 = -1e30f, mx2 = -1e30f;
    for (int e = st + lane; e < en; e += 32) {
        int s = sidx[e];
        float r0 = spos[s * 3 + 0] - qp0;
        float r1 = spos[s * 3 + 1] - qp1;
        float r2 = spos[s * 3 + 2] - qp2;
        s0 += r0; s1 += r1; s2 += r2;
        ss0 += r0 * r0; ss1 += r1 * r1; ss2 += r2 * r2;
        mn0 = fminf(mn0, r0); mn1 = fminf(mn1, r1); mn2 = fminf(mn2, r2);
        mx0 = fmaxf(mx0, r0); mx1 = fmaxf(mx1, r1); mx2 = fmaxf(mx2, r2);
    }
    #pragma unroll
    for (int off = 16; off > 0; off >>= 1) {
        s0 += __shfl_xor_sync(0xffffffffu, s0, off);
        s1 += __shfl_xor_sync(0xffffffffu, s1, off);
        s2 += __shfl_xor_sync(0xffffffffu, s2, off);
        ss0 += __shfl_xor_sync(0xffffffffu, ss0, off);
        ss1 += __shfl_xor_sync(0xffffffffu, ss1, off);
        ss2 += __shfl_xor_sync(0xffffffffu, ss2, off);
        mn0 = fminf(mn0, __shfl_xor_sync(0xffffffffu, mn0, off));
        mn1 = fminf(mn1, __shfl_xor_sync(0xffffffffu, mn1, off));
        mn2 = fminf(mn2, __shfl_xor_sync(0xffffffffu, mn2, off));
        mx0 = fmaxf(mx0, __shfl_xor_sync(0xffffffffu, mx0, off));
        mx1 = fmaxf(mx1, __shfl_xor_sync(0xffffffffu, mx1, off));
        mx2 = fmaxf(mx2, __shfl_xor_sync(0xffffffffu, mx2, off));
    }
    if (lane == 0) {
        float cnt = fmaxf((float)(en - st), 1.0f);
        float m0 = s0 / cnt, m1 = s1 / cnt, m2 = s2 / cnt;
        float v0 = fmaxf(ss0 / cnt - m0 * m0, 0.f);
        float v1 = fmaxf(ss1 / cnt - m1 * m1, 0.f);
        float v2 = fmaxf(ss2 / cnt - m2 * m2, 0.f);
        float* r = g_raw + q * 12;
        r[0] = m0; r[1] = m1; r[2] = m2;
        r[3] = sqrtf(v0); r[4] = sqrtf(v1); r[5] = sqrtf(v2);
        r[6] = fminf(fmaxf(mn0, -100.f), 100.f);
        r[7] = fminf(fmaxf(mn1, -100.f), 100.f);
        r[8] = fminf(fmaxf(mn2, -100.f), 100.f);
        r[9]  = fminf(fmaxf(mx0, -100.f), 100.f);
        r[10] = fminf(fmaxf(mx1, -100.f), 100.f);
        r[11] = fminf(fmaxf(mx2, -100.f), 100.f);
    }
}

// ---------------- LayerNorm: warp per row (D=256) ----------------
__global__ void k_ln(const float* __restrict__ x, const float* __restrict__ g,
                     const float* __restrict__ b, float* __restrict__ y) {
    int warp = (blockIdx.x * blockDim.x + threadIdx.x) >> 5;
    int lane = threadIdx.x & 31;
    if (warp >= NQ) return;
    const float4* xr = (const float4*)(x + warp * DD);
    float4 a = xr[lane * 2], c = xr[lane * 2 + 1];
    float sum = a.x + a.y + a.z + a.w + c.x + c.y + c.z + c.w;
    float ss = a.x * a.x + a.y * a.y + a.z * a.z + a.w * a.w +
               c.x * c.x + c.y * c.y + c.z * c.z + c.w * c.w;
    #pragma unroll
    for (int off = 16; off > 0; off >>= 1) {
        sum += __shfl_xor_sync(0xffffffffu, sum, off);
        ss  += __shfl_xor_sync(0xffffffffu, ss, off);
    }
    float mean = sum * (1.0f / 256.0f);
    float var = ss * (1.0f / 256.0f) - mean * mean;
    float rstd = rsqrtf(var + 1e-5f);
    const float4* gr = (const float4*)g;
    const float4* br = (const float4*)b;
    float4 g0 = gr[lane * 2], g1 = gr[lane * 2 + 1];
    float4 b0 = br[lane * 2], b1 = br[lane * 2 + 1];
    float4 o0, o1;
    o0.x = (a.x - mean) * rstd * g0.x + b0.x;
    o0.y = (a.y - mean) * rstd * g0.y + b0.y;
    o0.z = (a.z - mean) * rstd * g0.z + b0.z;
    o0.w = (a.w - mean) * rstd * g0.w + b0.w;
    o1.x = (c.x - mean) * rstd * g1.x + b1.x;
    o1.y = (c.y - mean) * rstd * g1.y + b1.y;
    o1.z = (c.z - mean) * rstd * g1.z + b1.z;
    o1.w = (c.w - mean) * rstd * g1.w + b1.w;
    float4* yr = (float4*)(y + warp * DD);
    yr[lane * 2] = o0;
    yr[lane * 2 + 1] = o1;
}

// ---------------- generic tiled fp32 GEMM: C = act(A@B + bias) (+res) ----------------
// A[M,K] row-major, B[K,N] row-major. M%64==0, N%64==0 guaranteed; K guarded.
template <bool BIAS, bool GELU, bool RES>
__global__ void k_gemm(const float* __restrict__ A, const float* __restrict__ B,
                       const float* __restrict__ bias, const float* __restrict__ res,
                       float* __restrict__ C, int M, int N, int K) {
    __shared__ float As[64][17];
    __shared__ float Bs[16][64];
    int tid = threadIdx.x;
    int tx = tid & 15, ty = tid >> 4;
    int m0 = blockIdx.y * 64, n0 = blockIdx.x * 64;
    float acc[4][4] = {};
    int KT = (K + 15) >> 4;
    for (int kt = 0; kt < KT; kt++) {
        int k0 = kt << 4;
        #pragma unroll
        for (int i = 0; i < 4; i++) {
            int lin = tid + i * 256;
            int ar = lin >> 4, ac = lin & 15;
            int gk = k0 + ac;
            As[ar][ac] = (gk < K) ? A[(size_t)(m0 + ar) * K + gk] : 0.f;
        }
        #pragma unroll
        for (int i = 0; i < 4; i++) {
            int lin = tid + i * 256;
            int br = lin >> 6, bc = lin & 63;
            int gk = k0 + br;
            Bs[br][bc] = (gk < K) ? B[(size_t)gk * N + n0 + bc] : 0.f;
        }
        __syncthreads();
        #pragma unroll
        for (int kk = 0; kk < 16; kk++) {
            float av[4];
            #pragma unroll
            for (int i = 0; i < 4; i++) av[i] = As[ty * 4 + i][kk];
            float4 bv = *(const float4*)&Bs[kk][tx * 4];
            float bvv[4] = {bv.x, bv.y, bv.z, bv.w};
            #pragma unroll
            for (int i = 0; i < 4; i++)
                #pragma unroll
                for (int j = 0; j < 4; j++)
                    acc[i][j] = fmaf(av[i], bvv[j], acc[i][j]);
        }
        __syncthreads();
    }
    #pragma unroll
    for (int i = 0; i < 4; i++) {
        int row = m0 + ty * 4 + i;
        #pragma unroll
        for (int j = 0; j < 4; j++) {
            int col = n0 + tx * 4 + j;
            float v = acc[i][j];
            if (BIAS) v += bias[col];
            if (GELU) v = gelu_f(v);
            if (RES) v += res[(size_t)row * N + col];
            C[(size_t)row * N + col] = v;
        }
    }
}

// ---------------- scores: warp per edge, all 8 heads ----------------
__global__ void k_scores(const int* __restrict__ qidx, const int* __restrict__ sidx,
                         const float* __restrict__ log_tau) {
    int warp = (blockIdx.x * blockDim.x + threadIdx.x) >> 5;
    int lane = threadIdx.x & 31;
    if (warp >= NE) return;
    int e = warp;
    int q = qidx[e], s = sidx[e];
    const float4* qr = (const float4*)(g_Qf + (size_t)q * DD);
    const float4* kr = (const float4*)(g_Kf + (size_t)s * DD);
    float4 qa = qr[lane * 2], qb = qr[lane * 2 + 1];
    float4 ka = kr[lane * 2], kb = kr[lane * 2 + 1];
    float d = qa.x * ka.x + qa.y * ka.y + qa.z * ka.z + qa.w * ka.w +
              qb.x * kb.x + qb.y * kb.y + qb.z * kb.z + qb.w * kb.w;
    d += __shfl_xor_sync(0xffffffffu, d, 1);
    d += __shfl_xor_sync(0xffffffffu, d, 2);
    if ((lane & 3) == 0) {
        float scale = 0.17677669529663689f * expf(-log_tau[0]);
        g_ex[(size_t)e * 8 + (lane >> 2)] = d * scale;
    }
}

// ---------------- segmented softmax: warp per query ----------------
__global__ void k_softmax() {
    int warp = (blockIdx.x * blockDim.x + threadIdx.x) >> 5;
    int lane = threadIdx.x & 31;
    if (warp >= NQ) return;
    int q = warp;
    int st = g_rowptr[q], en = g_rowptr[q + 1];
    float m[8];
    #pragma unroll
    for (int h = 0; h < 8; h++) m[h] = -1e30f;
    for (int e = st + lane; e < en; e += 32) {
        float4 v0 = *(const float4*)(g_ex + (size_t)e * 8);
        float4 v1 = *(const float4*)(g_ex + (size_t)e * 8 + 4);
        m[0] = fmaxf(m[0], v0.x); m[1] = fmaxf(m[1], v0.y);
        m[2] = fmaxf(m[2], v0.z); m[3] = fmaxf(m[3], v0.w);
        m[4] = fmaxf(m[4], v1.x); m[5] = fmaxf(m[5], v1.y);
        m[6] = fmaxf(m[6], v1.z); m[7] = fmaxf(m[7], v1.w);
    }
    #pragma unroll
    for (int h = 0; h < 8; h++) {
        #pragma unroll
        for (int off = 16; off > 0; off >>= 1)
            m[h] = fmaxf(m[h], __shfl_xor_sync(0xffffffffu, m[h], off));
        m[h] = fmaxf(m[h], 0.0f);   // torch scores_max init 0
    }
    float sm[8];
    #pragma unroll
    for (int h = 0; h < 8; h++) sm[h] = 0.f;
    for (int e = st + lane; e < en; e += 32) {
        float4 v0 = *(const float4*)(g_ex + (size_t)e * 8);
        float4 v1 = *(const float4*)(g_ex + (size_t)e * 8 + 4);
        v0.x = expf(v0.x - m[0]); v0.y = expf(v0.y - m[1]);
        v0.z = expf(v0.z - m[2]); v0.w = expf(v0.w - m[3]);
        v1.x = expf(v1.x - m[4]); v1.y = expf(v1.y - m[5]);
        v1.z = expf(v1.z - m[6]); v1.w = expf(v1.w - m[7]);
        sm[0] += v0.x; sm[1] += v0.y; sm[2] += v0.z; sm[3] += v0.w;
        sm[4] += v1.x; sm[5] += v1.y; sm[6] += v1.z; sm[7] += v1.w;
        *(float4*)(g_ex + (size_t)e * 8) = v0;
        *(float4*)(g_ex + (size_t)e * 8 + 4) = v1;
    }
    #pragma unroll
    for (int h = 0; h < 8; h++) {
        #pragma unroll
        for (int off = 16; off > 0; off >>= 1)
            sm[h] += __shfl_xor_sync(0xffffffffu, sm[h], off);
    }
    if (lane == 0) {
        #pragma unroll
        for (int h = 0; h < 8; h++)
            g_sinv[q * 8 + h] = 1.0f / fmaxf(sm[h], 1e-8f);
    }
}

// ---------------- weighted segment sum: block(256) per query ----------------
__global__ void k_weighted(const int* __restrict__ sidx) {
    int q = blockIdx.x;
    int tid = threadIdx.x;           // = dim d
    int h = tid >> 5;
    __shared__ float sA[32 * 8];
    __shared__ int sS[32];
    __shared__ float sinv_s[8];
    if (tid < 8) sinv_s[tid] = g_sinv[q * 8 + tid];
    __syncthreads();
    int st = g_rowptr[q], en = g_rowptr[q + 1];
    float acc = 0.f, acca = 0.f;
    for (int base = st; base < en; base += 32) {
        int n = min(32, en - base);
        int el = tid >> 3, hh = tid & 7;
        if (el < n) {
            float a = g_ex[(size_t)(base + el) * 8 + hh] * sinv_s[hh];
            sA[el * 8 + hh] = a;
            if (hh == 0) sS[el] = sidx[base + el];
        }
        __syncthreads();
        for (int i = 0; i < n; i++) {
            float a = sA[i * 8 + h];
            acc = fmaf(a, g_Vf[(size_t)sS[i] * DD + tid], acc);
            acca += a;
        }
        __syncthreads();
    }
    g_out[(size_t)q * DD + tid] = acc + acca * g_Gf[(size_t)q * DD + tid];
}

// ---------------- host launcher ----------------
static float* sym_f(const void* sym) {
    void* p = nullptr;
    cudaGetSymbolAddress(&p, sym);
    return (float*)p;
}

extern "C" void kernel_launch(void* const* d_in, const int* in_sizes, int n_in,
                              void* d_out, int out_size) {
    const float* query_tokens  = (const float*)d_in[0];
    const float* query_pos     = (const float*)d_in[1];
    const float* support_feats = (const float*)d_in[2];
    const float* support_pos   = (const float*)d_in[3];
    const float* Wq   = (const float*)d_in[4];
    const float* Wk   = (const float*)d_in[5];
    const float* Wv   = (const float*)d_in[6];
    const float* Wg   = (const float*)d_in[7];
    const float* Wo   = (const float*)d_in[8];
    const float* bo   = (const float*)d_in[9];
    const float* log_tau = (const float*)d_in[10];
    const float* ln1_g = (const float*)d_in[11];
    const float* ln1_b = (const float*)d_in[12];
    const float* ln2_g = (const float*)d_in[13];
    const float* ln2_b = (const float*)d_in[14];
    const float* Wf1  = (const float*)d_in[15];
    const float* bf1  = (const float*)d_in[16];
    const float* Wf2  = (const float*)d_in[17];
    const float* bf2  = (const float*)d_in[18];
    const float* Gw1  = (const float*)d_in[19];
    const float* Gb1  = (const float*)d_in[20];
    const float* Gw2  = (const float*)d_in[21];
    const float* Gb2  = (const float*)d_in[22];
    const int* q_idx  = (const int*)d_in[23];
    const int* s_idx  = (const int*)d_in[24];
    float* out = (float*)d_out;

    float* p_raw  = sym_f(g_raw);
    float* p_geoh = sym_f(g_geoh);
    float* p_geo  = sym_f(g_geo);
    float* p_qt   = sym_f(g_qt);
    float* p_Qf   = sym_f(g_Qf);
    float* p_Kf   = sym_f(g_Kf);
    float* p_Vf   = sym_f(g_Vf);
    float* p_Gf   = sym_f(g_Gf);
    float* p_out  = sym_f(g_out);
    float* p_x    = sym_f(g_x);
    float* p_h1   = sym_f(g_h1);

    // 1. CSR row pointers
    k_rowptr<<<(NQ + 1 + 255) / 256, 256>>>(q_idx);
    // 2. geo stats
    k_geostats<<<NQ / 8, 256>>>(query_pos, support_pos, s_idx);
    // 3-4. geo MLP
    k_gemm<true, true, false><<<dim3(NGEO / 64, NQ / 64), 256>>>(p_raw, Gw1, Gb1, nullptr, p_geoh, NQ, NGEO, 12);
    k_gemm<true, true, false><<<dim3(NGEO / 64, NQ / 64), 256>>>(p_geoh, Gw2, Gb2, nullptr, p_geo, NQ, NGEO, NGEO);
    // 5. LN1
    k_ln<<<NQ / 8, 256>>>(query_tokens, ln1_g, ln1_b, p_qt);
    // 6-9. projections
    k_gemm<false, false, false><<<dim3(DD / 64, NQ / 64), 256>>>(p_qt, Wq, nullptr, nullptr, p_Qf, NQ, DD, DD);
    k_gemm<false, false, false><<<dim3(DD / 64, NS / 64), 256>>>(support_feats, Wk, nullptr, nullptr, p_Kf, NS, DD, DD);
    k_gemm<false, false, false><<<dim3(DD / 64, NS / 64), 256>>>(support_feats, Wv, nullptr, nullptr, p_Vf, NS, DD, DD);
    k_gemm<false, false, false><<<dim3(DD / 64, NQ / 64), 256>>>(p_geo, Wg, nullptr, nullptr, p_Gf, NQ, DD, NGEO);
    // 10. per-edge scores
    k_scores<<<NE / 8, 256>>>(q_idx, s_idx, log_tau);
    // 11. segmented softmax
    k_softmax<<<NQ / 8, 256>>>();
    // 12. weighted segment sum
    k_weighted<<<NQ, 256>>>(s_idx);
    // 13. attn out projection + residual: x = query_tokens + out@Wo + bo
    k_gemm<true, false, true><<<dim3(DD / 64, NQ / 64), 256>>>(p_out, Wo, bo, query_tokens, p_x, NQ, DD, DD);
    // 14. LN2 (into p_qt, reused)
    k_ln<<<NQ / 8, 256>>>(p_x, ln2_g, ln2_b, p_qt);
    // 15. FFN1 with gelu
    k_gemm<true, true, false><<<dim3(NFFN / 64, NQ / 64), 256>>>(p_qt, Wf1, bf1, nullptr, p_h1, NQ, NFFN, DD);
    // 16. FFN2 + bias + residual -> final output
    k_gemm<true, false, true><<<dim3(DD / 64, NQ / 64), 256>>>(p_h1, Wf2, bf2, p_x, out, NQ, DD, NFFN);
}

// round 2
// speedup vs baseline: 2.1823x; 2.1823x over previous
#include <cuda_runtime.h>
#include <math.h>

#define NQ 8192
#define NS 32768
#define NE 131072
#define DD 256
#define NH 8
#define HDIM 32
#define NGEO 128
#define NFFN 512

// ---------------- scratch (device globals; no allocation) ----------------
__device__ float g_raw[NQ * 12];
__device__ float g_geoh[NQ * NGEO];
__device__ float g_geo[NQ * NGEO];
__device__ float g_qt[NQ * DD];     // LN1 output; reused for LN2 output
__device__ float g_Qf[NQ * DD];
__device__ float g_Kf[NS * DD];
__device__ float g_Vf[NS * DD];
__device__ float g_Gf[NQ * DD];
__device__ float g_ex[NE * NH];     // scores, then exp(score - smax)
__device__ float g_sinv[NQ * NH];
__device__ float g_out[NQ * DD];
__device__ float g_x[NQ * DD];
__device__ float g_h1[NQ * NFFN];
__device__ int   g_rowptr[NQ + 1];

__device__ __forceinline__ float gelu_f(float x) {
    return 0.5f * x * (1.0f + erff(x * 0.7071067811865475f));
}

__device__ __forceinline__ unsigned f2tf32(float x) {
    unsigned y;
    asm("cvt.rna.tf32.f32 %0, %1;" : "=r"(y) : "f"(x));
    return y;
}

// ---------------- row_ptr via binary search (q_idx is sorted) ----------------
__global__ void k_rowptr(const int* __restrict__ qidx) {
    int q = blockIdx.x * blockDim.x + threadIdx.x;
    if (q > NQ) return;
    int lo = 0, hi = NE;
    while (lo < hi) {
        int mid = (lo + hi) >> 1;
        if (qidx[mid] < q) lo = mid + 1; else hi = mid;
    }
    g_rowptr[q] = lo;
}

// ---------------- geo stats: warp per query ----------------
__global__ void k_geostats(const float* __restrict__ qpos,
                           const float* __restrict__ spos,
                           const int* __restrict__ sidx) {
    int warp = (blockIdx.x * blockDim.x + threadIdx.x) >> 5;
    int lane = threadIdx.x & 31;
    if (warp >= NQ) return;
    int q = warp;
    int st = g_rowptr[q], en = g_rowptr[q + 1];
    float qp0 = qpos[q * 3 + 0], qp1 = qpos[q * 3 + 1], qp2 = qpos[q * 3 + 2];
    float s0 = 0.f, s1 = 0.f, s2 = 0.f;
    float ss0 = 0.f, ss1 = 0.f, ss2 = 0.f;
    float mn0 = 1e30f, mn1 = 1e30f, mn2 = 1e30f;
    float mx0 = -1e30f, mx1 = -1e30f, mx2 = -1e30f;
    for (int e = st + lane; e < en; e += 32) {
        int s = sidx[e];
        float r0 = spos[s * 3 + 0] - qp0;
        float r1 = spos[s * 3 + 1] - qp1;
        float r2 = spos[s * 3 + 2] - qp2;
        s0 += r0; s1 += r1; s2 += r2;
        ss0 += r0 * r0; ss1 += r1 * r1; ss2 += r2 * r2;
        mn0 = fminf(mn0, r0); mn1 = fminf(mn1, r1); mn2 = fminf(mn2, r2);
        mx0 = fmaxf(mx0, r0); mx1 = fmaxf(mx1, r1); mx2 = fmaxf(mx2, r2);
    }
    #pragma unroll
    for (int off = 16; off > 0; off >>= 1) {
        s0 += __shfl_xor_sync(0xffffffffu, s0, off);
        s1 += __shfl_xor_sync(0xffffffffu, s1, off);
        s2 += __shfl_xor_sync(0xffffffffu, s2, off);
        ss0 += __shfl_xor_sync(0xffffffffu, ss0, off);
        ss1 += __shfl_xor_sync(0xffffffffu, ss1, off);
        ss2 += __shfl_xor_sync(0xffffffffu, ss2, off);
        mn0 = fminf(mn0, __shfl_xor_sync(0xffffffffu, mn0, off));
        mn1 = fminf(mn1, __shfl_xor_sync(0xffffffffu, mn1, off));
        mn2 = fminf(mn2, __shfl_xor_sync(0xffffffffu, mn2, off));
        mx0 = fmaxf(mx0, __shfl_xor_sync(0xffffffffu, mx0, off));
        mx1 = fmaxf(mx1, __shfl_xor_sync(0xffffffffu, mx1, off));
        mx2 = fmaxf(mx2, __shfl_xor_sync(0xffffffffu, mx2, off));
    }
    if (lane == 0) {
        float cnt = fmaxf((float)(en - st), 1.0f);
        float m0 = s0 / cnt, m1 = s1 / cnt, m2 = s2 / cnt;
        float v0 = fmaxf(ss0 / cnt - m0 * m0, 0.f);
        float v1 = fmaxf(ss1 / cnt - m1 * m1, 0.f);
        float v2 = fmaxf(ss2 / cnt - m2 * m2, 0.f);
        float* r = g_raw + q * 12;
        r[0] = m0; r[1] = m1; r[2] = m2;
        r[3] = sqrtf(v0); r[4] = sqrtf(v1); r[5] = sqrtf(v2);
        r[6] = fminf(fmaxf(mn0, -100.f), 100.f);
        r[7] = fminf(fmaxf(mn1, -100.f), 100.f);
        r[8] = fminf(fmaxf(mn2, -100.f), 100.f);
        r[9]  = fminf(fmaxf(mx0, -100.f), 100.f);
        r[10] = fminf(fmaxf(mx1, -100.f), 100.f);
        r[11] = fminf(fmaxf(mx2, -100.f), 100.f);
    }
}

// ---------------- LayerNorm: warp per row (D=256) ----------------
__global__ void k_ln(const float* __restrict__ x, const float* __restrict__ g,
                     const float* __restrict__ b, float* __restrict__ y) {
    int warp = (blockIdx.x * blockDim.x + threadIdx.x) >> 5;
    int lane = threadIdx.x & 31;
    if (warp >= NQ) return;
    const float4* xr = (const float4*)(x + warp * DD);
    float4 a = xr[lane * 2], c = xr[lane * 2 + 1];
    float sum = a.x + a.y + a.z + a.w + c.x + c.y + c.z + c.w;
    float ss = a.x * a.x + a.y * a.y + a.z * a.z + a.w * a.w +
               c.x * c.x + c.y * c.y + c.z * c.z + c.w * c.w;
    #pragma unroll
    for (int off = 16; off > 0; off >>= 1) {
        sum += __shfl_xor_sync(0xffffffffu, sum, off);
        ss  += __shfl_xor_sync(0xffffffffu, ss, off);
    }
    float mean = sum * (1.0f / 256.0f);
    float var = ss * (1.0f / 256.0f) - mean * mean;
    float rstd = rsqrtf(var + 1e-5f);
    const float4* gr = (const float4*)g;
    const float4* br = (const float4*)b;
    float4 g0 = gr[lane * 2], g1 = gr[lane * 2 + 1];
    float4 b0 = br[lane * 2], b1 = br[lane * 2 + 1];
    float4 o0, o1;
    o0.x = (a.x - mean) * rstd * g0.x + b0.x;
    o0.y = (a.y - mean) * rstd * g0.y + b0.y;
    o0.z = (a.z - mean) * rstd * g0.z + b0.z;
    o0.w = (a.w - mean) * rstd * g0.w + b0.w;
    o1.x = (c.x - mean) * rstd * g1.x + b1.x;
    o1.y = (c.y - mean) * rstd * g1.y + b1.y;
    o1.z = (c.z - mean) * rstd * g1.z + b1.z;
    o1.w = (c.w - mean) * rstd * g1.w + b1.w;
    float4* yr = (float4*)(y + warp * DD);
    yr[lane * 2] = o0;
    yr[lane * 2 + 1] = o1;
}

// ---------------- fp32 GEMM (only for K=12 geo1) ----------------
template <bool BIAS, bool GELU, bool RES>
__global__ void k_gemm(const float* __restrict__ A, const float* __restrict__ B,
                       const float* __restrict__ bias, const float* __restrict__ res,
                       float* __restrict__ C, int M, int N, int K) {
    __shared__ float As[64][17];
    __shared__ float Bs[16][64];
    int tid = threadIdx.x;
    int tx = tid & 15, ty = tid >> 4;
    int m0 = blockIdx.y * 64, n0 = blockIdx.x * 64;
    float acc[4][4] = {};
    int KT = (K + 15) >> 4;
    for (int kt = 0; kt < KT; kt++) {
        int k0 = kt << 4;
        #pragma unroll
        for (int i = 0; i < 4; i++) {
            int lin = tid + i * 256;
            int ar = lin >> 4, ac = lin & 15;
            int gk = k0 + ac;
            As[ar][ac] = (gk < K) ? A[(size_t)(m0 + ar) * K + gk] : 0.f;
        }
        #pragma unroll
        for (int i = 0; i < 4; i++) {
            int lin = tid + i * 256;
            int br = lin >> 6, bc = lin & 63;
            int gk = k0 + br;
            Bs[br][bc] = (gk < K) ? B[(size_t)gk * N + n0 + bc] : 0.f;
        }
        __syncthreads();
        #pragma unroll
        for (int kk = 0; kk < 16; kk++) {
            float av[4];
            #pragma unroll
            for (int i = 0; i < 4; i++) av[i] = As[ty * 4 + i][kk];
            float4 bv = *(const float4*)&Bs[kk][tx * 4];
            float bvv[4] = {bv.x, bv.y, bv.z, bv.w};
            #pragma unroll
            for (int i = 0; i < 4; i++)
                #pragma unroll
                for (int j = 0; j < 4; j++)
                    acc[i][j] = fmaf(av[i], bvv[j], acc[i][j]);
        }
        __syncthreads();
    }
    #pragma unroll
    for (int i = 0; i < 4; i++) {
        int row = m0 + ty * 4 + i;
        #pragma unroll
        for (int j = 0; j < 4; j++) {
            int col = n0 + tx * 4 + j;
            float v = acc[i][j];
            if (BIAS) v += bias[col];
            if (GELU) v = gelu_f(v);
            if (RES) v += res[(size_t)row * N + col];
            C[(size_t)row * N + col] = v;
        }
    }
}

// ---------------- TF32 tensor-core GEMM ----------------
// C[M,N] = act(A[M,K] @ B[K,N] + bias) (+res). M%128==0, N%128==0, K%16==0.
// Block tile 128x128, BK=16, 8 warps (2 x 4), warp tile 64x32, mma m16n8k8.
#define SMS 136   // smem row stride (mod 32 == 8 -> conflict-free frag loads)
template <bool BIAS, bool GELU, bool RES>
__global__ __launch_bounds__(256, 2)
void k_gemm_tf32(const float* __restrict__ A, const float* __restrict__ B,
                 const float* __restrict__ bias, const float* __restrict__ res,
                 float* __restrict__ C, int M, int N, int K) {
    __shared__ unsigned As[16][SMS];   // [k][m] transposed
    __shared__ unsigned Bs[16][SMS];   // [k][n]
    int tid = threadIdx.x;
    int warp = tid >> 5, lane = tid & 31;
    int wm = warp & 1;          // 0..1 -> 64-row slab
    int wn = warp >> 1;         // 0..3 -> 32-col slab
    int g = lane >> 2, t = lane & 3;
    int m0 = blockIdx.y * 128, n0 = blockIdx.x * 128;

    // A-load mapping: thread covers rows (tid>>2) and (tid>>2)+64, quad tid&3
    int ar = tid >> 2, aq = tid & 3;
    // B-load mapping: rows (tid>>5), (tid>>5)+8; col quad tid&31
    int br = tid >> 5, bq = tid & 31;

    float acc[4][4][4];
    #pragma unroll
    for (int i = 0; i < 4; i++)
        #pragma unroll
        for (int j = 0; j < 4; j++)
            #pragma unroll
            for (int c = 0; c < 4; c++) acc[i][j][c] = 0.f;

    int KT = K >> 4;
    for (int kt = 0; kt < KT; kt++) {
        int k0 = kt << 4;
        // load A tile (128x16), store transposed as tf32
        #pragma unroll
        for (int h = 0; h < 2; h++) {
            int row = ar + h * 64;
            float4 v = *(const float4*)&A[(size_t)(m0 + row) * K + k0 + aq * 4];
            As[aq * 4 + 0][row] = f2tf32(v.x);
            As[aq * 4 + 1][row] = f2tf32(v.y);
            As[aq * 4 + 2][row] = f2tf32(v.z);
            As[aq * 4 + 3][row] = f2tf32(v.w);
        }
        // load B tile (16x128) as tf32
        #pragma unroll
        for (int h = 0; h < 2; h++) {
            int row = br + h * 8;
            float4 v = *(const float4*)&B[(size_t)(k0 + row) * N + n0 + bq * 4];
            uint4 u;
            u.x = f2tf32(v.x); u.y = f2tf32(v.y);
            u.z = f2tf32(v.z); u.w = f2tf32(v.w);
            *(uint4*)&Bs[row][bq * 4] = u;
        }
        __syncthreads();
        #pragma unroll
        for (int ks = 0; ks < 16; ks += 8) {
            unsigned a[4][4], b[4][2];
            #pragma unroll
            for (int mi = 0; mi < 4; mi++) {
                int mb = wm * 64 + mi * 16 + g;
                a[mi][0] = As[ks + t][mb];
                a[mi][1] = As[ks + t][mb + 8];
                a[mi][2] = As[ks + t + 4][mb];
                a[mi][3] = As[ks + t + 4][mb + 8];
            }
            #pragma unroll
            for (int ni = 0; ni < 4; ni++) {
                int nb = wn * 32 + ni * 8 + g;
                b[ni][0] = Bs[ks + t][nb];
                b[ni][1] = Bs[ks + t + 4][nb];
            }
            #pragma unroll
            for (int mi = 0; mi < 4; mi++)
                #pragma unroll
                for (int ni = 0; ni < 4; ni++) {
                    asm volatile(
                        "mma.sync.aligned.m16n8k8.row.col.f32.tf32.tf32.f32 "
                        "{%0,%1,%2,%3}, {%4,%5,%6,%7}, {%8,%9}, {%0,%1,%2,%3};"
                        : "+f"(acc[mi][ni][0]), "+f"(acc[mi][ni][1]),
                          "+f"(acc[mi][ni][2]), "+f"(acc[mi][ni][3])
                        : "r"(a[mi][0]), "r"(a[mi][1]), "r"(a[mi][2]), "r"(a[mi][3]),
                          "r"(b[ni][0]), "r"(b[ni][1]));
                }
        }
        __syncthreads();
    }
    // epilogue
    #pragma unroll
    for (int mi = 0; mi < 4; mi++) {
        int mrow = m0 + wm * 64 + mi * 16 + g;
        #pragma unroll
        for (int ni = 0; ni < 4; ni++) {
            int ncol = n0 + wn * 32 + ni * 8 + 2 * t;
            #pragma unroll
            for (int half = 0; half < 2; half++) {
                int row = mrow + half * 8;
                float v0 = acc[mi][ni][half * 2 + 0];
                float v1 = acc[mi][ni][half * 2 + 1];
                if (BIAS) { v0 += bias[ncol]; v1 += bias[ncol + 1]; }
                if (GELU) { v0 = gelu_f(v0); v1 = gelu_f(v1); }
                if (RES) {
                    const float2 r = *(const float2*)&res[(size_t)row * N + ncol];
                    v0 += r.x; v1 += r.y;
                }
                float2 o; o.x = v0; o.y = v1;
                *(float2*)&C[(size_t)row * N + ncol] = o;
            }
        }
    }
}

// ---------------- scores: warp per edge, all 8 heads ----------------
__global__ void k_scores(const int* __restrict__ qidx, const int* __restrict__ sidx,
                         const float* __restrict__ log_tau) {
    int warp = (blockIdx.x * blockDim.x + threadIdx.x) >> 5;
    int lane = threadIdx.x & 31;
    if (warp >= NE) return;
    int e = warp;
    int q = qidx[e], s = sidx[e];
    const float4* qr = (const float4*)(g_Qf + (size_t)q * DD);
    const float4* kr = (const float4*)(g_Kf + (size_t)s * DD);
    float4 qa = qr[lane * 2], qb = qr[lane * 2 + 1];
    float4 ka = kr[lane * 2], kb = kr[lane * 2 + 1];
    float d = qa.x * ka.x + qa.y * ka.y + qa.z * ka.z + qa.w * ka.w +
              qb.x * kb.x + qb.y * kb.y + qb.z * kb.z + qb.w * kb.w;
    d += __shfl_xor_sync(0xffffffffu, d, 1);
    d += __shfl_xor_sync(0xffffffffu, d, 2);
    if ((lane & 3) == 0) {
        float scale = 0.17677669529663689f * expf(-log_tau[0]);
        g_ex[(size_t)e * 8 + (lane >> 2)] = d * scale;
    }
}

// ---------------- segmented softmax: warp per query ----------------
__global__ void k_softmax() {
    int warp = (blockIdx.x * blockDim.x + threadIdx.x) >> 5;
    int lane = threadIdx.x & 31;
    if (warp >= NQ) return;
    int q = warp;
    int st = g_rowptr[q], en = g_rowptr[q + 1];
    float m[8];
    #pragma unroll
    for (int h = 0; h < 8; h++) m[h] = -1e30f;
    for (int e = st + lane; e < en; e += 32) {
        float4 v0 = *(const float4*)(g_ex + (size_t)e * 8);
        float4 v1 = *(const float4*)(g_ex + (size_t)e * 8 + 4);
        m[0] = fmaxf(m[0], v0.x); m[1] = fmaxf(m[1], v0.y);
        m[2] = fmaxf(m[2], v0.z); m[3] = fmaxf(m[3], v0.w);
        m[4] = fmaxf(m[4], v1.x); m[5] = fmaxf(m[5], v1.y);
        m[6] = fmaxf(m[6], v1.z); m[7] = fmaxf(m[7], v1.w);
    }
    #pragma unroll
    for (int h = 0; h < 8; h++) {
        #pragma unroll
        for (int off = 16; off > 0; off >>= 1)
            m[h] = fmaxf(m[h], __shfl_xor_sync(0xffffffffu, m[h], off));
        m[h] = fmaxf(m[h], 0.0f);
    }
    float sm[8];
    #pragma unroll
    for (int h = 0; h < 8; h++) sm[h] = 0.f;
    for (int e = st + lane; e < en; e += 32) {
        float4 v0 = *(const float4*)(g_ex + (size_t)e * 8);
        float4 v1 = *(const float4*)(g_ex + (size_t)e * 8 + 4);
        v0.x = expf(v0.x - m[0]); v0.y = expf(v0.y - m[1]);
        v0.z = expf(v0.z - m[2]); v0.w = expf(v0.w - m[3]);
        v1.x = expf(v1.x - m[4]); v1.y = expf(v1.y - m[5]);
        v1.z = expf(v1.z - m[6]); v1.w = expf(v1.w - m[7]);
        sm[0] += v0.x; sm[1] += v0.y; sm[2] += v0.z; sm[3] += v0.w;
        sm[4] += v1.x; sm[5] += v1.y; sm[6] += v1.z; sm[7] += v1.w;
        *(float4*)(g_ex + (size_t)e * 8) = v0;
        *(float4*)(g_ex + (size_t)e * 8 + 4) = v1;
    }
    #pragma unroll
    for (int h = 0; h < 8; h++) {
        #pragma unroll
        for (int off = 16; off > 0; off >>= 1)
            sm[h] += __shfl_xor_sync(0xffffffffu, sm[h], off);
    }
    if (lane == 0) {
        #pragma unroll
        for (int h = 0; h < 8; h++)
            g_sinv[q * 8 + h] = 1.0f / fmaxf(sm[h], 1e-8f);
    }
}

// ---------------- weighted segment sum: block(256) per query ----------------
__global__ void k_weighted(const int* __restrict__ sidx) {
    int q = blockIdx.x;
    int tid = threadIdx.x;           // = dim d
    int h = tid >> 5;
    __shared__ float sA[32 * 8];
    __shared__ int sS[32];
    __shared__ float sinv_s[8];
    if (tid < 8) sinv_s[tid] = g_sinv[q * 8 + tid];
    __syncthreads();
    int st = g_rowptr[q], en = g_rowptr[q + 1];
    float acc = 0.f, acca = 0.f;
    for (int base = st; base < en; base += 32) {
        int n = min(32, en - base);
        int el = tid >> 3, hh = tid & 7;
        if (el < n) {
            float a = g_ex[(size_t)(base + el) * 8 + hh] * sinv_s[hh];
            sA[el * 8 + hh] = a;
            if (hh == 0) sS[el] = sidx[base + el];
        }
        __syncthreads();
        for (int i = 0; i < n; i++) {
            float a = sA[i * 8 + h];
            acc = fmaf(a, g_Vf[(size_t)sS[i] * DD + tid], acc);
            acca += a;
        }
        __syncthreads();
    }
    g_out[(size_t)q * DD + tid] = acc + acca * g_Gf[(size_t)q * DD + tid];
}

// ---------------- host launcher ----------------
static float* sym_f(const void* sym) {
    void* p = nullptr;
    cudaGetSymbolAddress(&p, sym);
    return (float*)p;
}

extern "C" void kernel_launch(void* const* d_in, const int* in_sizes, int n_in,
                              void* d_out, int out_size) {
    const float* query_tokens  = (const float*)d_in[0];
    const float* query_pos     = (const float*)d_in[1];
    const float* support_feats = (const float*)d_in[2];
    const float* support_pos   = (const float*)d_in[3];
    const float* Wq   = (const float*)d_in[4];
    const float* Wk   = (const float*)d_in[5];
    const float* Wv   = (const float*)d_in[6];
    const float* Wg   = (const float*)d_in[7];
    const float* Wo   = (const float*)d_in[8];
    const float* bo   = (const float*)d_in[9];
    const float* log_tau = (const float*)d_in[10];
    const float* ln1_g = (const float*)d_in[11];
    const float* ln1_b = (const float*)d_in[12];
    const float* ln2_g = (const float*)d_in[13];
    const float* ln2_b = (const float*)d_in[14];
    const float* Wf1  = (const float*)d_in[15];
    const float* bf1  = (const float*)d_in[16];
    const float* Wf2  = (const float*)d_in[17];
    const float* bf2  = (const float*)d_in[18];
    const float* Gw1  = (const float*)d_in[19];
    const float* Gb1  = (const float*)d_in[20];
    const float* Gw2  = (const float*)d_in[21];
    const float* Gb2  = (const float*)d_in[22];
    const int* q_idx  = (const int*)d_in[23];
    const int* s_idx  = (const int*)d_in[24];
    float* out = (float*)d_out;

    float* p_raw  = sym_f(g_raw);
    float* p_geoh = sym_f(g_geoh);
    float* p_geo  = sym_f(g_geo);
    float* p_qt   = sym_f(g_qt);
    float* p_Qf   = sym_f(g_Qf);
    float* p_Kf   = sym_f(g_Kf);
    float* p_Vf   = sym_f(g_Vf);
    float* p_Gf   = sym_f(g_Gf);
    float* p_out  = sym_f(g_out);
    float* p_x    = sym_f(g_x);
    float* p_h1   = sym_f(g_h1);

    // 1. CSR row pointers
    k_rowptr<<<(NQ + 1 + 255) / 256, 256>>>(q_idx);
    // 2. geo stats
    k_geostats<<<NQ / 8, 256>>>(query_pos, support_pos, s_idx);
    // 3. geo MLP layer 1 (K=12 -> fp32 kernel)
    k_gemm<true, true, false><<<dim3(NGEO / 64, NQ / 64), 256>>>(p_raw, Gw1, Gb1, nullptr, p_geoh, NQ, NGEO, 12);
    // 4. geo MLP layer 2 (tf32)
    k_gemm_tf32<true, true, false><<<dim3(NGEO / 128, NQ / 128), 256>>>(p_geoh, Gw2, Gb2, nullptr, p_geo, NQ, NGEO, NGEO);
    // 5. LN1
    k_ln<<<NQ / 8, 256>>>(query_tokens, ln1_g, ln1_b, p_qt);
    // 6-9. projections (tf32)
    k_gemm_tf32<false, false, false><<<dim3(DD / 128, NQ / 128), 256>>>(p_qt, Wq, nullptr, nullptr, p_Qf, NQ, DD, DD);
    k_gemm_tf32<false, false, false><<<dim3(DD / 128, NS / 128), 256>>>(support_feats, Wk, nullptr, nullptr, p_Kf, NS, DD, DD);
    k_gemm_tf32<false, false, false><<<dim3(DD / 128, NS / 128), 256>>>(support_feats, Wv, nullptr, nullptr, p_Vf, NS, DD, DD);
    k_gemm_tf32<false, false, false><<<dim3(DD / 128, NQ / 128), 256>>>(p_geo, Wg, nullptr, nullptr, p_Gf, NQ, DD, NGEO);
    // 10. per-edge scores
    k_scores<<<NE / 8, 256>>>(q_idx, s_idx, log_tau);
    // 11. segmented softmax
    k_softmax<<<NQ / 8, 256>>>();
    // 12. weighted segment sum
    k_weighted<<<NQ, 256>>>(s_idx);
    // 13. attn out projection + residual (tf32)
    k_gemm_tf32<true, false, true><<<dim3(DD / 128, NQ / 128), 256>>>(p_out, Wo, bo, query_tokens, p_x, NQ, DD, DD);
    // 14. LN2 (into p_qt, reused)
    k_ln<<<NQ / 8, 256>>>(p_x, ln2_g, ln2_b, p_qt);
    // 15. FFN1 with gelu (tf32)
    k_gemm_tf32<true, true, false><<<dim3(NFFN / 128, NQ / 128), 256>>>(p_qt, Wf1, bf1, nullptr, p_h1, NQ, NFFN, DD);
    // 16. FFN2 + bias + residual -> final output (tf32)
    k_gemm_tf32<true, false, true><<<dim3(DD / 128, NQ / 128), 256>>>(p_h1, Wf2, bf2, p_x, out, NQ, DD, NFFN);
}

// round 4
// speedup vs baseline: 3.2344x; 1.4821x over previous
#include <cuda_runtime.h>
#include <math.h>

#define NQ 8192
#define NS 32768
#define NE 131072
#define DD 256
#define NH 8
#define HDIM 32
#define NGEO 128
#define NFFN 512

// ---------------- scratch (device globals; no allocation) ----------------
__device__ float g_raw[NQ * 12];
__device__ float g_geoh[NQ * NGEO];
__device__ float g_geo[NQ * NGEO];
__device__ float g_qt[NQ * DD];     // LN1 output; reused for LN2 output
__device__ float g_Qf[NQ * DD];
__device__ float g_Kf[NS * DD];
__device__ float g_Vf[NS * DD];
__device__ float g_Gf[NQ * DD];
__device__ float g_ex[NE * NH];     // scores, then exp(score - smax)
__device__ float g_sinv[NQ * NH];
__device__ float g_out[NQ * DD];
__device__ float g_x[NQ * DD];
__device__ float g_h1[NQ * NFFN];
__device__ int   g_rowptr[NQ + 1];

__device__ __forceinline__ float gelu_f(float x) {
    return 0.5f * x * (1.0f + erff(x * 0.7071067811865475f));
}

__device__ __forceinline__ void cpa16(float* dst, const float* src) {
    unsigned d = (unsigned)__cvta_generic_to_shared(dst);
    asm volatile("cp.async.cg.shared.global [%0], [%1], 16;" :: "r"(d), "l"(src));
}

// ---------------- row_ptr via binary search (q_idx is sorted) ----------------
__global__ void k_rowptr(const int* __restrict__ qidx) {
    int q = blockIdx.x * blockDim.x + threadIdx.x;
    if (q > NQ) return;
    int lo = 0, hi = NE;
    while (lo < hi) {
        int mid = (lo + hi) >> 1;
        if (qidx[mid] < q) lo = mid + 1; else hi = mid;
    }
    g_rowptr[q] = lo;
}

// ---------------- geo stats: warp per query ----------------
__global__ void k_geostats(const float* __restrict__ qpos,
                           const float* __restrict__ spos,
                           const int* __restrict__ sidx) {
    int warp = (blockIdx.x * blockDim.x + threadIdx.x) >> 5;
    int lane = threadIdx.x & 31;
    if (warp >= NQ) return;
    int q = warp;
    int st = g_rowptr[q], en = g_rowptr[q + 1];
    float qp0 = qpos[q * 3 + 0], qp1 = qpos[q * 3 + 1], qp2 = qpos[q * 3 + 2];
    float s0 = 0.f, s1 = 0.f, s2 = 0.f;
    float ss0 = 0.f, ss1 = 0.f, ss2 = 0.f;
    float mn0 = 1e30f, mn1 = 1e30f, mn2 = 1e30f;
    float mx0 = -1e30f, mx1 = -1e30f, mx2 = -1e30f;
    for (int e = st + lane; e < en; e += 32) {
        int s = sidx[e];
        float r0 = spos[s * 3 + 0] - qp0;
        float r1 = spos[s * 3 + 1] - qp1;
        float r2 = spos[s * 3 + 2] - qp2;
        s0 += r0; s1 += r1; s2 += r2;
        ss0 += r0 * r0; ss1 += r1 * r1; ss2 += r2 * r2;
        mn0 = fminf(mn0, r0); mn1 = fminf(mn1, r1); mn2 = fminf(mn2, r2);
        mx0 = fmaxf(mx0, r0); mx1 = fmaxf(mx1, r1); mx2 = fmaxf(mx2, r2);
    }
    #pragma unroll
    for (int off = 16; off > 0; off >>= 1) {
        s0 += __shfl_xor_sync(0xffffffffu, s0, off);
        s1 += __shfl_xor_sync(0xffffffffu, s1, off);
        s2 += __shfl_xor_sync(0xffffffffu, s2, off);
        ss0 += __shfl_xor_sync(0xffffffffu, ss0, off);
        ss1 += __shfl_xor_sync(0xffffffffu, ss1, off);
        ss2 += __shfl_xor_sync(0xffffffffu, ss2, off);
        mn0 = fminf(mn0, __shfl_xor_sync(0xffffffffu, mn0, off));
        mn1 = fminf(mn1, __shfl_xor_sync(0xffffffffu, mn1, off));
        mn2 = fminf(mn2, __shfl_xor_sync(0xffffffffu, mn2, off));
        mx0 = fmaxf(mx0, __shfl_xor_sync(0xffffffffu, mx0, off));
        mx1 = fmaxf(mx1, __shfl_xor_sync(0xffffffffu, mx1, off));
        mx2 = fmaxf(mx2, __shfl_xor_sync(0xffffffffu, mx2, off));
    }
    if (lane == 0) {
        float cnt = fmaxf((float)(en - st), 1.0f);
        float m0 = s0 / cnt, m1 = s1 / cnt, m2 = s2 / cnt;
        float v0 = fmaxf(ss0 / cnt - m0 * m0, 0.f);
        float v1 = fmaxf(ss1 / cnt - m1 * m1, 0.f);
        float v2 = fmaxf(ss2 / cnt - m2 * m2, 0.f);
        float* r = g_raw + q * 12;
        r[0] = m0; r[1] = m1; r[2] = m2;
        r[3] = sqrtf(v0); r[4] = sqrtf(v1); r[5] = sqrtf(v2);
        r[6] = fminf(fmaxf(mn0, -100.f), 100.f);
        r[7] = fminf(fmaxf(mn1, -100.f), 100.f);
        r[8] = fminf(fmaxf(mn2, -100.f), 100.f);
        r[9]  = fminf(fmaxf(mx0, -100.f), 100.f);
        r[10] = fminf(fmaxf(mx1, -100.f), 100.f);
        r[11] = fminf(fmaxf(mx2, -100.f), 100.f);
    }
}

// ---------------- LayerNorm: warp per row (D=256) ----------------
__global__ void k_ln(const float* __restrict__ x, const float* __restrict__ g,
                     const float* __restrict__ b, float* __restrict__ y) {
    int warp = (blockIdx.x * blockDim.x + threadIdx.x) >> 5;
    int lane = threadIdx.x & 31;
    if (warp >= NQ) return;
    const float4* xr = (const float4*)(x + warp * DD);
    float4 a = xr[lane * 2], c = xr[lane * 2 + 1];
    float sum = a.x + a.y + a.z + a.w + c.x + c.y + c.z + c.w;
    float ss = a.x * a.x + a.y * a.y + a.z * a.z + a.w * a.w +
               c.x * c.x + c.y * c.y + c.z * c.z + c.w * c.w;
    #pragma unroll
    for (int off = 16; off > 0; off >>= 1) {
        sum += __shfl_xor_sync(0xffffffffu, sum, off);
        ss  += __shfl_xor_sync(0xffffffffu, ss, off);
    }
    float mean = sum * (1.0f / 256.0f);
    float var = ss * (1.0f / 256.0f) - mean * mean;
    float rstd = rsqrtf(var + 1e-5f);
    const float4* gr = (const float4*)g;
    const float4* br = (const float4*)b;
    float4 g0 = gr[lane * 2], g1 = gr[lane * 2 + 1];
    float4 b0 = br[lane * 2], b1 = br[lane * 2 + 1];
    float4 o0, o1;
    o0.x = (a.x - mean) * rstd * g0.x + b0.x;
    o0.y = (a.y - mean) * rstd * g0.y + b0.y;
    o0.z = (a.z - mean) * rstd * g0.z + b0.z;
    o0.w = (a.w - mean) * rstd * g0.w + b0.w;
    o1.x = (c.x - mean) * rstd * g1.x + b1.x;
    o1.y = (c.y - mean) * rstd * g1.y + b1.y;
    o1.z = (c.z - mean) * rstd * g1.z + b1.z;
    o1.w = (c.w - mean) * rstd * g1.w + b1.w;
    float4* yr = (float4*)(y + warp * DD);
    yr[lane * 2] = o0;
    yr[lane * 2 + 1] = o1;
}

// ---------------- fp32 GEMM (only for K=12 geo1) ----------------
template <bool BIAS, bool GELU, bool RES>
__global__ void k_gemm(const float* __restrict__ A, const float* __restrict__ B,
                       const float* __restrict__ bias, const float* __restrict__ res,
                       float* __restrict__ C, int M, int N, int K) {
    __shared__ float As[64][17];
    __shared__ float Bs[16][64];
    int tid = threadIdx.x;
    int tx = tid & 15, ty = tid >> 4;
    int m0 = blockIdx.y * 64, n0 = blockIdx.x * 64;
    float acc[4][4] = {};
    int KT = (K + 15) >> 4;
    for (int kt = 0; kt < KT; kt++) {
        int k0 = kt << 4;
        #pragma unroll
        for (int i = 0; i < 4; i++) {
            int lin = tid + i * 256;
            int ar = lin >> 4, ac = lin & 15;
            int gk = k0 + ac;
            As[ar][ac] = (gk < K) ? A[(size_t)(m0 + ar) * K + gk] : 0.f;
        }
        #pragma unroll
        for (int i = 0; i < 4; i++) {
            int lin = tid + i * 256;
            int br = lin >> 6, bc = lin & 63;
            int gk = k0 + br;
            Bs[br][bc] = (gk < K) ? B[(size_t)gk * N + n0 + bc] : 0.f;
        }
        __syncthreads();
        #pragma unroll
        for (int kk = 0; kk < 16; kk++) {
            float av[4];
            #pragma unroll
            for (int i = 0; i < 4; i++) av[i] = As[ty * 4 + i][kk];
            float4 bv = *(const float4*)&Bs[kk][tx * 4];
            float bvv[4] = {bv.x, bv.y, bv.z, bv.w};
            #pragma unroll
            for (int i = 0; i < 4; i++)
                #pragma unroll
                for (int j = 0; j < 4; j++)
                    acc[i][j] = fmaf(av[i], bvv[j], acc[i][j]);
        }
        __syncthreads();
    }
    #pragma unroll
    for (int i = 0; i < 4; i++) {
        int row = m0 + ty * 4 + i;
        #pragma unroll
        for (int j = 0; j < 4; j++) {
            int col = n0 + tx * 4 + j;
            float v = acc[i][j];
            if (BIAS) v += bias[col];
            if (GELU) v = gelu_f(v);
            if (RES) v += res[(size_t)row * N + col];
            C[(size_t)row * N + col] = v;
        }
    }
}

// ---------------- TF32 tensor-core GEMM, cp.async double-buffered ----------------
template <int BM, bool BIAS, bool GELU, bool RES>
__global__ __launch_bounds__(256, 2)
void k_gemm_tc(const float* __restrict__ A, const float* __restrict__ B,
               const float* __restrict__ bias, const float* __restrict__ res,
               float* __restrict__ C, int M, int N, int K) {
    constexpr int SA = 20, SB = 136;
    constexpr int MI = BM / 32;
    __shared__ float As[2][BM][SA];
    __shared__ float Bs[2][16][SB];
    int tid = threadIdx.x;
    int warp = tid >> 5, lane = tid & 31;
    int wm = warp & 1, wn = warp >> 1;
    int g = lane >> 2, t = lane & 3;
    int m0 = blockIdx.y * BM, n0 = blockIdx.x * 128;

    int arow = tid >> 2, aq = (tid & 3) * 4;
    int brow = tid >> 5, bq = (tid & 31) * 4;
    const float* Ag = A + (size_t)(m0 + arow) * K + aq;
    const float* Bg = B + (size_t)brow * N + n0 + bq;

    float acc[MI][4][4];
    #pragma unroll
    for (int i = 0; i < MI; i++)
        #pragma unroll
        for (int j = 0; j < 4; j++)
            #pragma unroll
            for (int c = 0; c < 4; c++) acc[i][j][c] = 0.f;

    int KT = K >> 4;
    #pragma unroll
    for (int h = 0; h < BM / 64; h++)
        cpa16(&As[0][arow + h * 64][aq], Ag + (size_t)(h * 64) * K);
    #pragma unroll
    for (int h = 0; h < 2; h++)
        cpa16(&Bs[0][brow + h * 8][bq], Bg + (size_t)(h * 8) * N);
    asm volatile("cp.async.commit_group;");

    int buf = 0;
    for (int kt = 0; kt < KT; kt++) {
        if (kt + 1 < KT) {
            int k0 = (kt + 1) << 4;
            #pragma unroll
            for (int h = 0; h < BM / 64; h++)
                cpa16(&As[buf ^ 1][arow + h * 64][aq], Ag + (size_t)(h * 64) * K + k0);
            #pragma unroll
            for (int h = 0; h < 2; h++)
                cpa16(&Bs[buf ^ 1][brow + h * 8][bq], Bg + (size_t)(k0 + h * 8) * N);
            asm volatile("cp.async.commit_group;");
            asm volatile("cp.async.wait_group 1;");
        } else {
            asm volatile("cp.async.wait_group 0;");
        }
        __syncthreads();
        #pragma unroll
        for (int ks = 0; ks < 16; ks += 8) {
            unsigned a[MI][4], b[4][2];
            #pragma unroll
            for (int mi = 0; mi < MI; mi++) {
                int mb = wm * (BM / 2) + mi * 16 + g;
                a[mi][0] = __float_as_uint(As[buf][mb][ks + t]);
                a[mi][1] = __float_as_uint(As[buf][mb + 8][ks + t]);
                a[mi][2] = __float_as_uint(As[buf][mb][ks + t + 4]);
                a[mi][3] = __float_as_uint(As[buf][mb + 8][ks + t + 4]);
            }
            #pragma unroll
            for (int ni = 0; ni < 4; ni++) {
                int nb = wn * 32 + ni * 8 + g;
                b[ni][0] = __float_as_uint(Bs[buf][ks + t][nb]);
                b[ni][1] = __float_as_uint(Bs[buf][ks + t + 4][nb]);
            }
            #pragma unroll
            for (int mi = 0; mi < MI; mi++)
                #pragma unroll
                for (int ni = 0; ni < 4; ni++) {
                    asm volatile(
                        "mma.sync.aligned.m16n8k8.row.col.f32.tf32.tf32.f32 "
                        "{%0,%1,%2,%3}, {%4,%5,%6,%7}, {%8,%9}, {%0,%1,%2,%3};"
                        : "+f"(acc[mi][ni][0]), "+f"(acc[mi][ni][1]),
                          "+f"(acc[mi][ni][2]), "+f"(acc[mi][ni][3])
                        : "r"(a[mi][0]), "r"(a[mi][1]), "r"(a[mi][2]), "r"(a[mi][3]),
                          "r"(b[ni][0]), "r"(b[ni][1]));
                }
        }
        buf ^= 1;
        __syncthreads();
    }
    #pragma unroll
    for (int mi = 0; mi < MI; mi++) {
        int mrow = m0 + wm * (BM / 2) + mi * 16 + g;
        #pragma unroll
        for (int ni = 0; ni < 4; ni++) {
            int ncol = n0 + wn * 32 + ni * 8 + 2 * t;
            #pragma unroll
            for (int half = 0; half < 2; half++) {
                int row = mrow + half * 8;
                float v0 = acc[mi][ni][half * 2 + 0];
                float v1 = acc[mi][ni][half * 2 + 1];
                if (BIAS) { v0 += bias[ncol]; v1 += bias[ncol + 1]; }
                if (GELU) { v0 = gelu_f(v0); v1 = gelu_f(v1); }
                if (RES) {
                    const float2 r = *(const float2*)&res[(size_t)row * N + ncol];
                    v0 += r.x; v1 += r.y;
                }
                float2 o; o.x = v0; o.y = v1;
                *(float2*)&C[(size_t)row * N + ncol] = o;
            }
        }
    }
}

// ---------------- scores: warp per edge, all 8 heads ----------------
__global__ void k_scores(const int* __restrict__ qidx, const int* __restrict__ sidx,
                         const float* __restrict__ log_tau) {
    int warp = (blockIdx.x * blockDim.x + threadIdx.x) >> 5;
    int lane = threadIdx.x & 31;
    if (warp >= NE) return;
    int e = warp;
    int q = qidx[e], s = sidx[e];
    const float4* qr = (const float4*)(g_Qf + (size_t)q * DD);
    const float4* kr = (const float4*)(g_Kf + (size_t)s * DD);
    float4 qa = qr[lane * 2], qb = qr[lane * 2 + 1];
    float4 ka = kr[lane * 2], kb = kr[lane * 2 + 1];
    float d = qa.x * ka.x + qa.y * ka.y + qa.z * ka.z + qa.w * ka.w +
              qb.x * kb.x + qb.y * kb.y + qb.z * kb.z + qb.w * kb.w;
    d += __shfl_xor_sync(0xffffffffu, d, 1);
    d += __shfl_xor_sync(0xffffffffu, d, 2);
    if ((lane & 3) == 0) {
        float scale = 0.17677669529663689f * expf(-log_tau[0]);
        g_ex[(size_t)e * 8 + (lane >> 2)] = d * scale;
    }
}

// ---------------- segmented softmax: warp per query ----------------
__global__ void k_softmax() {
    int warp = (blockIdx.x * blockDim.x + threadIdx.x) >> 5;
    int lane = threadIdx.x & 31;
    if (warp >= NQ) return;
    int q = warp;
    int st = g_rowptr[q], en = g_rowptr[q + 1];
    float m[8];
    #pragma unroll
    for (int h = 0; h < 8; h++) m[h] = -1e30f;
    for (int e = st + lane; e < en; e += 32) {
        float4 v0 = *(const float4*)(g_ex + (size_t)e * 8);
        float4 v1 = *(const float4*)(g_ex + (size_t)e * 8 + 4);
        m[0] = fmaxf(m[0], v0.x); m[1] = fmaxf(m[1], v0.y);
        m[2] = fmaxf(m[2], v0.z); m[3] = fmaxf(m[3], v0.w);
        m[4] = fmaxf(m[4], v1.x); m[5] = fmaxf(m[5], v1.y);
        m[6] = fmaxf(m[6], v1.z); m[7] = fmaxf(m[7], v1.w);
    }
    #pragma unroll
    for (int h = 0; h < 8; h++) {
        #pragma unroll
        for (int off = 16; off > 0; off >>= 1)
            m[h] = fmaxf(m[h], __shfl_xor_sync(0xffffffffu, m[h], off));
        m[h] = fmaxf(m[h], 0.0f);
    }
    float sm[8];
    #pragma unroll
    for (int h = 0; h < 8; h++) sm[h] = 0.f;
    for (int e = st + lane; e < en; e += 32) {
        float4 v0 = *(const float4*)(g_ex + (size_t)e * 8);
        float4 v1 = *(const float4*)(g_ex + (size_t)e * 8 + 4);
        v0.x = expf(v0.x - m[0]); v0.y = expf(v0.y - m[1]);
        v0.z = expf(v0.z - m[2]); v0.w = expf(v0.w - m[3]);
        v1.x = expf(v1.x - m[4]); v1.y = expf(v1.y - m[5]);
        v1.z = expf(v1.z - m[6]); v1.w = expf(v1.w - m[7]);
        sm[0] += v0.x; sm[1] += v0.y; sm[2] += v0.z; sm[3] += v0.w;
        sm[4] += v1.x; sm[5] += v1.y; sm[6] += v1.z; sm[7] += v1.w;
        *(float4*)(g_ex + (size_t)e * 8) = v0;
        *(float4*)(g_ex + (size_t)e * 8 + 4) = v1;
    }
    #pragma unroll
    for (int h = 0; h < 8; h++) {
        #pragma unroll
        for (int off = 16; off > 0; off >>= 1)
            sm[h] += __shfl_xor_sync(0xffffffffu, sm[h], off);
    }
    if (lane == 0) {
        #pragma unroll
        for (int h = 0; h < 8; h++)
            g_sinv[q * 8 + h] = 1.0f / fmaxf(sm[h], 1e-8f);
    }
}

// ---------------- weighted segment sum: block(256) per query ----------------
__global__ void k_weighted(const int* __restrict__ sidx) {
    int q = blockIdx.x;
    int tid = threadIdx.x;           // = dim d
    int h = tid >> 5;
    __shared__ float sA[32 * 8];
    __shared__ int sS[32];
    __shared__ float sinv_s[8];
    if (tid < 8) sinv_s[tid] = g_sinv[q * 8 + tid];
    __syncthreads();
    int st = g_rowptr[q], en = g_rowptr[q + 1];
    float acc = 0.f, acca = 0.f;
    for (int base = st; base < en; base += 32) {
        int n = min(32, en - base);
        int el = tid >> 3, hh = tid & 7;
        if (el < n) {
            float a = g_ex[(size_t)(base + el) * 8 + hh] * sinv_s[hh];
            sA[el * 8 + hh] = a;
            if (hh == 0) sS[el] = sidx[base + el];
        }
        __syncthreads();
        for (int i = 0; i < n; i++) {
            float a = sA[i * 8 + h];
            acc = fmaf(a, g_Vf[(size_t)sS[i] * DD + tid], acc);
            acca += a;
        }
        __syncthreads();
    }
    g_out[(size_t)q * DD + tid] = acc + acca * g_Gf[(size_t)q * DD + tid];
}

// ---------------- host launcher ----------------
static float* sym_f(const void* sym) {
    void* p = nullptr;
    cudaGetSymbolAddress(&p, sym);
    return (float*)p;
}

// Streams/events created exactly once (first, non-captured correctness call)
// and reused for every subsequent call, so no device-side pool allocation
// occurs after the harness's pre-capture baseline. The launched work is
// identical on every call.
struct Ctx {
    cudaStream_t s1, s2;
    cudaEvent_t evRoot, evK, evV, evG, evRP;
    Ctx() {
        cudaStreamCreateWithFlags(&s1, cudaStreamNonBlocking);
        cudaStreamCreateWithFlags(&s2, cudaStreamNonBlocking);
        cudaEventCreateWithFlags(&evRoot, cudaEventDisableTiming);
        cudaEventCreateWithFlags(&evK, cudaEventDisableTiming);
        cudaEventCreateWithFlags(&evV, cudaEventDisableTiming);
        cudaEventCreateWithFlags(&evG, cudaEventDisableTiming);
        cudaEventCreateWithFlags(&evRP, cudaEventDisableTiming);
    }
};

extern "C" void kernel_launch(void* const* d_in, const int* in_sizes, int n_in,
                              void* d_out, int out_size) {
    const float* query_tokens  = (const float*)d_in[0];
    const float* query_pos     = (const float*)d_in[1];
    const float* support_feats = (const float*)d_in[2];
    const float* support_pos   = (const float*)d_in[3];
    const float* Wq   = (const float*)d_in[4];
    const float* Wk   = (const float*)d_in[5];
    const float* Wv   = (const float*)d_in[6];
    const float* Wg   = (const float*)d_in[7];
    const float* Wo   = (const float*)d_in[8];
    const float* bo   = (const float*)d_in[9];
    const float* log_tau = (const float*)d_in[10];
    const float* ln1_g = (const float*)d_in[11];
    const float* ln1_b = (const float*)d_in[12];
    const float* ln2_g = (const float*)d_in[13];
    const float* ln2_b = (const float*)d_in[14];
    const float* Wf1  = (const float*)d_in[15];
    const float* bf1  = (const float*)d_in[16];
    const float* Wf2  = (const float*)d_in[17];
    const float* bf2  = (const float*)d_in[18];
    const float* Gw1  = (const float*)d_in[19];
    const float* Gb1  = (const float*)d_in[20];
    const float* Gw2  = (const float*)d_in[21];
    const float* Gb2  = (const float*)d_in[22];
    const int* q_idx  = (const int*)d_in[23];
    const int* s_idx  = (const int*)d_in[24];
    float* out = (float*)d_out;

    float* p_raw  = sym_f(g_raw);
    float* p_geoh = sym_f(g_geoh);
    float* p_geo  = sym_f(g_geo);
    float* p_qt   = sym_f(g_qt);
    float* p_Qf   = sym_f(g_Qf);
    float* p_Kf   = sym_f(g_Kf);
    float* p_Vf   = sym_f(g_Vf);
    float* p_Gf   = sym_f(g_Gf);
    float* p_out  = sym_f(g_out);
    float* p_x    = sym_f(g_x);
    float* p_h1   = sym_f(g_h1);

    static Ctx ctx;   // created once, reused on every call

    // fork
    cudaEventRecord(ctx.evRoot, 0);
    cudaStreamWaitEvent(ctx.s1, ctx.evRoot, 0);
    cudaStreamWaitEvent(ctx.s2, ctx.evRoot, 0);

    // s1: big support-side GEMMs
    k_gemm_tc<128, false, false, false><<<dim3(DD / 128, NS / 128), 256, 0, ctx.s1>>>(
        support_feats, Wk, nullptr, nullptr, p_Kf, NS, DD, DD);
    cudaEventRecord(ctx.evK, ctx.s1);
    k_gemm_tc<128, false, false, false><<<dim3(DD / 128, NS / 128), 256, 0, ctx.s1>>>(
        support_feats, Wv, nullptr, nullptr, p_Vf, NS, DD, DD);
    cudaEventRecord(ctx.evV, ctx.s1);

    // s2: geo chain
    k_rowptr<<<(NQ + 1 + 255) / 256, 256, 0, ctx.s2>>>(q_idx);
    cudaEventRecord(ctx.evRP, ctx.s2);
    k_geostats<<<NQ / 8, 256, 0, ctx.s2>>>(query_pos, support_pos, s_idx);
    k_gemm<true, true, false><<<dim3(NGEO / 64, NQ / 64), 256, 0, ctx.s2>>>(
        p_raw, Gw1, Gb1, nullptr, p_geoh, NQ, NGEO, 12);
    k_gemm_tc<64, true, true, false><<<dim3(NGEO / 128, NQ / 64), 256, 0, ctx.s2>>>(
        p_geoh, Gw2, Gb2, nullptr, p_geo, NQ, NGEO, NGEO);
    k_gemm_tc<64, false, false, false><<<dim3(DD / 128, NQ / 64), 256, 0, ctx.s2>>>(
        p_geo, Wg, nullptr, nullptr, p_Gf, NQ, DD, NGEO);
    cudaEventRecord(ctx.evG, ctx.s2);

    // s0 (default): query chain
    k_ln<<<NQ / 8, 256>>>(query_tokens, ln1_g, ln1_b, p_qt);
    k_gemm_tc<64, false, false, false><<<dim3(DD / 128, NQ / 64), 256>>>(
        p_qt, Wq, nullptr, nullptr, p_Qf, NQ, DD, DD);

    // join for edge phase
    cudaStreamWaitEvent(0, ctx.evK, 0);
    cudaStreamWaitEvent(0, ctx.evRP, 0);
    k_scores<<<NE / 8, 256>>>(q_idx, s_idx, log_tau);
    k_softmax<<<NQ / 8, 256>>>();
    cudaStreamWaitEvent(0, ctx.evV, 0);
    cudaStreamWaitEvent(0, ctx.evG, 0);
    k_weighted<<<NQ, 256>>>(s_idx);

    // tail on s0
    k_gemm_tc<64, true, false, true><<<dim3(DD / 128, NQ / 64), 256>>>(
        p_out, Wo, bo, query_tokens, p_x, NQ, DD, DD);
    k_ln<<<NQ / 8, 256>>>(p_x, ln2_g, ln2_b, p_qt);
    k_gemm_tc<64, true, true, false><<<dim3(NFFN / 128, NQ / 64), 256>>>(
        p_qt, Wf1, bf1, nullptr, p_h1, NQ, NFFN, DD);
    k_gemm_tc<64, true, false, true><<<dim3(DD / 128, NQ / 64), 256>>>(
        p_h1, Wf2, bf2, p_x, out, NQ, DD, NFFN);
}

// round 5
// speedup vs baseline: 3.3945x; 1.0495x over previous
#include <cuda_runtime.h>
#include <math.h>

#define NQ 8192
#define NS 32768
#define NE 131072
#define DD 256
#define NH 8
#define HDIM 32
#define NGEO 128
#define NFFN 512

// ---------------- scratch (device globals; no allocation) ----------------
__device__ float g_raw[NQ * 12];
__device__ float g_geoh[NQ * NGEO];
__device__ float g_geo[NQ * NGEO];
__device__ float g_qt[NQ * DD];     // LN1 output; reused for LN2 output
__device__ float g_Qf[NQ * DD];
__device__ float g_Kf[NS * DD];
__device__ float g_Vf[NS * DD];
__device__ float g_Gf[NQ * DD];
__device__ float g_out[NQ * DD];
__device__ float g_x[NQ * DD];
__device__ float g_h1[NQ * NFFN];
__device__ int   g_rowptr[NQ + 1];

__device__ __forceinline__ float gelu_f(float x) {
    return 0.5f * x * (1.0f + erff(x * 0.7071067811865475f));
}

__device__ __forceinline__ void cpa16(float* dst, const float* src) {
    unsigned d = (unsigned)__cvta_generic_to_shared(dst);
    asm volatile("cp.async.cg.shared.global [%0], [%1], 16;" :: "r"(d), "l"(src));
}

// ---------------- row_ptr via binary search (q_idx is sorted) ----------------
__global__ void k_rowptr(const int* __restrict__ qidx) {
    int q = blockIdx.x * blockDim.x + threadIdx.x;
    if (q > NQ) return;
    int lo = 0, hi = NE;
    while (lo < hi) {
        int mid = (lo + hi) >> 1;
        if (qidx[mid] < q) lo = mid + 1; else hi = mid;
    }
    g_rowptr[q] = lo;
}

// ---------------- geo stats: warp per query ----------------
__global__ void k_geostats(const float* __restrict__ qpos,
                           const float* __restrict__ spos,
                           const int* __restrict__ sidx) {
    int warp = (blockIdx.x * blockDim.x + threadIdx.x) >> 5;
    int lane = threadIdx.x & 31;
    if (warp >= NQ) return;
    int q = warp;
    int st = g_rowptr[q], en = g_rowptr[q + 1];
    float qp0 = qpos[q * 3 + 0], qp1 = qpos[q * 3 + 1], qp2 = qpos[q * 3 + 2];
    float s0 = 0.f, s1 = 0.f, s2 = 0.f;
    float ss0 = 0.f, ss1 = 0.f, ss2 = 0.f;
    float mn0 = 1e30f, mn1 = 1e30f, mn2 = 1e30f;
    float mx0 = -1e30f, mx1 = -1e30f, mx2 = -1e30f;
    for (int e = st + lane; e < en; e += 32) {
        int s = sidx[e];
        float r0 = spos[s * 3 + 0] - qp0;
        float r1 = spos[s * 3 + 1] - qp1;
        float r2 = spos[s * 3 + 2] - qp2;
        s0 += r0; s1 += r1; s2 += r2;
        ss0 += r0 * r0; ss1 += r1 * r1; ss2 += r2 * r2;
        mn0 = fminf(mn0, r0); mn1 = fminf(mn1, r1); mn2 = fminf(mn2, r2);
        mx0 = fmaxf(mx0, r0); mx1 = fmaxf(mx1, r1); mx2 = fmaxf(mx2, r2);
    }
    #pragma unroll
    for (int off = 16; off > 0; off >>= 1) {
        s0 += __shfl_xor_sync(0xffffffffu, s0, off);
        s1 += __shfl_xor_sync(0xffffffffu, s1, off);
        s2 += __shfl_xor_sync(0xffffffffu, s2, off);
        ss0 += __shfl_xor_sync(0xffffffffu, ss0, off);
        ss1 += __shfl_xor_sync(0xffffffffu, ss1, off);
        ss2 += __shfl_xor_sync(0xffffffffu, ss2, off);
        mn0 = fminf(mn0, __shfl_xor_sync(0xffffffffu, mn0, off));
        mn1 = fminf(mn1, __shfl_xor_sync(0xffffffffu, mn1, off));
        mn2 = fminf(mn2, __shfl_xor_sync(0xffffffffu, mn2, off));
        mx0 = fmaxf(mx0, __shfl_xor_sync(0xffffffffu, mx0, off));
        mx1 = fmaxf(mx1, __shfl_xor_sync(0xffffffffu, mx1, off));
        mx2 = fmaxf(mx2, __shfl_xor_sync(0xffffffffu, mx2, off));
    }
    if (lane == 0) {
        float cnt = fmaxf((float)(en - st), 1.0f);
        float m0 = s0 / cnt, m1 = s1 / cnt, m2 = s2 / cnt;
        float v0 = fmaxf(ss0 / cnt - m0 * m0, 0.f);
        float v1 = fmaxf(ss1 / cnt - m1 * m1, 0.f);
        float v2 = fmaxf(ss2 / cnt - m2 * m2, 0.f);
        float* r = g_raw + q * 12;
        r[0] = m0; r[1] = m1; r[2] = m2;
        r[3] = sqrtf(v0); r[4] = sqrtf(v1); r[5] = sqrtf(v2);
        r[6] = fminf(fmaxf(mn0, -100.f), 100.f);
        r[7] = fminf(fmaxf(mn1, -100.f), 100.f);
        r[8] = fminf(fmaxf(mn2, -100.f), 100.f);
        r[9]  = fminf(fmaxf(mx0, -100.f), 100.f);
        r[10] = fminf(fmaxf(mx1, -100.f), 100.f);
        r[11] = fminf(fmaxf(mx2, -100.f), 100.f);
    }
}

// ---------------- LayerNorm: warp per row (D=256) ----------------
__global__ void k_ln(const float* __restrict__ x, const float* __restrict__ g,
                     const float* __restrict__ b, float* __restrict__ y) {
    int warp = (blockIdx.x * blockDim.x + threadIdx.x) >> 5;
    int lane = threadIdx.x & 31;
    if (warp >= NQ) return;
    const float4* xr = (const float4*)(x + warp * DD);
    float4 a = xr[lane * 2], c = xr[lane * 2 + 1];
    float sum = a.x + a.y + a.z + a.w + c.x + c.y + c.z + c.w;
    float ss = a.x * a.x + a.y * a.y + a.z * a.z + a.w * a.w +
               c.x * c.x + c.y * c.y + c.z * c.z + c.w * c.w;
    #pragma unroll
    for (int off = 16; off > 0; off >>= 1) {
        sum += __shfl_xor_sync(0xffffffffu, sum, off);
        ss  += __shfl_xor_sync(0xffffffffu, ss, off);
    }
    float mean = sum * (1.0f / 256.0f);
    float var = ss * (1.0f / 256.0f) - mean * mean;
    float rstd = rsqrtf(var + 1e-5f);
    const float4* gr = (const float4*)g;
    const float4* br = (const float4*)b;
    float4 g0 = gr[lane * 2], g1 = gr[lane * 2 + 1];
    float4 b0 = br[lane * 2], b1 = br[lane * 2 + 1];
    float4 o0, o1;
    o0.x = (a.x - mean) * rstd * g0.x + b0.x;
    o0.y = (a.y - mean) * rstd * g0.y + b0.y;
    o0.z = (a.z - mean) * rstd * g0.z + b0.z;
    o0.w = (a.w - mean) * rstd * g0.w + b0.w;
    o1.x = (c.x - mean) * rstd * g1.x + b1.x;
    o1.y = (c.y - mean) * rstd * g1.y + b1.y;
    o1.z = (c.z - mean) * rstd * g1.z + b1.z;
    o1.w = (c.w - mean) * rstd * g1.w + b1.w;
    float4* yr = (float4*)(y + warp * DD);
    yr[lane * 2] = o0;
    yr[lane * 2 + 1] = o1;
}

// ---------------- fp32 GEMM (only for K=12 geo1) ----------------
template <bool BIAS, bool GELU, bool RES>
__global__ void k_gemm(const float* __restrict__ A, const float* __restrict__ B,
                       const float* __restrict__ bias, const float* __restrict__ res,
                       float* __restrict__ C, int M, int N, int K) {
    __shared__ float As[64][17];
    __shared__ float Bs[16][64];
    int tid = threadIdx.x;
    int tx = tid & 15, ty = tid >> 4;
    int m0 = blockIdx.y * 64, n0 = blockIdx.x * 64;
    float acc[4][4] = {};
    int KT = (K + 15) >> 4;
    for (int kt = 0; kt < KT; kt++) {
        int k0 = kt << 4;
        #pragma unroll
        for (int i = 0; i < 4; i++) {
            int lin = tid + i * 256;
            int ar = lin >> 4, ac = lin & 15;
            int gk = k0 + ac;
            As[ar][ac] = (gk < K) ? A[(size_t)(m0 + ar) * K + gk] : 0.f;
        }
        #pragma unroll
        for (int i = 0; i < 4; i++) {
            int lin = tid + i * 256;
            int br = lin >> 6, bc = lin & 63;
            int gk = k0 + br;
            Bs[br][bc] = (gk < K) ? B[(size_t)gk * N + n0 + bc] : 0.f;
        }
        __syncthreads();
        #pragma unroll
        for (int kk = 0; kk < 16; kk++) {
            float av[4];
            #pragma unroll
            for (int i = 0; i < 4; i++) av[i] = As[ty * 4 + i][kk];
            float4 bv = *(const float4*)&Bs[kk][tx * 4];
            float bvv[4] = {bv.x, bv.y, bv.z, bv.w};
            #pragma unroll
            for (int i = 0; i < 4; i++)
                #pragma unroll
                for (int j = 0; j < 4; j++)
                    acc[i][j] = fmaf(av[i], bvv[j], acc[i][j]);
        }
        __syncthreads();
    }
    #pragma unroll
    for (int i = 0; i < 4; i++) {
        int row = m0 + ty * 4 + i;
        #pragma unroll
        for (int j = 0; j < 4; j++) {
            int col = n0 + tx * 4 + j;
            float v = acc[i][j];
            if (BIAS) v += bias[col];
            if (GELU) v = gelu_f(v);
            if (RES) v += res[(size_t)row * N + col];
            C[(size_t)row * N + col] = v;
        }
    }
}

// ---------------- TF32 tensor-core GEMM, cp.async double-buffered ----------------
template <int BM, bool BIAS, bool GELU, bool RES>
__global__ __launch_bounds__(256, 2)
void k_gemm_tc(const float* __restrict__ A, const float* __restrict__ B,
               const float* __restrict__ bias, const float* __restrict__ res,
               float* __restrict__ C, int M, int N, int K) {
    constexpr int SA = 20, SB = 136;
    constexpr int MI = BM / 32;
    __shared__ float As[2][BM][SA];
    __shared__ float Bs[2][16][SB];
    int tid = threadIdx.x;
    int warp = tid >> 5, lane = tid & 31;
    int wm = warp & 1, wn = warp >> 1;
    int g = lane >> 2, t = lane & 3;
    int m0 = blockIdx.y * BM, n0 = blockIdx.x * 128;

    int arow = tid >> 2, aq = (tid & 3) * 4;
    int brow = tid >> 5, bq = (tid & 31) * 4;
    const float* Ag = A + (size_t)(m0 + arow) * K + aq;
    const float* Bg = B + (size_t)brow * N + n0 + bq;

    float acc[MI][4][4];
    #pragma unroll
    for (int i = 0; i < MI; i++)
        #pragma unroll
        for (int j = 0; j < 4; j++)
            #pragma unroll
            for (int c = 0; c < 4; c++) acc[i][j][c] = 0.f;

    int KT = K >> 4;
    #pragma unroll
    for (int h = 0; h < BM / 64; h++)
        cpa16(&As[0][arow + h * 64][aq], Ag + (size_t)(h * 64) * K);
    #pragma unroll
    for (int h = 0; h < 2; h++)
        cpa16(&Bs[0][brow + h * 8][bq], Bg + (size_t)(h * 8) * N);
    asm volatile("cp.async.commit_group;");

    int buf = 0;
    for (int kt = 0; kt < KT; kt++) {
        if (kt + 1 < KT) {
            int k0 = (kt + 1) << 4;
            #pragma unroll
            for (int h = 0; h < BM / 64; h++)
                cpa16(&As[buf ^ 1][arow + h * 64][aq], Ag + (size_t)(h * 64) * K + k0);
            #pragma unroll
            for (int h = 0; h < 2; h++)
                cpa16(&Bs[buf ^ 1][brow + h * 8][bq], Bg + (size_t)(k0 + h * 8) * N);
            asm volatile("cp.async.commit_group;");
            asm volatile("cp.async.wait_group 1;");
        } else {
            asm volatile("cp.async.wait_group 0;");
        }
        __syncthreads();
        #pragma unroll
        for (int ks = 0; ks < 16; ks += 8) {
            unsigned a[MI][4], b[4][2];
            #pragma unroll
            for (int mi = 0; mi < MI; mi++) {
                int mb = wm * (BM / 2) + mi * 16 + g;
                a[mi][0] = __float_as_uint(As[buf][mb][ks + t]);
                a[mi][1] = __float_as_uint(As[buf][mb + 8][ks + t]);
                a[mi][2] = __float_as_uint(As[buf][mb][ks + t + 4]);
                a[mi][3] = __float_as_uint(As[buf][mb + 8][ks + t + 4]);
            }
            #pragma unroll
            for (int ni = 0; ni < 4; ni++) {
                int nb = wn * 32 + ni * 8 + g;
                b[ni][0] = __float_as_uint(Bs[buf][ks + t][nb]);
                b[ni][1] = __float_as_uint(Bs[buf][ks + t + 4][nb]);
            }
            #pragma unroll
            for (int mi = 0; mi < MI; mi++)
                #pragma unroll
                for (int ni = 0; ni < 4; ni++) {
                    asm volatile(
                        "mma.sync.aligned.m16n8k8.row.col.f32.tf32.tf32.f32 "
                        "{%0,%1,%2,%3}, {%4,%5,%6,%7}, {%8,%9}, {%0,%1,%2,%3};"
                        : "+f"(acc[mi][ni][0]), "+f"(acc[mi][ni][1]),
                          "+f"(acc[mi][ni][2]), "+f"(acc[mi][ni][3])
                        : "r"(a[mi][0]), "r"(a[mi][1]), "r"(a[mi][2]), "r"(a[mi][3]),
                          "r"(b[ni][0]), "r"(b[ni][1]));
                }
        }
        buf ^= 1;
        __syncthreads();
    }
    #pragma unroll
    for (int mi = 0; mi < MI; mi++) {
        int mrow = m0 + wm * (BM / 2) + mi * 16 + g;
        #pragma unroll
        for (int ni = 0; ni < 4; ni++) {
            int ncol = n0 + wn * 32 + ni * 8 + 2 * t;
            #pragma unroll
            for (int half = 0; half < 2; half++) {
                int row = mrow + half * 8;
                float v0 = acc[mi][ni][half * 2 + 0];
                float v1 = acc[mi][ni][half * 2 + 1];
                if (BIAS) { v0 += bias[ncol]; v1 += bias[ncol + 1]; }
                if (GELU) { v0 = gelu_f(v0); v1 = gelu_f(v1); }
                if (RES) {
                    const float2 r = *(const float2*)&res[(size_t)row * N + ncol];
                    v0 += r.x; v1 += r.y;
                }
                float2 o; o.x = v0; o.y = v1;
                *(float2*)&C[(size_t)row * N + ncol] = o;
            }
        }
    }
}

// ---------------- fused edge attention: warp per query, online softmax ----------
// Computes per-query: scores over its edges (8 heads), softmax with
// smax = max(0, seg_max) via online init m=0, and the weighted sum of
// (V[s] + G[q]) -- all in one pass over edges. Lane d covers dims
// [lane*8, lane*8+8), which lie entirely inside head (lane>>2); the quad
// shfl reduce (xor 1,2) yields that head's score on each of its 4 lanes.
__global__ void k_attn(const int* __restrict__ sidx,
                       const float* __restrict__ log_tau) {
    int warp = (blockIdx.x * blockDim.x + threadIdx.x) >> 5;
    int lane = threadIdx.x & 31;
    if (warp >= NQ) return;
    int q = warp;
    int st = g_rowptr[q], en = g_rowptr[q + 1];
    float scale = 0.17677669529663689f * expf(-log_tau[0]);

    const float4* qr = (const float4*)(g_Qf + (size_t)q * DD);
    float4 q0 = qr[lane * 2], q1 = qr[lane * 2 + 1];

    float m = 0.0f;           // reference: smax = max(0, segment max)
    float ssum = 0.0f;        // per-head (uniform within quad)
    float4 a0 = {0.f, 0.f, 0.f, 0.f}, a1 = {0.f, 0.f, 0.f, 0.f};

    for (int e = st; e < en; e++) {
        int s = sidx[e];
        const float4* kr = (const float4*)(g_Kf + (size_t)s * DD);
        float4 k0 = kr[lane * 2], k1 = kr[lane * 2 + 1];
        float d = q0.x * k0.x + q0.y * k0.y + q0.z * k0.z + q0.w * k0.w +
                  q1.x * k1.x + q1.y * k1.y + q1.z * k1.z + q1.w * k1.w;
        d += __shfl_xor_sync(0xffffffffu, d, 1);
        d += __shfl_xor_sync(0xffffffffu, d, 2);
        d *= scale;
        float mn = fmaxf(m, d);
        float c = __expf(m - mn);
        float r = __expf(d - mn);
        const float4* vr = (const float4*)(g_Vf + (size_t)s * DD);
        float4 v0 = vr[lane * 2], v1 = vr[lane * 2 + 1];
        a0.x = a0.x * c + r * v0.x; a0.y = a0.y * c + r * v0.y;
        a0.z = a0.z * c + r * v0.z; a0.w = a0.w * c + r * v0.w;
        a1.x = a1.x * c + r * v1.x; a1.y = a1.y * c + r * v1.y;
        a1.z = a1.z * c + r * v1.z; a1.w = a1.w * c + r * v1.w;
        ssum = ssum * c + r;
        m = mn;
    }

    float inv = 1.0f / fmaxf(ssum, 1e-8f);
    float gsc = ssum * inv;   // sum of alphas (normalized)
    const float4* gr = (const float4*)(g_Gf + (size_t)q * DD);
    float4 g0 = gr[lane * 2], g1 = gr[lane * 2 + 1];
    float4 o0, o1;
    o0.x = a0.x * inv + g0.x * gsc; o0.y = a0.y * inv + g0.y * gsc;
    o0.z = a0.z * inv + g0.z * gsc; o0.w = a0.w * inv + g0.w * gsc;
    o1.x = a1.x * inv + g1.x * gsc; o1.y = a1.y * inv + g1.y * gsc;
    o1.z = a1.z * inv + g1.z * gsc; o1.w = a1.w * inv + g1.w * gsc;
    float4* orow = (float4*)(g_out + (size_t)q * DD);
    orow[lane * 2] = o0;
    orow[lane * 2 + 1] = o1;
}

// ---------------- host launcher ----------------
static float* sym_f(const void* sym) {
    void* p = nullptr;
    cudaGetSymbolAddress(&p, sym);
    return (float*)p;
}

// Streams/events created exactly once (first, non-captured correctness call)
// and reused every call: no device-side allocation after the pre-capture
// baseline; identical launched work each call.
struct Ctx {
    cudaStream_t s1, s2;
    cudaEvent_t evRoot, evK, evG;
    Ctx() {
        cudaStreamCreateWithFlags(&s1, cudaStreamNonBlocking);
        cudaStreamCreateWithFlags(&s2, cudaStreamNonBlocking);
        cudaEventCreateWithFlags(&evRoot, cudaEventDisableTiming);
        cudaEventCreateWithFlags(&evK, cudaEventDisableTiming);
        cudaEventCreateWithFlags(&evG, cudaEventDisableTiming);
    }
};

extern "C" void kernel_launch(void* const* d_in, const int* in_sizes, int n_in,
                              void* d_out, int out_size) {
    const float* query_tokens  = (const float*)d_in[0];
    const float* query_pos     = (const float*)d_in[1];
    const float* support_feats = (const float*)d_in[2];
    const float* support_pos   = (const float*)d_in[3];
    const float* Wq   = (const float*)d_in[4];
    const float* Wk   = (const float*)d_in[5];
    const float* Wv   = (const float*)d_in[6];
    const float* Wg   = (const float*)d_in[7];
    const float* Wo   = (const float*)d_in[8];
    const float* bo   = (const float*)d_in[9];
    const float* log_tau = (const float*)d_in[10];
    const float* ln1_g = (const float*)d_in[11];
    const float* ln1_b = (const float*)d_in[12];
    const float* ln2_g = (const float*)d_in[13];
    const float* ln2_b = (const float*)d_in[14];
    const float* Wf1  = (const float*)d_in[15];
    const float* bf1  = (const float*)d_in[16];
    const float* Wf2  = (const float*)d_in[17];
    const float* bf2  = (const float*)d_in[18];
    const float* Gw1  = (const float*)d_in[19];
    const float* Gb1  = (const float*)d_in[20];
    const float* Gw2  = (const float*)d_in[21];
    const float* Gb2  = (const float*)d_in[22];
    const int* q_idx  = (const int*)d_in[23];
    const int* s_idx  = (const int*)d_in[24];
    float* out = (float*)d_out;

    float* p_raw  = sym_f(g_raw);
    float* p_geoh = sym_f(g_geoh);
    float* p_geo  = sym_f(g_geo);
    float* p_qt   = sym_f(g_qt);
    float* p_Qf   = sym_f(g_Qf);
    float* p_Kf   = sym_f(g_Kf);
    float* p_Vf   = sym_f(g_Vf);
    float* p_Gf   = sym_f(g_Gf);
    float* p_out  = sym_f(g_out);
    float* p_x    = sym_f(g_x);
    float* p_h1   = sym_f(g_h1);

    static Ctx ctx;

    // fork
    cudaEventRecord(ctx.evRoot, 0);
    cudaStreamWaitEvent(ctx.s1, ctx.evRoot, 0);
    cudaStreamWaitEvent(ctx.s2, ctx.evRoot, 0);

    // s1: K projection
    k_gemm_tc<128, false, false, false><<<dim3(DD / 128, NS / 128), 256, 0, ctx.s1>>>(
        support_feats, Wk, nullptr, nullptr, p_Kf, NS, DD, DD);
    cudaEventRecord(ctx.evK, ctx.s1);

    // s2: geo chain (rowptr -> stats -> MLP -> Gf)
    k_rowptr<<<(NQ + 1 + 255) / 256, 256, 0, ctx.s2>>>(q_idx);
    k_geostats<<<NQ / 8, 256, 0, ctx.s2>>>(query_pos, support_pos, s_idx);
    k_gemm<true, true, false><<<dim3(NGEO / 64, NQ / 64), 256, 0, ctx.s2>>>(
        p_raw, Gw1, Gb1, nullptr, p_geoh, NQ, NGEO, 12);
    k_gemm_tc<64, true, true, false><<<dim3(NGEO / 128, NQ / 64), 256, 0, ctx.s2>>>(
        p_geoh, Gw2, Gb2, nullptr, p_geo, NQ, NGEO, NGEO);
    k_gemm_tc<64, false, false, false><<<dim3(DD / 128, NQ / 64), 256, 0, ctx.s2>>>(
        p_geo, Wg, nullptr, nullptr, p_Gf, NQ, DD, NGEO);
    cudaEventRecord(ctx.evG, ctx.s2);

    // s0 (default): query chain + V projection
    k_ln<<<NQ / 8, 256>>>(query_tokens, ln1_g, ln1_b, p_qt);
    k_gemm_tc<64, false, false, false><<<dim3(DD / 128, NQ / 64), 256>>>(
        p_qt, Wq, nullptr, nullptr, p_Qf, NQ, DD, DD);
    k_gemm_tc<128, false, false, false><<<dim3(DD / 128, NS / 128), 256>>>(
        support_feats, Wv, nullptr, nullptr, p_Vf, NS, DD, DD);

    // join, then fused edge attention
    cudaStreamWaitEvent(0, ctx.evK, 0);
    cudaStreamWaitEvent(0, ctx.evG, 0);
    k_attn<<<NQ / 8, 256>>>(s_idx, log_tau);

    // tail on s0
    k_gemm_tc<64, true, false, true><<<dim3(DD / 128, NQ / 64), 256>>>(
        p_out, Wo, bo, query_tokens, p_x, NQ, DD, DD);
    k_ln<<<NQ / 8, 256>>>(p_x, ln2_g, ln2_b, p_qt);
    k_gemm_tc<64, true, true, false><<<dim3(NFFN / 128, NQ / 64), 256>>>(
        p_qt, Wf1, bf1, nullptr, p_h1, NQ, NFFN, DD);
    k_gemm_tc<64, true, false, true><<<dim3(DD / 128, NQ / 64), 256>>>(
        p_h1, Wf2, bf2, p_x, out, NQ, DD, NFFN);
}

// round 6
// speedup vs baseline: 3.7257x; 1.0976x over previous
#include <cuda_runtime.h>
#include <math.h>

#define NQ 8192
#define NS 32768
#define NE 131072
#define DD 256
#define NH 8
#define HDIM 32
#define NGEO 128
#define NFFN 512

// ---------------- scratch (device globals; no allocation) ----------------
__device__ float g_raw[NQ * 12];
__device__ float g_geoh[NQ * NGEO];
__device__ float g_geo[NQ * NGEO];
__device__ float g_qt[NQ * DD];
__device__ float g_Qf[NQ * DD];
__device__ float g_Kf[NS * DD];
__device__ float g_Vf[NS * DD];
__device__ float g_Gf[NQ * DD];
__device__ float g_out[NQ * DD];
__device__ float g_x[NQ * DD];
__device__ float g_h1[NQ * NFFN];
__device__ int   g_rowptr[NQ + 1];

__device__ __forceinline__ float gelu_f(float x) {
    return 0.5f * x * (1.0f + erff(x * 0.7071067811865475f));
}

__device__ __forceinline__ void cpa16(float* dst, const float* src) {
    unsigned d = (unsigned)__cvta_generic_to_shared(dst);
    asm volatile("cp.async.cg.shared.global [%0], [%1], 16;" :: "r"(d), "l"(src));
}

// ---------------- row_ptr via binary search (q_idx is sorted) ----------------
__global__ void k_rowptr(const int* __restrict__ qidx) {
    int q = blockIdx.x * blockDim.x + threadIdx.x;
    if (q > NQ) return;
    int lo = 0, hi = NE;
    while (lo < hi) {
        int mid = (lo + hi) >> 1;
        if (qidx[mid] < q) lo = mid + 1; else hi = mid;
    }
    g_rowptr[q] = lo;
}

// ---------------- geo stats: warp per query ----------------
__global__ void k_geostats(const float* __restrict__ qpos,
                           const float* __restrict__ spos,
                           const int* __restrict__ sidx) {
    int warp = (blockIdx.x * blockDim.x + threadIdx.x) >> 5;
    int lane = threadIdx.x & 31;
    if (warp >= NQ) return;
    int q = warp;
    int st = g_rowptr[q], en = g_rowptr[q + 1];
    float qp0 = qpos[q * 3 + 0], qp1 = qpos[q * 3 + 1], qp2 = qpos[q * 3 + 2];
    float s0 = 0.f, s1 = 0.f, s2 = 0.f;
    float ss0 = 0.f, ss1 = 0.f, ss2 = 0.f;
    float mn0 = 1e30f, mn1 = 1e30f, mn2 = 1e30f;
    float mx0 = -1e30f, mx1 = -1e30f, mx2 = -1e30f;
    for (int e = st + lane; e < en; e += 32) {
        int s = sidx[e];
        float r0 = spos[s * 3 + 0] - qp0;
        float r1 = spos[s * 3 + 1] - qp1;
        float r2 = spos[s * 3 + 2] - qp2;
        s0 += r0; s1 += r1; s2 += r2;
        ss0 += r0 * r0; ss1 += r1 * r1; ss2 += r2 * r2;
        mn0 = fminf(mn0, r0); mn1 = fminf(mn1, r1); mn2 = fminf(mn2, r2);
        mx0 = fmaxf(mx0, r0); mx1 = fmaxf(mx1, r1); mx2 = fmaxf(mx2, r2);
    }
    #pragma unroll
    for (int off = 16; off > 0; off >>= 1) {
        s0 += __shfl_xor_sync(0xffffffffu, s0, off);
        s1 += __shfl_xor_sync(0xffffffffu, s1, off);
        s2 += __shfl_xor_sync(0xffffffffu, s2, off);
        ss0 += __shfl_xor_sync(0xffffffffu, ss0, off);
        ss1 += __shfl_xor_sync(0xffffffffu, ss1, off);
        ss2 += __shfl_xor_sync(0xffffffffu, ss2, off);
        mn0 = fminf(mn0, __shfl_xor_sync(0xffffffffu, mn0, off));
        mn1 = fminf(mn1, __shfl_xor_sync(0xffffffffu, mn1, off));
        mn2 = fminf(mn2, __shfl_xor_sync(0xffffffffu, mn2, off));
        mx0 = fmaxf(mx0, __shfl_xor_sync(0xffffffffu, mx0, off));
        mx1 = fmaxf(mx1, __shfl_xor_sync(0xffffffffu, mx1, off));
        mx2 = fmaxf(mx2, __shfl_xor_sync(0xffffffffu, mx2, off));
    }
    if (lane == 0) {
        float cnt = fmaxf((float)(en - st), 1.0f);
        float m0 = s0 / cnt, m1 = s1 / cnt, m2 = s2 / cnt;
        float v0 = fmaxf(ss0 / cnt - m0 * m0, 0.f);
        float v1 = fmaxf(ss1 / cnt - m1 * m1, 0.f);
        float v2 = fmaxf(ss2 / cnt - m2 * m2, 0.f);
        float* r = g_raw + q * 12;
        r[0] = m0; r[1] = m1; r[2] = m2;
        r[3] = sqrtf(v0); r[4] = sqrtf(v1); r[5] = sqrtf(v2);
        r[6] = fminf(fmaxf(mn0, -100.f), 100.f);
        r[7] = fminf(fmaxf(mn1, -100.f), 100.f);
        r[8] = fminf(fmaxf(mn2, -100.f), 100.f);
        r[9]  = fminf(fmaxf(mx0, -100.f), 100.f);
        r[10] = fminf(fmaxf(mx1, -100.f), 100.f);
        r[11] = fminf(fmaxf(mx2, -100.f), 100.f);
    }
}

// ---------------- LayerNorm: warp per row (D=256) ----------------
__global__ void k_ln(const float* __restrict__ x, const float* __restrict__ g,
                     const float* __restrict__ b, float* __restrict__ y) {
    int warp = (blockIdx.x * blockDim.x + threadIdx.x) >> 5;
    int lane = threadIdx.x & 31;
    if (warp >= NQ) return;
    const float4* xr = (const float4*)(x + warp * DD);
    float4 a = xr[lane * 2], c = xr[lane * 2 + 1];
    float sum = a.x + a.y + a.z + a.w + c.x + c.y + c.z + c.w;
    float ss = a.x * a.x + a.y * a.y + a.z * a.z + a.w * a.w +
               c.x * c.x + c.y * c.y + c.z * c.z + c.w * c.w;
    #pragma unroll
    for (int off = 16; off > 0; off >>= 1) {
        sum += __shfl_xor_sync(0xffffffffu, sum, off);
        ss  += __shfl_xor_sync(0xffffffffu, ss, off);
    }
    float mean = sum * (1.0f / 256.0f);
    float var = ss * (1.0f / 256.0f) - mean * mean;
    float rstd = rsqrtf(var + 1e-5f);
    const float4* gr = (const float4*)g;
    const float4* br = (const float4*)b;
    float4 g0 = gr[lane * 2], g1 = gr[lane * 2 + 1];
    float4 b0 = br[lane * 2], b1 = br[lane * 2 + 1];
    float4 o0, o1;
    o0.x = (a.x - mean) * rstd * g0.x + b0.x;
    o0.y = (a.y - mean) * rstd * g0.y + b0.y;
    o0.z = (a.z - mean) * rstd * g0.z + b0.z;
    o0.w = (a.w - mean) * rstd * g0.w + b0.w;
    o1.x = (c.x - mean) * rstd * g1.x + b1.x;
    o1.y = (c.y - mean) * rstd * g1.y + b1.y;
    o1.z = (c.z - mean) * rstd * g1.z + b1.z;
    o1.w = (c.w - mean) * rstd * g1.w + b1.w;
    float4* yr = (float4*)(y + warp * DD);
    yr[lane * 2] = o0;
    yr[lane * 2 + 1] = o1;
}

// ---------------- fp32 GEMM (only for K=12 geo1) ----------------
template <bool BIAS, bool GELU, bool RES>
__global__ void k_gemm(const float* __restrict__ A, const float* __restrict__ B,
                       const float* __restrict__ bias, const float* __restrict__ res,
                       float* __restrict__ C, int M, int N, int K) {
    __shared__ float As[64][17];
    __shared__ float Bs[16][64];
    int tid = threadIdx.x;
    int tx = tid & 15, ty = tid >> 4;
    int m0 = blockIdx.y * 64, n0 = blockIdx.x * 64;
    float acc[4][4] = {};
    int KT = (K + 15) >> 4;
    for (int kt = 0; kt < KT; kt++) {
        int k0 = kt << 4;
        #pragma unroll
        for (int i = 0; i < 4; i++) {
            int lin = tid + i * 256;
            int ar = lin >> 4, ac = lin & 15;
            int gk = k0 + ac;
            As[ar][ac] = (gk < K) ? A[(size_t)(m0 + ar) * K + gk] : 0.f;
        }
        #pragma unroll
        for (int i = 0; i < 4; i++) {
            int lin = tid + i * 256;
            int br = lin >> 6, bc = lin & 63;
            int gk = k0 + br;
            Bs[br][bc] = (gk < K) ? B[(size_t)gk * N + n0 + bc] : 0.f;
        }
        __syncthreads();
        #pragma unroll
        for (int kk = 0; kk < 16; kk++) {
            float av[4];
            #pragma unroll
            for (int i = 0; i < 4; i++) av[i] = As[ty * 4 + i][kk];
            float4 bv = *(const float4*)&Bs[kk][tx * 4];
            float bvv[4] = {bv.x, bv.y, bv.z, bv.w};
            #pragma unroll
            for (int i = 0; i < 4; i++)
                #pragma unroll
                for (int j = 0; j < 4; j++)
                    acc[i][j] = fmaf(av[i], bvv[j], acc[i][j]);
        }
        __syncthreads();
    }
    #pragma unroll
    for (int i = 0; i < 4; i++) {
        int row = m0 + ty * 4 + i;
        #pragma unroll
        for (int j = 0; j < 4; j++) {
            int col = n0 + tx * 4 + j;
            float v = acc[i][j];
            if (BIAS) v += bias[col];
            if (GELU) v = gelu_f(v);
            if (RES) v += res[(size_t)row * N + col];
            C[(size_t)row * N + col] = v;
        }
    }
}

// ---------------- TF32 tensor-core GEMM body, BK=32, cp.async 2-stage ----------
// Dynamic smem: As[2][BM][36] then Bs[2][32][136].
template <int BM, bool BIAS, bool GELU, bool RES>
__device__ __forceinline__ void gemm_body(
    const float* __restrict__ A, const float* __restrict__ B,
    const float* __restrict__ bias, const float* __restrict__ res,
    float* __restrict__ C, int N, int K, int m0, int n0) {
    constexpr int SA = 36, SB = 136;
    constexpr int MI = BM / 32;
    extern __shared__ float smem[];
    float (*As)[BM][SA] = reinterpret_cast<float(*)[BM][SA]>(smem);
    float (*Bs)[32][SB] = reinterpret_cast<float(*)[32][SB]>(smem + 2 * BM * SA);

    int tid = threadIdx.x;
    int warp = tid >> 5, lane = tid & 31;
    int wm = warp & 1, wn = warp >> 1;
    int g = lane >> 2, t = lane & 3;

    float acc[MI][4][4];
    #pragma unroll
    for (int i = 0; i < MI; i++)
        #pragma unroll
        for (int j = 0; j < 4; j++)
            #pragma unroll
            for (int c = 0; c < 4; c++) acc[i][j][c] = 0.f;

    int KT = K >> 5;
    // stage loads: A BM x 32 (BM/32 float4/thread), B 32 x 128 (4 float4/thread)
    #pragma unroll
    for (int i = 0; i < BM / 32; i++) {
        int lin = tid + i * 256;
        int row = lin >> 3, colq = (lin & 7) * 4;
        cpa16(&As[0][row][colq], &A[(size_t)(m0 + row) * K + colq]);
    }
    #pragma unroll
    for (int i = 0; i < 4; i++) {
        int lin = tid + i * 256;
        int row = lin >> 5, colq = (lin & 31) * 4;
        cpa16(&Bs[0][row][colq], &B[(size_t)row * N + n0 + colq]);
    }
    asm volatile("cp.async.commit_group;");

    int buf = 0;
    for (int kt = 0; kt < KT; kt++) {
        if (kt + 1 < KT) {
            int k0 = (kt + 1) << 5;
            #pragma unroll
            for (int i = 0; i < BM / 32; i++) {
                int lin = tid + i * 256;
                int row = lin >> 3, colq = (lin & 7) * 4;
                cpa16(&As[buf ^ 1][row][colq], &A[(size_t)(m0 + row) * K + k0 + colq]);
            }
            #pragma unroll
            for (int i = 0; i < 4; i++) {
                int lin = tid + i * 256;
                int row = lin >> 5, colq = (lin & 31) * 4;
                cpa16(&Bs[buf ^ 1][row][colq], &B[(size_t)(k0 + row) * N + n0 + colq]);
            }
            asm volatile("cp.async.commit_group;");
            asm volatile("cp.async.wait_group 1;");
        } else {
            asm volatile("cp.async.wait_group 0;");
        }
        __syncthreads();
        #pragma unroll
        for (int ks = 0; ks < 32; ks += 8) {
            unsigned a[MI][4], b[4][2];
            #pragma unroll
            for (int mi = 0; mi < MI; mi++) {
                int mb = wm * (BM / 2) + mi * 16 + g;
                a[mi][0] = __float_as_uint(As[buf][mb][ks + t]);
                a[mi][1] = __float_as_uint(As[buf][mb + 8][ks + t]);
                a[mi][2] = __float_as_uint(As[buf][mb][ks + t + 4]);
                a[mi][3] = __float_as_uint(As[buf][mb + 8][ks + t + 4]);
            }
            #pragma unroll
            for (int ni = 0; ni < 4; ni++) {
                int nb = wn * 32 + ni * 8 + g;
                b[ni][0] = __float_as_uint(Bs[buf][ks + t][nb]);
                b[ni][1] = __float_as_uint(Bs[buf][ks + t + 4][nb]);
            }
            #pragma unroll
            for (int mi = 0; mi < MI; mi++)
                #pragma unroll
                for (int ni = 0; ni < 4; ni++) {
                    asm volatile(
                        "mma.sync.aligned.m16n8k8.row.col.f32.tf32.tf32.f32 "
                        "{%0,%1,%2,%3}, {%4,%5,%6,%7}, {%8,%9}, {%0,%1,%2,%3};"
                        : "+f"(acc[mi][ni][0]), "+f"(acc[mi][ni][1]),
                          "+f"(acc[mi][ni][2]), "+f"(acc[mi][ni][3])
                        : "r"(a[mi][0]), "r"(a[mi][1]), "r"(a[mi][2]), "r"(a[mi][3]),
                          "r"(b[ni][0]), "r"(b[ni][1]));
                }
        }
        buf ^= 1;
        __syncthreads();
    }
    #pragma unroll
    for (int mi = 0; mi < MI; mi++) {
        int mrow = m0 + wm * (BM / 2) + mi * 16 + g;
        #pragma unroll
        for (int ni = 0; ni < 4; ni++) {
            int ncol = n0 + wn * 32 + ni * 8 + 2 * t;
            #pragma unroll
            for (int half = 0; half < 2; half++) {
                int row = mrow + half * 8;
                float v0 = acc[mi][ni][half * 2 + 0];
                float v1 = acc[mi][ni][half * 2 + 1];
                if (BIAS) { v0 += bias[ncol]; v1 += bias[ncol + 1]; }
                if (GELU) { v0 = gelu_f(v0); v1 = gelu_f(v1); }
                if (RES) {
                    const float2 r = *(const float2*)&res[(size_t)row * N + ncol];
                    v0 += r.x; v1 += r.y;
                }
                float2 o; o.x = v0; o.y = v1;
                *(float2*)&C[(size_t)row * N + ncol] = o;
            }
        }
    }
}

template <int BM, bool BIAS, bool GELU, bool RES>
__global__ __launch_bounds__(256, 2)
void k_gemm_tc(const float* __restrict__ A, const float* __restrict__ B,
               const float* __restrict__ bias, const float* __restrict__ res,
               float* __restrict__ C, int N, int K) {
    gemm_body<BM, BIAS, GELU, RES>(A, B, bias, res, C, N, K,
                                   blockIdx.y * BM, blockIdx.x * 128);
}

// Merged K/V projection: blockIdx.z selects (Wk->Kf) or (Wv->Vf).
__global__ __launch_bounds__(256, 2)
void k_gemm_kv(const float* __restrict__ A,
               const float* __restrict__ B0, const float* __restrict__ B1,
               float* __restrict__ C0, float* __restrict__ C1, int N, int K) {
    const float* B = blockIdx.z ? B1 : B0;
    float* C = blockIdx.z ? C1 : C0;
    gemm_body<128, false, false, false>(A, B, nullptr, nullptr, C, N, K,
                                        blockIdx.y * 128, blockIdx.x * 128);
}

// ---------------- fused edge attention: warp per query, online softmax ----------
__global__ void k_attn(const int* __restrict__ sidx,
                       const float* __restrict__ log_tau) {
    int warp = (blockIdx.x * blockDim.x + threadIdx.x) >> 5;
    int lane = threadIdx.x & 31;
    if (warp >= NQ) return;
    int q = warp;
    int st = g_rowptr[q], en = g_rowptr[q + 1];
    float scale = 0.17677669529663689f * expf(-log_tau[0]);

    const float4* qr = (const float4*)(g_Qf + (size_t)q * DD);
    float4 q0 = qr[lane * 2], q1 = qr[lane * 2 + 1];

    float m = 0.0f;           // reference: smax = max(0, segment max)
    float ssum = 0.0f;
    float4 a0 = {0.f, 0.f, 0.f, 0.f}, a1 = {0.f, 0.f, 0.f, 0.f};

    int e = st;
    for (; e + 1 < en; e += 2) {
        int sA = sidx[e], sB = sidx[e + 1];
        const float4* krA = (const float4*)(g_Kf + (size_t)sA * DD);
        const float4* krB = (const float4*)(g_Kf + (size_t)sB * DD);
        float4 kA0 = krA[lane * 2], kA1 = krA[lane * 2 + 1];
        float4 kB0 = krB[lane * 2], kB1 = krB[lane * 2 + 1];
        const float4* vrA = (const float4*)(g_Vf + (size_t)sA * DD);
        const float4* vrB = (const float4*)(g_Vf + (size_t)sB * DD);
        float4 vA0 = vrA[lane * 2], vA1 = vrA[lane * 2 + 1];
        float4 vB0 = vrB[lane * 2], vB1 = vrB[lane * 2 + 1];

        float dA = q0.x * kA0.x + q0.y * kA0.y + q0.z * kA0.z + q0.w * kA0.w +
                   q1.x * kA1.x + q1.y * kA1.y + q1.z * kA1.z + q1.w * kA1.w;
        float dB = q0.x * kB0.x + q0.y * kB0.y + q0.z * kB0.z + q0.w * kB0.w +
                   q1.x * kB1.x + q1.y * kB1.y + q1.z * kB1.z + q1.w * kB1.w;
        dA += __shfl_xor_sync(0xffffffffu, dA, 1);
        dA += __shfl_xor_sync(0xffffffffu, dA, 2);
        dB += __shfl_xor_sync(0xffffffffu, dB, 1);
        dB += __shfl_xor_sync(0xffffffffu, dB, 2);
        dA *= scale; dB *= scale;

        float mn = fmaxf(m, fmaxf(dA, dB));
        float c = __expf(m - mn);
        float rA = __expf(dA - mn);
        float rB = __expf(dB - mn);
        a0.x = a0.x * c + rA * vA0.x + rB * vB0.x;
        a0.y = a0.y * c + rA * vA0.y + rB * vB0.y;
        a0.z = a0.z * c + rA * vA0.z + rB * vB0.z;
        a0.w = a0.w * c + rA * vA0.w + rB * vB0.w;
        a1.x = a1.x * c + rA * vA1.x + rB * vB1.x;
        a1.y = a1.y * c + rA * vA1.y + rB * vB1.y;
        a1.z = a1.z * c + rA * vA1.z + rB * vB1.z;
        a1.w = a1.w * c + rA * vA1.w + rB * vB1.w;
        ssum = ssum * c + rA + rB;
        m = mn;
    }
    if (e < en) {
        int s = sidx[e];
        const float4* kr = (const float4*)(g_Kf + (size_t)s * DD);
        float4 k0 = kr[lane * 2], k1 = kr[lane * 2 + 1];
        float d = q0.x * k0.x + q0.y * k0.y + q0.z * k0.z + q0.w * k0.w +
                  q1.x * k1.x + q1.y * k1.y + q1.z * k1.z + q1.w * k1.w;
        d += __shfl_xor_sync(0xffffffffu, d, 1);
        d += __shfl_xor_sync(0xffffffffu, d, 2);
        d *= scale;
        float mn = fmaxf(m, d);
        float c = __expf(m - mn);
        float r = __expf(d - mn);
        const float4* vr = (const float4*)(g_Vf + (size_t)s * DD);
        float4 v0 = vr[lane * 2], v1 = vr[lane * 2 + 1];
        a0.x = a0.x * c + r * v0.x; a0.y = a0.y * c + r * v0.y;
        a0.z = a0.z * c + r * v0.z; a0.w = a0.w * c + r * v0.w;
        a1.x = a1.x * c + r * v1.x; a1.y = a1.y * c + r * v1.y;
        a1.z = a1.z * c + r * v1.z; a1.w = a1.w * c + r * v1.w;
        ssum = ssum * c + r;
        m = mn;
    }

    float inv = 1.0f / fmaxf(ssum, 1e-8f);
    float gsc = ssum * inv;
    const float4* gr = (const float4*)(g_Gf + (size_t)q * DD);
    float4 g0 = gr[lane * 2], g1 = gr[lane * 2 + 1];
    float4 o0, o1;
    o0.x = a0.x * inv + g0.x * gsc; o0.y = a0.y * inv + g0.y * gsc;
    o0.z = a0.z * inv + g0.z * gsc; o0.w = a0.w * inv + g0.w * gsc;
    o1.x = a1.x * inv + g1.x * gsc; o1.y = a1.y * inv + g1.y * gsc;
    o1.z = a1.z * inv + g1.z * gsc; o1.w = a1.w * inv + g1.w * gsc;
    float4* orow = (float4*)(g_out + (size_t)q * DD);
    orow[lane * 2] = o0;
    orow[lane * 2 + 1] = o1;
}

// ---------------- host launcher ----------------
static float* sym_f(const void* sym) {
    void* p = nullptr;
    cudaGetSymbolAddress(&p, sym);
    return (float*)p;
}

#define SMEM_BM(BM) ((2 * (BM) * 36 + 2 * 32 * 136) * (int)sizeof(float))

// Streams/events created once (first, non-captured call) and reused; smem
// attributes set once. No device allocation after the pre-capture baseline.
struct Ctx {
    cudaStream_t s1, s2;
    cudaEvent_t evRoot, evKV, evG;
    Ctx() {
        cudaStreamCreateWithFlags(&s1, cudaStreamNonBlocking);
        cudaStreamCreateWithFlags(&s2, cudaStreamNonBlocking);
        cudaEventCreateWithFlags(&evRoot, cudaEventDisableTiming);
        cudaEventCreateWithFlags(&evKV, cudaEventDisableTiming);
        cudaEventCreateWithFlags(&evG, cudaEventDisableTiming);
        cudaFuncSetAttribute((const void*)k_gemm_kv,
            cudaFuncAttributeMaxDynamicSharedMemorySize, SMEM_BM(128));
        cudaFuncSetAttribute((const void*)k_gemm_tc<64, false, false, false>,
            cudaFuncAttributeMaxDynamicSharedMemorySize, SMEM_BM(64));
        cudaFuncSetAttribute((const void*)k_gemm_tc<64, true, true, false>,
            cudaFuncAttributeMaxDynamicSharedMemorySize, SMEM_BM(64));
        cudaFuncSetAttribute((const void*)k_gemm_tc<64, true, false, true>,
            cudaFuncAttributeMaxDynamicSharedMemorySize, SMEM_BM(64));
    }
};

extern "C" void kernel_launch(void* const* d_in, const int* in_sizes, int n_in,
                              void* d_out, int out_size) {
    const float* query_tokens  = (const float*)d_in[0];
    const float* query_pos     = (const float*)d_in[1];
    const float* support_feats = (const float*)d_in[2];
    const float* support_pos   = (const float*)d_in[3];
    const float* Wq   = (const float*)d_in[4];
    const float* Wk   = (const float*)d_in[5];
    const float* Wv   = (const float*)d_in[6];
    const float* Wg   = (const float*)d_in[7];
    const float* Wo   = (const float*)d_in[8];
    const float* bo   = (const float*)d_in[9];
    const float* log_tau = (const float*)d_in[10];
    const float* ln1_g = (const float*)d_in[11];
    const float* ln1_b = (const float*)d_in[12];
    const float* ln2_g = (const float*)d_in[13];
    const float* ln2_b = (const float*)d_in[14];
    const float* Wf1  = (const float*)d_in[15];
    const float* bf1  = (const float*)d_in[16];
    const float* Wf2  = (const float*)d_in[17];
    const float* bf2  = (const float*)d_in[18];
    const float* Gw1  = (const float*)d_in[19];
    const float* Gb1  = (const float*)d_in[20];
    const float* Gw2  = (const float*)d_in[21];
    const float* Gb2  = (const float*)d_in[22];
    const int* q_idx  = (const int*)d_in[23];
    const int* s_idx  = (const int*)d_in[24];
    float* out = (float*)d_out;

    float* p_raw  = sym_f(g_raw);
    float* p_geoh = sym_f(g_geoh);
    float* p_geo  = sym_f(g_geo);
    float* p_qt   = sym_f(g_qt);
    float* p_Qf   = sym_f(g_Qf);
    float* p_Kf   = sym_f(g_Kf);
    float* p_Vf   = sym_f(g_Vf);
    float* p_Gf   = sym_f(g_Gf);
    float* p_out  = sym_f(g_out);
    float* p_x    = sym_f(g_x);
    float* p_h1   = sym_f(g_h1);

    static Ctx ctx;

    // fork
    cudaEventRecord(ctx.evRoot, 0);
    cudaStreamWaitEvent(ctx.s1, ctx.evRoot, 0);
    cudaStreamWaitEvent(ctx.s2, ctx.evRoot, 0);

    // s1: merged K/V projections (one 1024-CTA launch)
    k_gemm_kv<<<dim3(DD / 128, NS / 128, 2), 256, SMEM_BM(128), ctx.s1>>>(
        support_feats, Wk, Wv, p_Kf, p_Vf, DD, DD);
    cudaEventRecord(ctx.evKV, ctx.s1);

    // s2: geo chain
    k_rowptr<<<(NQ + 1 + 255) / 256, 256, 0, ctx.s2>>>(q_idx);
    k_geostats<<<NQ / 8, 256, 0, ctx.s2>>>(query_pos, support_pos, s_idx);
    k_gemm<true, true, false><<<dim3(NGEO / 64, NQ / 64), 256, 0, ctx.s2>>>(
        p_raw, Gw1, Gb1, nullptr, p_geoh, NQ, NGEO, 12);
    k_gemm_tc<64, true, true, false><<<dim3(NGEO / 128, NQ / 64), 256, SMEM_BM(64), ctx.s2>>>(
        p_geoh, Gw2, Gb2, nullptr, p_geo, NGEO, NGEO);
    k_gemm_tc<64, false, false, false><<<dim3(DD / 128, NQ / 64), 256, SMEM_BM(64), ctx.s2>>>(
        p_geo, Wg, nullptr, nullptr, p_Gf, DD, NGEO);
    cudaEventRecord(ctx.evG, ctx.s2);

    // s0 (default): query chain
    k_ln<<<NQ / 8, 256>>>(query_tokens, ln1_g, ln1_b, p_qt);
    k_gemm_tc<64, false, false, false><<<dim3(DD / 128, NQ / 64), 256, SMEM_BM(64)>>>(
        p_qt, Wq, nullptr, nullptr, p_Qf, DD, DD);

    // join, fused edge attention
    cudaStreamWaitEvent(0, ctx.evKV, 0);
    cudaStreamWaitEvent(0, ctx.evG, 0);
    k_attn<<<NQ / 8, 256>>>(s_idx, log_tau);

    // tail
    k_gemm_tc<64, true, false, true><<<dim3(DD / 128, NQ / 64), 256, SMEM_BM(64)>>>(
        p_out, Wo, bo, query_tokens, p_x, DD, DD);
    k_ln<<<NQ / 8, 256>>>(p_x, ln2_g, ln2_b, p_qt);
    k_gemm_tc<64, true, true, false><<<dim3(NFFN / 128, NQ / 64), 256, SMEM_BM(64)>>>(
        p_qt, Wf1, bf1, nullptr, p_h1, NFFN, DD);
    k_gemm_tc<64, true, false, true><<<dim3(DD / 128, NQ / 64), 256, SMEM_BM(64)>>>(
        p_h1, Wf2, bf2, p_x, out, DD, NFFN);
}

// round 7
// speedup vs baseline: 4.6966x; 1.2606x over previous
#include <cuda_runtime.h>
#include <cuda_fp16.h>
#include <math.h>

#define NQ 8192
#define NS 32768
#define NE 131072
#define DD 256
#define NH 8
#define HDIM 32
#define NGEO 128
#define NFFN 512

// ---------------- scratch (device globals; no allocation) ----------------
__device__ float  g_raw[NQ * 12];
__device__ float  g_x[NQ * DD];
__device__ int    g_rowptr[NQ + 1];

// half activations / weights
__device__ __half g_sf_h[NS * DD];
__device__ __half g_qt_h[NQ * DD];
__device__ __half g_geoh_h[NQ * NGEO];
__device__ __half g_geo_h[NQ * NGEO];
__device__ __half g_Qf_h[NQ * DD];
__device__ __half g_Kf_h[NS * DD];
__device__ __half g_Vf_h[NS * DD];
__device__ __half g_Gf_h[NQ * DD];
__device__ __half g_out_h[NQ * DD];
__device__ __half g_h1_h[NQ * NFFN];
__device__ __half g_Wq_h[DD * DD];
__device__ __half g_Wk_h[DD * DD];
__device__ __half g_Wv_h[DD * DD];
__device__ __half g_Wg_h[NGEO * DD];
__device__ __half g_Wo_h[DD * DD];
__device__ __half g_Wf1_h[DD * NFFN];
__device__ __half g_Wf2_h[NFFN * DD];
__device__ __half g_Gw2_h[NGEO * NGEO];

__device__ __forceinline__ float gelu_f(float x) {
    return 0.5f * x * (1.0f + erff(x * 0.7071067811865475f));
}

__device__ __forceinline__ void cpa16(void* dst, const void* src) {
    unsigned d = (unsigned)__cvta_generic_to_shared(dst);
    asm volatile("cp.async.cg.shared.global [%0], [%1], 16;" :: "r"(d), "l"(src));
}
__device__ __forceinline__ unsigned smem_u32(const void* p) {
    return (unsigned)__cvta_generic_to_shared(p);
}
__device__ __forceinline__ void unpack8(uint4 u, float* f) {
    float2 a = __half22float2(*(const __half2*)&u.x);
    float2 b = __half22float2(*(const __half2*)&u.y);
    float2 c = __half22float2(*(const __half2*)&u.z);
    float2 d = __half22float2(*(const __half2*)&u.w);
    f[0] = a.x; f[1] = a.y; f[2] = b.x; f[3] = b.y;
    f[4] = c.x; f[5] = c.y; f[6] = d.x; f[7] = d.y;
}

// ---------------- fp32 -> fp16 convert (vectorized) ----------------
__global__ void k_cvt(const float* __restrict__ src, __half* __restrict__ dst, int n4) {
    int i = blockIdx.x * blockDim.x + threadIdx.x;
    if (i >= n4) return;
    float4 v = ((const float4*)src)[i];
    __half2 h0 = __floats2half2_rn(v.x, v.y);
    __half2 h1 = __floats2half2_rn(v.z, v.w);
    uint2 u;
    u.x = *(unsigned*)&h0;
    u.y = *(unsigned*)&h1;
    ((uint2*)dst)[i] = u;
}

// ---------------- row_ptr via binary search (q_idx is sorted) ----------------
__global__ void k_rowptr(const int* __restrict__ qidx) {
    int q = blockIdx.x * blockDim.x + threadIdx.x;
    if (q > NQ) return;
    int lo = 0, hi = NE;
    while (lo < hi) {
        int mid = (lo + hi) >> 1;
        if (qidx[mid] < q) lo = mid + 1; else hi = mid;
    }
    g_rowptr[q] = lo;
}

// ---------------- geo stats: warp per query ----------------
__global__ void k_geostats(const float* __restrict__ qpos,
                           const float* __restrict__ spos,
                           const int* __restrict__ sidx) {
    int warp = (blockIdx.x * blockDim.x + threadIdx.x) >> 5;
    int lane = threadIdx.x & 31;
    if (warp >= NQ) return;
    int q = warp;
    int st = g_rowptr[q], en = g_rowptr[q + 1];
    float qp0 = qpos[q * 3 + 0], qp1 = qpos[q * 3 + 1], qp2 = qpos[q * 3 + 2];
    float s0 = 0.f, s1 = 0.f, s2 = 0.f;
    float ss0 = 0.f, ss1 = 0.f, ss2 = 0.f;
    float mn0 = 1e30f, mn1 = 1e30f, mn2 = 1e30f;
    float mx0 = -1e30f, mx1 = -1e30f, mx2 = -1e30f;
    for (int e = st + lane; e < en; e += 32) {
        int s = sidx[e];
        float r0 = spos[s * 3 + 0] - qp0;
        float r1 = spos[s * 3 + 1] - qp1;
        float r2 = spos[s * 3 + 2] - qp2;
        s0 += r0; s1 += r1; s2 += r2;
        ss0 += r0 * r0; ss1 += r1 * r1; ss2 += r2 * r2;
        mn0 = fminf(mn0, r0); mn1 = fminf(mn1, r1); mn2 = fminf(mn2, r2);
        mx0 = fmaxf(mx0, r0); mx1 = fmaxf(mx1, r1); mx2 = fmaxf(mx2, r2);
    }
    #pragma unroll
    for (int off = 16; off > 0; off >>= 1) {
        s0 += __shfl_xor_sync(0xffffffffu, s0, off);
        s1 += __shfl_xor_sync(0xffffffffu, s1, off);
        s2 += __shfl_xor_sync(0xffffffffu, s2, off);
        ss0 += __shfl_xor_sync(0xffffffffu, ss0, off);
        ss1 += __shfl_xor_sync(0xffffffffu, ss1, off);
        ss2 += __shfl_xor_sync(0xffffffffu, ss2, off);
        mn0 = fminf(mn0, __shfl_xor_sync(0xffffffffu, mn0, off));
        mn1 = fminf(mn1, __shfl_xor_sync(0xffffffffu, mn1, off));
        mn2 = fminf(mn2, __shfl_xor_sync(0xffffffffu, mn2, off));
        mx0 = fmaxf(mx0, __shfl_xor_sync(0xffffffffu, mx0, off));
        mx1 = fmaxf(mx1, __shfl_xor_sync(0xffffffffu, mx1, off));
        mx2 = fmaxf(mx2, __shfl_xor_sync(0xffffffffu, mx2, off));
    }
    if (lane == 0) {
        float cnt = fmaxf((float)(en - st), 1.0f);
        float m0 = s0 / cnt, m1 = s1 / cnt, m2 = s2 / cnt;
        float v0 = fmaxf(ss0 / cnt - m0 * m0, 0.f);
        float v1 = fmaxf(ss1 / cnt - m1 * m1, 0.f);
        float v2 = fmaxf(ss2 / cnt - m2 * m2, 0.f);
        float* r = g_raw + q * 12;
        r[0] = m0; r[1] = m1; r[2] = m2;
        r[3] = sqrtf(v0); r[4] = sqrtf(v1); r[5] = sqrtf(v2);
        r[6] = fminf(fmaxf(mn0, -100.f), 100.f);
        r[7] = fminf(fmaxf(mn1, -100.f), 100.f);
        r[8] = fminf(fmaxf(mn2, -100.f), 100.f);
        r[9]  = fminf(fmaxf(mx0, -100.f), 100.f);
        r[10] = fminf(fmaxf(mx1, -100.f), 100.f);
        r[11] = fminf(fmaxf(mx2, -100.f), 100.f);
    }
}

// ---------------- LayerNorm: warp per row, fp32 in, fp16 out ----------------
__global__ void k_ln(const float* __restrict__ x, const float* __restrict__ g,
                     const float* __restrict__ b, __half* __restrict__ y) {
    int warp = (blockIdx.x * blockDim.x + threadIdx.x) >> 5;
    int lane = threadIdx.x & 31;
    if (warp >= NQ) return;
    const float4* xr = (const float4*)(x + warp * DD);
    float4 a = xr[lane * 2], c = xr[lane * 2 + 1];
    float sum = a.x + a.y + a.z + a.w + c.x + c.y + c.z + c.w;
    float ss = a.x * a.x + a.y * a.y + a.z * a.z + a.w * a.w +
               c.x * c.x + c.y * c.y + c.z * c.z + c.w * c.w;
    #pragma unroll
    for (int off = 16; off > 0; off >>= 1) {
        sum += __shfl_xor_sync(0xffffffffu, sum, off);
        ss  += __shfl_xor_sync(0xffffffffu, ss, off);
    }
    float mean = sum * (1.0f / 256.0f);
    float var = ss * (1.0f / 256.0f) - mean * mean;
    float rstd = rsqrtf(var + 1e-5f);
    const float4* gr = (const float4*)g;
    const float4* br = (const float4*)b;
    float4 g0 = gr[lane * 2], g1 = gr[lane * 2 + 1];
    float4 b0 = br[lane * 2], b1 = br[lane * 2 + 1];
    float o[8];
    o[0] = (a.x - mean) * rstd * g0.x + b0.x;
    o[1] = (a.y - mean) * rstd * g0.y + b0.y;
    o[2] = (a.z - mean) * rstd * g0.z + b0.z;
    o[3] = (a.w - mean) * rstd * g0.w + b0.w;
    o[4] = (c.x - mean) * rstd * g1.x + b1.x;
    o[5] = (c.y - mean) * rstd * g1.y + b1.y;
    o[6] = (c.z - mean) * rstd * g1.z + b1.z;
    o[7] = (c.w - mean) * rstd * g1.w + b1.w;
    __half2 h0 = __floats2half2_rn(o[0], o[1]);
    __half2 h1 = __floats2half2_rn(o[2], o[3]);
    __half2 h2 = __floats2half2_rn(o[4], o[5]);
    __half2 h3 = __floats2half2_rn(o[6], o[7]);
    uint4 u;
    u.x = *(unsigned*)&h0; u.y = *(unsigned*)&h1;
    u.z = *(unsigned*)&h2; u.w = *(unsigned*)&h3;
    ((uint4*)(y + (size_t)warp * DD))[lane] = u;
}

// ---------------- fp32 GEMM (K=12 geo1), half output ----------------
__global__ void k_gemm12(const float* __restrict__ A, const float* __restrict__ B,
                         const float* __restrict__ bias, __half* __restrict__ C,
                         int M, int N, int K) {
    __shared__ float As[64][17];
    __shared__ float Bs[16][64];
    int tid = threadIdx.x;
    int tx = tid & 15, ty = tid >> 4;
    int m0 = blockIdx.y * 64, n0 = blockIdx.x * 64;
    float acc[4][4] = {};
    int KT = (K + 15) >> 4;
    for (int kt = 0; kt < KT; kt++) {
        int k0 = kt << 4;
        #pragma unroll
        for (int i = 0; i < 4; i++) {
            int lin = tid + i * 256;
            int ar = lin >> 4, ac = lin & 15;
            int gk = k0 + ac;
            As[ar][ac] = (gk < K) ? A[(size_t)(m0 + ar) * K + gk] : 0.f;
        }
        #pragma unroll
        for (int i = 0; i < 4; i++) {
            int lin = tid + i * 256;
            int br = lin >> 6, bc = lin & 63;
            int gk = k0 + br;
            Bs[br][bc] = (gk < K) ? B[(size_t)gk * N + n0 + bc] : 0.f;
        }
        __syncthreads();
        #pragma unroll
        for (int kk = 0; kk < 16; kk++) {
            float av[4];
            #pragma unroll
            for (int i = 0; i < 4; i++) av[i] = As[ty * 4 + i][kk];
            float4 bv = *(const float4*)&Bs[kk][tx * 4];
            float bvv[4] = {bv.x, bv.y, bv.z, bv.w};
            #pragma unroll
            for (int i = 0; i < 4; i++)
                #pragma unroll
                for (int j = 0; j < 4; j++)
                    acc[i][j] = fmaf(av[i], bvv[j], acc[i][j]);
        }
        __syncthreads();
    }
    #pragma unroll
    for (int i = 0; i < 4; i++) {
        int row = m0 + ty * 4 + i;
        #pragma unroll
        for (int j = 0; j < 4; j++) {
            int col = n0 + tx * 4 + j;
            float v = acc[i][j] + bias[col];
            v = gelu_f(v);
            C[(size_t)row * N + col] = __float2half_rn(v);
        }
    }
}

// ---------------- FP16 tensor-core GEMM, BK=32, cp.async 2-stage ----------------
// A[M,K], B[K,N] half; C = act(A@B + bias)(+res), half or float out.
// 256 thr = 8 warps (2m x 4n); warp tile (BM/2)x32; mma m16n8k16 via ldmatrix.
template <int BM, bool BIAS, bool GELU, bool RES, bool HOUT>
__device__ __forceinline__ void hgemm_body(
    const __half* __restrict__ A, const __half* __restrict__ B,
    const float* __restrict__ bias, const float* __restrict__ res,
    void* __restrict__ Cv, int N, int K, int m0, int n0) {
    constexpr int SA = 40, SB = 136;   // halves per row (pad)
    constexpr int MI = BM / 32;
    extern __shared__ __half smem[];
    __half (*As)[BM][SA] = reinterpret_cast<__half(*)[BM][SA]>(smem);
    __half (*Bs)[32][SB] = reinterpret_cast<__half(*)[32][SB]>(smem + 2 * BM * SA);

    int tid = threadIdx.x;
    int warp = tid >> 5, lane = tid & 31;
    int wm = warp & 1, wn = warp >> 1;
    int g = lane >> 2, t = lane & 3;

    float acc[MI][4][4];
    #pragma unroll
    for (int i = 0; i < MI; i++)
        #pragma unroll
        for (int j = 0; j < 4; j++)
            #pragma unroll
            for (int c = 0; c < 4; c++) acc[i][j][c] = 0.f;

    int KT = K >> 5;
    // stage loads: A BM x 32 halves = BM*4 16B-chunks; B 32 x 128 halves = 512 chunks
    #pragma unroll
    for (int i = 0; i < BM / 64; i++) {
        int lin = tid + i * 256;
        int row = lin >> 2, col = (lin & 3) * 8;
        cpa16(&As[0][row][col], &A[(size_t)(m0 + row) * K + col]);
    }
    #pragma unroll
    for (int i = 0; i < 2; i++) {
        int lin = tid + i * 256;
        int row = lin >> 4, col = (lin & 15) * 8;
        cpa16(&Bs[0][row][col], &B[(size_t)row * N + n0 + col]);
    }
    asm volatile("cp.async.commit_group;");

    int buf = 0;
    for (int kt = 0; kt < KT; kt++) {
        if (kt + 1 < KT) {
            int k0 = (kt + 1) << 5;
            #pragma unroll
            for (int i = 0; i < BM / 64; i++) {
                int lin = tid + i * 256;
                int row = lin >> 2, col = (lin & 3) * 8;
                cpa16(&As[buf ^ 1][row][col], &A[(size_t)(m0 + row) * K + k0 + col]);
            }
            #pragma unroll
            for (int i = 0; i < 2; i++) {
                int lin = tid + i * 256;
                int row = lin >> 4, col = (lin & 15) * 8;
                cpa16(&Bs[buf ^ 1][row][col], &B[(size_t)(k0 + row) * N + n0 + col]);
            }
            asm volatile("cp.async.commit_group;");
            asm volatile("cp.async.wait_group 1;");
        } else {
            asm volatile("cp.async.wait_group 0;");
        }
        __syncthreads();
        #pragma unroll
        for (int ks = 0; ks < 32; ks += 16) {
            unsigned a[MI][4], b[4][2];
            #pragma unroll
            for (int mi = 0; mi < MI; mi++) {
                int row = wm * (BM / 2) + mi * 16 + (lane & 7) + ((lane >> 3) & 1) * 8;
                int col = ks + (lane >> 4) * 8;
                unsigned addr = smem_u32(&As[buf][row][col]);
                asm volatile(
                    "ldmatrix.sync.aligned.m8n8.x4.shared.b16 {%0,%1,%2,%3}, [%4];"
                    : "=r"(a[mi][0]), "=r"(a[mi][1]), "=r"(a[mi][2]), "=r"(a[mi][3])
                    : "r"(addr));
            }
            #pragma unroll
            for (int p = 0; p < 2; p++) {
                int krow = ks + (lane & 7) + ((lane >> 3) & 1) * 8;
                int ncol = wn * 32 + p * 16 + (lane >> 4) * 8;
                unsigned addr = smem_u32(&Bs[buf][krow][ncol]);
                unsigned r0, r1, r2, r3;
                asm volatile(
                    "ldmatrix.sync.aligned.m8n8.x4.trans.shared.b16 {%0,%1,%2,%3}, [%4];"
                    : "=r"(r0), "=r"(r1), "=r"(r2), "=r"(r3) : "r"(addr));
                b[2 * p][0] = r0; b[2 * p][1] = r1;
                b[2 * p + 1][0] = r2; b[2 * p + 1][1] = r3;
            }
            #pragma unroll
            for (int mi = 0; mi < MI; mi++)
                #pragma unroll
                for (int ni = 0; ni < 4; ni++) {
                    asm volatile(
                        "mma.sync.aligned.m16n8k16.row.col.f32.f16.f16.f32 "
                        "{%0,%1,%2,%3}, {%4,%5,%6,%7}, {%8,%9}, {%0,%1,%2,%3};"
                        : "+f"(acc[mi][ni][0]), "+f"(acc[mi][ni][1]),
                          "+f"(acc[mi][ni][2]), "+f"(acc[mi][ni][3])
                        : "r"(a[mi][0]), "r"(a[mi][1]), "r"(a[mi][2]), "r"(a[mi][3]),
                          "r"(b[ni][0]), "r"(b[ni][1]));
                }
        }
        buf ^= 1;
        __syncthreads();
    }
    // epilogue
    #pragma unroll
    for (int mi = 0; mi < MI; mi++) {
        int mrow = m0 + wm * (BM / 2) + mi * 16 + g;
        #pragma unroll
        for (int ni = 0; ni < 4; ni++) {
            int ncol = n0 + wn * 32 + ni * 8 + 2 * t;
            #pragma unroll
            for (int half = 0; half < 2; half++) {
                int row = mrow + half * 8;
                float v0 = acc[mi][ni][half * 2 + 0];
                float v1 = acc[mi][ni][half * 2 + 1];
                if (BIAS) { v0 += bias[ncol]; v1 += bias[ncol + 1]; }
                if (GELU) { v0 = gelu_f(v0); v1 = gelu_f(v1); }
                if (RES) {
                    const float2 r = *(const float2*)&res[(size_t)row * N + ncol];
                    v0 += r.x; v1 += r.y;
                }
                if (HOUT) {
                    __half2 h = __floats2half2_rn(v0, v1);
                    *(__half2*)&((__half*)Cv)[(size_t)row * N + ncol] = h;
                } else {
                    float2 o; o.x = v0; o.y = v1;
                    *(float2*)&((float*)Cv)[(size_t)row * N + ncol] = o;
                }
            }
        }
    }
}

template <int BM, bool BIAS, bool GELU, bool RES, bool HOUT>
__global__ __launch_bounds__(256, 2)
void k_hgemm(const __half* __restrict__ A, const __half* __restrict__ B,
             const float* __restrict__ bias, const float* __restrict__ res,
             void* __restrict__ C, int N, int K) {
    hgemm_body<BM, BIAS, GELU, RES, HOUT>(A, B, bias, res, C, N, K,
                                          blockIdx.y * BM, blockIdx.x * 128);
}

// Merged K/V projection: blockIdx.z selects (Wk->Kf) or (Wv->Vf).
__global__ __launch_bounds__(256, 2)
void k_hgemm_kv(const __half* __restrict__ A,
                const __half* __restrict__ B0, const __half* __restrict__ B1,
                __half* __restrict__ C0, __half* __restrict__ C1, int N, int K) {
    const __half* B = blockIdx.z ? B1 : B0;
    __half* C = blockIdx.z ? C1 : C0;
    hgemm_body<128, false, false, false, true>(A, B, nullptr, nullptr, C, N, K,
                                               blockIdx.y * 128, blockIdx.x * 128);
}

// ---------------- fused edge attention: warp per query, online softmax ----------
__global__ void k_attn(const int* __restrict__ sidx,
                       const float* __restrict__ log_tau) {
    int warp = (blockIdx.x * blockDim.x + threadIdx.x) >> 5;
    int lane = threadIdx.x & 31;
    if (warp >= NQ) return;
    int q = warp;
    int st = g_rowptr[q], en = g_rowptr[q + 1];
    float scale = 0.17677669529663689f * expf(-log_tau[0]);

    float qv[8];
    unpack8(((const uint4*)(g_Qf_h + (size_t)q * DD))[lane], qv);

    float m = 0.0f;   // reference: smax = max(0, segment max)
    float ssum = 0.0f;
    float a[8] = {0.f, 0.f, 0.f, 0.f, 0.f, 0.f, 0.f, 0.f};

    int e = st;
    for (; e + 1 < en; e += 2) {
        int sA = sidx[e], sB = sidx[e + 1];
        float kA[8], kB[8], vA[8], vB[8];
        unpack8(((const uint4*)(g_Kf_h + (size_t)sA * DD))[lane], kA);
        unpack8(((const uint4*)(g_Kf_h + (size_t)sB * DD))[lane], kB);
        unpack8(((const uint4*)(g_Vf_h + (size_t)sA * DD))[lane], vA);
        unpack8(((const uint4*)(g_Vf_h + (size_t)sB * DD))[lane], vB);
        float dA = 0.f, dB = 0.f;
        #pragma unroll
        for (int j = 0; j < 8; j++) { dA += qv[j] * kA[j]; dB += qv[j] * kB[j]; }
        dA += __shfl_xor_sync(0xffffffffu, dA, 1);
        dA += __shfl_xor_sync(0xffffffffu, dA, 2);
        dB += __shfl_xor_sync(0xffffffffu, dB, 1);
        dB += __shfl_xor_sync(0xffffffffu, dB, 2);
        dA *= scale; dB *= scale;
        float mn = fmaxf(m, fmaxf(dA, dB));
        float c = __expf(m - mn);
        float rA = __expf(dA - mn);
        float rB = __expf(dB - mn);
        #pragma unroll
        for (int j = 0; j < 8; j++) a[j] = a[j] * c + rA * vA[j] + rB * vB[j];
        ssum = ssum * c + rA + rB;
        m = mn;
    }
    if (e < en) {
        int s = sidx[e];
        float kv[8], vv[8];
        unpack8(((const uint4*)(g_Kf_h + (size_t)s * DD))[lane], kv);
        unpack8(((const uint4*)(g_Vf_h + (size_t)s * DD))[lane], vv);
        float d = 0.f;
        #pragma unroll
        for (int j = 0; j < 8; j++) d += qv[j] * kv[j];
        d += __shfl_xor_sync(0xffffffffu, d, 1);
        d += __shfl_xor_sync(0xffffffffu, d, 2);
        d *= scale;
        float mn = fmaxf(m, d);
        float c = __expf(m - mn);
        float r = __expf(d - mn);
        #pragma unroll
        for (int j = 0; j < 8; j++) a[j] = a[j] * c + r * vv[j];
        ssum = ssum * c + r;
        m = mn;
    }

    float inv = 1.0f / fmaxf(ssum, 1e-8f);
    float gsc = ssum * inv;
    float gv[8];
    unpack8(((const uint4*)(g_Gf_h + (size_t)q * DD))[lane], gv);
    float o[8];
    #pragma unroll
    for (int j = 0; j < 8; j++) o[j] = a[j] * inv + gv[j] * gsc;
    __half2 h0 = __floats2half2_rn(o[0], o[1]);
    __half2 h1 = __floats2half2_rn(o[2], o[3]);
    __half2 h2 = __floats2half2_rn(o[4], o[5]);
    __half2 h3 = __floats2half2_rn(o[6], o[7]);
    uint4 u;
    u.x = *(unsigned*)&h0; u.y = *(unsigned*)&h1;
    u.z = *(unsigned*)&h2; u.w = *(unsigned*)&h3;
    ((uint4*)(g_out_h + (size_t)q * DD))[lane] = u;
}

// ---------------- host ----------------
template <typename T>
static T* symp(const void* sym) {
    void* p = nullptr;
    cudaGetSymbolAddress(&p, sym);
    return (T*)p;
}

#define SMEM_H(BM) ((2 * (BM) * 40 + 2 * 32 * 136) * (int)sizeof(__half))

struct Ctx {
    cudaStream_t s1, s2;
    cudaEvent_t evRoot, evKV, evG;
    Ctx() {
        cudaStreamCreateWithFlags(&s1, cudaStreamNonBlocking);
        cudaStreamCreateWithFlags(&s2, cudaStreamNonBlocking);
        cudaEventCreateWithFlags(&evRoot, cudaEventDisableTiming);
        cudaEventCreateWithFlags(&evKV, cudaEventDisableTiming);
        cudaEventCreateWithFlags(&evG, cudaEventDisableTiming);
        cudaFuncSetAttribute((const void*)k_hgemm_kv,
            cudaFuncAttributeMaxDynamicSharedMemorySize, SMEM_H(128));
        cudaFuncSetAttribute((const void*)k_hgemm<64, false, false, false, true>,
            cudaFuncAttributeMaxDynamicSharedMemorySize, SMEM_H(64));
        cudaFuncSetAttribute((const void*)k_hgemm<64, true, true, false, true>,
            cudaFuncAttributeMaxDynamicSharedMemorySize, SMEM_H(64));
        cudaFuncSetAttribute((const void*)k_hgemm<64, true, false, true, false>,
            cudaFuncAttributeMaxDynamicSharedMemorySize, SMEM_H(64));
    }
};

extern "C" void kernel_launch(void* const* d_in, const int* in_sizes, int n_in,
                              void* d_out, int out_size) {
    const float* query_tokens  = (const float*)d_in[0];
    const float* query_pos     = (const float*)d_in[1];
    const float* support_feats = (const float*)d_in[2];
    const float* support_pos   = (const float*)d_in[3];
    const float* Wq   = (const float*)d_in[4];
    const float* Wk   = (const float*)d_in[5];
    const float* Wv   = (const float*)d_in[6];
    const float* Wg   = (const float*)d_in[7];
    const float* Wo   = (const float*)d_in[8];
    const float* bo   = (const float*)d_in[9];
    const float* log_tau = (const float*)d_in[10];
    const float* ln1_g = (const float*)d_in[11];
    const float* ln1_b = (const float*)d_in[12];
    const float* ln2_g = (const float*)d_in[13];
    const float* ln2_b = (const float*)d_in[14];
    const float* Wf1  = (const float*)d_in[15];
    const float* bf1  = (const float*)d_in[16];
    const float* Wf2  = (const float*)d_in[17];
    const float* bf2  = (const float*)d_in[18];
    const float* Gw1  = (const float*)d_in[19];
    const float* Gb1  = (const float*)d_in[20];
    const float* Gw2  = (const float*)d_in[21];
    const float* Gb2  = (const float*)d_in[22];
    const int* q_idx  = (const int*)d_in[23];
    const int* s_idx  = (const int*)d_in[24];
    float* out = (float*)d_out;

    float*  p_raw   = symp<float>(g_raw);
    float*  p_x     = symp<float>(g_x);
    __half* p_sf    = symp<__half>(g_sf_h);
    __half* p_qt    = symp<__half>(g_qt_h);
    __half* p_geoh  = symp<__half>(g_geoh_h);
    __half* p_geo   = symp<__half>(g_geo_h);
    __half* p_Qf    = symp<__half>(g_Qf_h);
    __half* p_Kf    = symp<__half>(g_Kf_h);
    __half* p_Vf    = symp<__half>(g_Vf_h);
    __half* p_Gf    = symp<__half>(g_Gf_h);
    __half* p_outh  = symp<__half>(g_out_h);
    __half* p_h1    = symp<__half>(g_h1_h);
    __half* p_Wq    = symp<__half>(g_Wq_h);
    __half* p_Wk    = symp<__half>(g_Wk_h);
    __half* p_Wv    = symp<__half>(g_Wv_h);
    __half* p_Wg    = symp<__half>(g_Wg_h);
    __half* p_Wo    = symp<__half>(g_Wo_h);
    __half* p_Wf1   = symp<__half>(g_Wf1_h);
    __half* p_Wf2   = symp<__half>(g_Wf2_h);
    __half* p_Gw2   = symp<__half>(g_Gw2_h);

    static Ctx ctx;

    // fork
    cudaEventRecord(ctx.evRoot, 0);
    cudaStreamWaitEvent(ctx.s1, ctx.evRoot, 0);
    cudaStreamWaitEvent(ctx.s2, ctx.evRoot, 0);

    // s1: converts + merged K/V projection
    k_cvt<<<(NS * DD / 4 + 255) / 256, 256, 0, ctx.s1>>>(support_feats, p_sf, NS * DD / 4);
    k_cvt<<<(DD * DD / 4 + 255) / 256, 256, 0, ctx.s1>>>(Wk, p_Wk, DD * DD / 4);
    k_cvt<<<(DD * DD / 4 + 255) / 256, 256, 0, ctx.s1>>>(Wv, p_Wv, DD * DD / 4);
    k_hgemm_kv<<<dim3(DD / 128, NS / 128, 2), 256, SMEM_H(128), ctx.s1>>>(
        p_sf, p_Wk, p_Wv, p_Kf, p_Vf, DD, DD);
    cudaEventRecord(ctx.evKV, ctx.s1);

    // s2: geo chain
    k_rowptr<<<(NQ + 1 + 255) / 256, 256, 0, ctx.s2>>>(q_idx);
    k_geostats<<<NQ / 8, 256, 0, ctx.s2>>>(query_pos, support_pos, s_idx);
    k_cvt<<<(NGEO * NGEO / 4 + 255) / 256, 256, 0, ctx.s2>>>(Gw2, p_Gw2, NGEO * NGEO / 4);
    k_cvt<<<(NGEO * DD / 4 + 255) / 256, 256, 0, ctx.s2>>>(Wg, p_Wg, NGEO * DD / 4);
    k_gemm12<<<dim3(NGEO / 64, NQ / 64), 256, 0, ctx.s2>>>(
        p_raw, Gw1, Gb1, p_geoh, NQ, NGEO, 12);
    k_hgemm<64, true, true, false, true><<<dim3(NGEO / 128, NQ / 64), 256, SMEM_H(64), ctx.s2>>>(
        p_geoh, p_Gw2, Gb2, nullptr, p_geo, NGEO, NGEO);
    k_hgemm<64, false, false, false, true><<<dim3(DD / 128, NQ / 64), 256, SMEM_H(64), ctx.s2>>>(
        p_geo, p_Wg, nullptr, nullptr, p_Gf, DD, NGEO);
    cudaEventRecord(ctx.evG, ctx.s2);

    // s0 (default): query chain + remaining weight converts
    k_cvt<<<(DD * DD / 4 + 255) / 256, 256>>>(Wq, p_Wq, DD * DD / 4);
    k_ln<<<NQ / 8, 256>>>(query_tokens, ln1_g, ln1_b, p_qt);
    k_hgemm<64, false, false, false, true><<<dim3(DD / 128, NQ / 64), 256, SMEM_H(64)>>>(
        p_qt, p_Wq, nullptr, nullptr, p_Qf, DD, DD);
    k_cvt<<<(DD * DD / 4 + 255) / 256, 256>>>(Wo, p_Wo, DD * DD / 4);
    k_cvt<<<(DD * NFFN / 4 + 255) / 256, 256>>>(Wf1, p_Wf1, DD * NFFN / 4);
    k_cvt<<<(NFFN * DD / 4 + 255) / 256, 256>>>(Wf2, p_Wf2, NFFN * DD / 4);

    // join, fused edge attention
    cudaStreamWaitEvent(0, ctx.evKV, 0);
    cudaStreamWaitEvent(0, ctx.evG, 0);
    k_attn<<<NQ / 8, 256>>>(s_idx, log_tau);

    // tail
    k_hgemm<64, true, false, true, false><<<dim3(DD / 128, NQ / 64), 256, SMEM_H(64)>>>(
        p_outh, p_Wo, bo, query_tokens, p_x, DD, DD);
    k_ln<<<NQ / 8, 256>>>(p_x, ln2_g, ln2_b, p_qt);
    k_hgemm<64, true, true, false, true><<<dim3(NFFN / 128, NQ / 64), 256, SMEM_H(64)>>>(
        p_qt, p_Wf1, bf1, nullptr, p_h1, NFFN, DD);
    k_hgemm<64, true, false, true, false><<<dim3(DD / 128, NQ / 64), 256, SMEM_H(64)>>>(
        p_h1, p_Wf2, bf2, p_x, out, DD, NFFN);
}

// round 8
// speedup vs baseline: 4.8267x; 1.0277x over previous
#include <cuda_runtime.h>
#include <cuda_fp16.h>
#include <math.h>

#define NQ 8192
#define NS 32768
#define NE 131072
#define DD 256
#define NH 8
#define HDIM 32
#define NGEO 128
#define NFFN 512

// ---------------- scratch (device globals; no allocation) ----------------
__device__ float  g_raw[NQ * 12];
__device__ float  g_x[NQ * DD];
__device__ int    g_rowptr[NQ + 1];

// half activations / weights
__device__ __half g_qt_h[NQ * DD];
__device__ __half g_geoh_h[NQ * NGEO];
__device__ __half g_geo_h[NQ * NGEO];
__device__ __half g_Qf_h[NQ * DD];
__device__ __half g_Kf_h[NS * DD];
__device__ __half g_Vf_h[NS * DD];
__device__ __half g_Gf_h[NQ * DD];
__device__ __half g_out_h[NQ * DD];
__device__ __half g_h1_h[NQ * NFFN];
__device__ __half g_Wq_h[DD * DD];
__device__ __half g_Wk_h[DD * DD];
__device__ __half g_Wv_h[DD * DD];
__device__ __half g_Wg_h[NGEO * DD];
__device__ __half g_Wo_h[DD * DD];
__device__ __half g_Wf1_h[DD * NFFN];
__device__ __half g_Wf2_h[NFFN * DD];
__device__ __half g_Gw2_h[NGEO * NGEO];

__device__ __forceinline__ float gelu_f(float x) {
    return 0.5f * x * (1.0f + erff(x * 0.7071067811865475f));
}

__device__ __forceinline__ void cpa16(void* dst, const void* src) {
    unsigned d = (unsigned)__cvta_generic_to_shared(dst);
    asm volatile("cp.async.cg.shared.global [%0], [%1], 16;" :: "r"(d), "l"(src));
}
__device__ __forceinline__ unsigned smem_u32(const void* p) {
    return (unsigned)__cvta_generic_to_shared(p);
}
__device__ __forceinline__ void unpack8(uint4 u, float* f) {
    float2 a = __half22float2(*(const __half2*)&u.x);
    float2 b = __half22float2(*(const __half2*)&u.y);
    float2 c = __half22float2(*(const __half2*)&u.z);
    float2 d = __half22float2(*(const __half2*)&u.w);
    f[0] = a.x; f[1] = a.y; f[2] = b.x; f[3] = b.y;
    f[4] = c.x; f[5] = c.y; f[6] = d.x; f[7] = d.y;
}

// ---------------- fp32 -> fp16 convert (vectorized) ----------------
__global__ void k_cvt(const float* __restrict__ src, __half* __restrict__ dst, int n4) {
    int i = blockIdx.x * blockDim.x + threadIdx.x;
    if (i >= n4) return;
    float4 v = ((const float4*)src)[i];
    __half2 h0 = __floats2half2_rn(v.x, v.y);
    __half2 h1 = __floats2half2_rn(v.z, v.w);
    uint2 u;
    u.x = *(unsigned*)&h0;
    u.y = *(unsigned*)&h1;
    ((uint2*)dst)[i] = u;
}

// ---------------- row_ptr via binary search (q_idx is sorted) ----------------
__global__ void k_rowptr(const int* __restrict__ qidx) {
    int q = blockIdx.x * blockDim.x + threadIdx.x;
    if (q > NQ) return;
    int lo = 0, hi = NE;
    while (lo < hi) {
        int mid = (lo + hi) >> 1;
        if (qidx[mid] < q) lo = mid + 1; else hi = mid;
    }
    g_rowptr[q] = lo;
}

// ---------------- geo stats: warp per query ----------------
__global__ void k_geostats(const float* __restrict__ qpos,
                           const float* __restrict__ spos,
                           const int* __restrict__ sidx) {
    int warp = (blockIdx.x * blockDim.x + threadIdx.x) >> 5;
    int lane = threadIdx.x & 31;
    if (warp >= NQ) return;
    int q = warp;
    int st = g_rowptr[q], en = g_rowptr[q + 1];
    float qp0 = qpos[q * 3 + 0], qp1 = qpos[q * 3 + 1], qp2 = qpos[q * 3 + 2];
    float s0 = 0.f, s1 = 0.f, s2 = 0.f;
    float ss0 = 0.f, ss1 = 0.f, ss2 = 0.f;
    float mn0 = 1e30f, mn1 = 1e30f, mn2 = 1e30f;
    float mx0 = -1e30f, mx1 = -1e30f, mx2 = -1e30f;
    for (int e = st + lane; e < en; e += 32) {
        int s = sidx[e];
        float r0 = spos[s * 3 + 0] - qp0;
        float r1 = spos[s * 3 + 1] - qp1;
        float r2 = spos[s * 3 + 2] - qp2;
        s0 += r0; s1 += r1; s2 += r2;
        ss0 += r0 * r0; ss1 += r1 * r1; ss2 += r2 * r2;
        mn0 = fminf(mn0, r0); mn1 = fminf(mn1, r1); mn2 = fminf(mn2, r2);
        mx0 = fmaxf(mx0, r0); mx1 = fmaxf(mx1, r1); mx2 = fmaxf(mx2, r2);
    }
    #pragma unroll
    for (int off = 16; off > 0; off >>= 1) {
        s0 += __shfl_xor_sync(0xffffffffu, s0, off);
        s1 += __shfl_xor_sync(0xffffffffu, s1, off);
        s2 += __shfl_xor_sync(0xffffffffu, s2, off);
        ss0 += __shfl_xor_sync(0xffffffffu, ss0, off);
        ss1 += __shfl_xor_sync(0xffffffffu, ss1, off);
        ss2 += __shfl_xor_sync(0xffffffffu, ss2, off);
        mn0 = fminf(mn0, __shfl_xor_sync(0xffffffffu, mn0, off));
        mn1 = fminf(mn1, __shfl_xor_sync(0xffffffffu, mn1, off));
        mn2 = fminf(mn2, __shfl_xor_sync(0xffffffffu, mn2, off));
        mx0 = fmaxf(mx0, __shfl_xor_sync(0xffffffffu, mx0, off));
        mx1 = fmaxf(mx1, __shfl_xor_sync(0xffffffffu, mx1, off));
        mx2 = fmaxf(mx2, __shfl_xor_sync(0xffffffffu, mx2, off));
    }
    if (lane == 0) {
        float cnt = fmaxf((float)(en - st), 1.0f);
        float m0 = s0 / cnt, m1 = s1 / cnt, m2 = s2 / cnt;
        float v0 = fmaxf(ss0 / cnt - m0 * m0, 0.f);
        float v1 = fmaxf(ss1 / cnt - m1 * m1, 0.f);
        float v2 = fmaxf(ss2 / cnt - m2 * m2, 0.f);
        float* r = g_raw + q * 12;
        r[0] = m0; r[1] = m1; r[2] = m2;
        r[3] = sqrtf(v0); r[4] = sqrtf(v1); r[5] = sqrtf(v2);
        r[6] = fminf(fmaxf(mn0, -100.f), 100.f);
        r[7] = fminf(fmaxf(mn1, -100.f), 100.f);
        r[8] = fminf(fmaxf(mn2, -100.f), 100.f);
        r[9]  = fminf(fmaxf(mx0, -100.f), 100.f);
        r[10] = fminf(fmaxf(mx1, -100.f), 100.f);
        r[11] = fminf(fmaxf(mx2, -100.f), 100.f);
    }
}

// ---------------- LayerNorm: warp per row, fp32 in, fp16 out ----------------
__global__ void k_ln(const float* __restrict__ x, const float* __restrict__ g,
                     const float* __restrict__ b, __half* __restrict__ y) {
    int warp = (blockIdx.x * blockDim.x + threadIdx.x) >> 5;
    int lane = threadIdx.x & 31;
    if (warp >= NQ) return;
    const float4* xr = (const float4*)(x + warp * DD);
    float4 a = xr[lane * 2], c = xr[lane * 2 + 1];
    float sum = a.x + a.y + a.z + a.w + c.x + c.y + c.z + c.w;
    float ss = a.x * a.x + a.y * a.y + a.z * a.z + a.w * a.w +
               c.x * c.x + c.y * c.y + c.z * c.z + c.w * c.w;
    #pragma unroll
    for (int off = 16; off > 0; off >>= 1) {
        sum += __shfl_xor_sync(0xffffffffu, sum, off);
        ss  += __shfl_xor_sync(0xffffffffu, ss, off);
    }
    float mean = sum * (1.0f / 256.0f);
    float var = ss * (1.0f / 256.0f) - mean * mean;
    float rstd = rsqrtf(var + 1e-5f);
    const float4* gr = (const float4*)g;
    const float4* br = (const float4*)b;
    float4 g0 = gr[lane * 2], g1 = gr[lane * 2 + 1];
    float4 b0 = br[lane * 2], b1 = br[lane * 2 + 1];
    float o[8];
    o[0] = (a.x - mean) * rstd * g0.x + b0.x;
    o[1] = (a.y - mean) * rstd * g0.y + b0.y;
    o[2] = (a.z - mean) * rstd * g0.z + b0.z;
    o[3] = (a.w - mean) * rstd * g0.w + b0.w;
    o[4] = (c.x - mean) * rstd * g1.x + b1.x;
    o[5] = (c.y - mean) * rstd * g1.y + b1.y;
    o[6] = (c.z - mean) * rstd * g1.z + b1.z;
    o[7] = (c.w - mean) * rstd * g1.w + b1.w;
    __half2 h0 = __floats2half2_rn(o[0], o[1]);
    __half2 h1 = __floats2half2_rn(o[2], o[3]);
    __half2 h2 = __floats2half2_rn(o[4], o[5]);
    __half2 h3 = __floats2half2_rn(o[6], o[7]);
    uint4 u;
    u.x = *(unsigned*)&h0; u.y = *(unsigned*)&h1;
    u.z = *(unsigned*)&h2; u.w = *(unsigned*)&h3;
    ((uint4*)(y + (size_t)warp * DD))[lane] = u;
}

// ---------------- fp32 GEMM (K=12 geo1), half output ----------------
__global__ void k_gemm12(const float* __restrict__ A, const float* __restrict__ B,
                         const float* __restrict__ bias, __half* __restrict__ C,
                         int M, int N, int K) {
    __shared__ float As[64][17];
    __shared__ float Bs[16][64];
    int tid = threadIdx.x;
    int tx = tid & 15, ty = tid >> 4;
    int m0 = blockIdx.y * 64, n0 = blockIdx.x * 64;
    float acc[4][4] = {};
    int KT = (K + 15) >> 4;
    for (int kt = 0; kt < KT; kt++) {
        int k0 = kt << 4;
        #pragma unroll
        for (int i = 0; i < 4; i++) {
            int lin = tid + i * 256;
            int ar = lin >> 4, ac = lin & 15;
            int gk = k0 + ac;
            As[ar][ac] = (gk < K) ? A[(size_t)(m0 + ar) * K + gk] : 0.f;
        }
        #pragma unroll
        for (int i = 0; i < 4; i++) {
            int lin = tid + i * 256;
            int br = lin >> 6, bc = lin & 63;
            int gk = k0 + br;
            Bs[br][bc] = (gk < K) ? B[(size_t)gk * N + n0 + bc] : 0.f;
        }
        __syncthreads();
        #pragma unroll
        for (int kk = 0; kk < 16; kk++) {
            float av[4];
            #pragma unroll
            for (int i = 0; i < 4; i++) av[i] = As[ty * 4 + i][kk];
            float4 bv = *(const float4*)&Bs[kk][tx * 4];
            float bvv[4] = {bv.x, bv.y, bv.z, bv.w};
            #pragma unroll
            for (int i = 0; i < 4; i++)
                #pragma unroll
                for (int j = 0; j < 4; j++)
                    acc[i][j] = fmaf(av[i], bvv[j], acc[i][j]);
        }
        __syncthreads();
    }
    #pragma unroll
    for (int i = 0; i < 4; i++) {
        int row = m0 + ty * 4 + i;
        #pragma unroll
        for (int j = 0; j < 4; j++) {
            int col = n0 + tx * 4 + j;
            float v = acc[i][j] + bias[col];
            v = gelu_f(v);
            C[(size_t)row * N + col] = __float2half_rn(v);
        }
    }
}

// ---------------- FP16 tensor-core GEMM, BK=32, cp.async 2-stage ----------------
template <int BM, bool BIAS, bool GELU, bool RES, bool HOUT>
__device__ __forceinline__ void hgemm_body(
    const __half* __restrict__ A, const __half* __restrict__ B,
    const float* __restrict__ bias, const float* __restrict__ res,
    void* __restrict__ Cv, int N, int K, int m0, int n0) {
    constexpr int SA = 40, SB = 136;   // halves per row (pad)
    constexpr int MI = BM / 32;
    extern __shared__ __half smem[];
    __half (*As)[BM][SA] = reinterpret_cast<__half(*)[BM][SA]>(smem);
    __half (*Bs)[32][SB] = reinterpret_cast<__half(*)[32][SB]>(smem + 2 * BM * SA);

    int tid = threadIdx.x;
    int warp = tid >> 5, lane = tid & 31;
    int wm = warp & 1, wn = warp >> 1;
    int g = lane >> 2, t = lane & 3;

    float acc[MI][4][4];
    #pragma unroll
    for (int i = 0; i < MI; i++)
        #pragma unroll
        for (int j = 0; j < 4; j++)
            #pragma unroll
            for (int c = 0; c < 4; c++) acc[i][j][c] = 0.f;

    int KT = K >> 5;
    #pragma unroll
    for (int i = 0; i < BM / 64; i++) {
        int lin = tid + i * 256;
        int row = lin >> 2, col = (lin & 3) * 8;
        cpa16(&As[0][row][col], &A[(size_t)(m0 + row) * K + col]);
    }
    #pragma unroll
    for (int i = 0; i < 2; i++) {
        int lin = tid + i * 256;
        int row = lin >> 4, col = (lin & 15) * 8;
        cpa16(&Bs[0][row][col], &B[(size_t)row * N + n0 + col]);
    }
    asm volatile("cp.async.commit_group;");

    int buf = 0;
    for (int kt = 0; kt < KT; kt++) {
        if (kt + 1 < KT) {
            int k0 = (kt + 1) << 5;
            #pragma unroll
            for (int i = 0; i < BM / 64; i++) {
                int lin = tid + i * 256;
                int row = lin >> 2, col = (lin & 3) * 8;
                cpa16(&As[buf ^ 1][row][col], &A[(size_t)(m0 + row) * K + k0 + col]);
            }
            #pragma unroll
            for (int i = 0; i < 2; i++) {
                int lin = tid + i * 256;
                int row = lin >> 4, col = (lin & 15) * 8;
                cpa16(&Bs[buf ^ 1][row][col], &B[(size_t)(k0 + row) * N + n0 + col]);
            }
            asm volatile("cp.async.commit_group;");
            asm volatile("cp.async.wait_group 1;");
        } else {
            asm volatile("cp.async.wait_group 0;");
        }
        __syncthreads();
        #pragma unroll
        for (int ks = 0; ks < 32; ks += 16) {
            unsigned a[MI][4], b[4][2];
            #pragma unroll
            for (int mi = 0; mi < MI; mi++) {
                int row = wm * (BM / 2) + mi * 16 + (lane & 7) + ((lane >> 3) & 1) * 8;
                int col = ks + (lane >> 4) * 8;
                unsigned addr = smem_u32(&As[buf][row][col]);
                asm volatile(
                    "ldmatrix.sync.aligned.m8n8.x4.shared.b16 {%0,%1,%2,%3}, [%4];"
                    : "=r"(a[mi][0]), "=r"(a[mi][1]), "=r"(a[mi][2]), "=r"(a[mi][3])
                    : "r"(addr));
            }
            #pragma unroll
            for (int p = 0; p < 2; p++) {
                int krow = ks + (lane & 7) + ((lane >> 3) & 1) * 8;
                int ncol = wn * 32 + p * 16 + (lane >> 4) * 8;
                unsigned addr = smem_u32(&Bs[buf][krow][ncol]);
                unsigned r0, r1, r2, r3;
                asm volatile(
                    "ldmatrix.sync.aligned.m8n8.x4.trans.shared.b16 {%0,%1,%2,%3}, [%4];"
                    : "=r"(r0), "=r"(r1), "=r"(r2), "=r"(r3) : "r"(addr));
                b[2 * p][0] = r0; b[2 * p][1] = r1;
                b[2 * p + 1][0] = r2; b[2 * p + 1][1] = r3;
            }
            #pragma unroll
            for (int mi = 0; mi < MI; mi++)
                #pragma unroll
                for (int ni = 0; ni < 4; ni++) {
                    asm volatile(
                        "mma.sync.aligned.m16n8k16.row.col.f32.f16.f16.f32 "
                        "{%0,%1,%2,%3}, {%4,%5,%6,%7}, {%8,%9}, {%0,%1,%2,%3};"
                        : "+f"(acc[mi][ni][0]), "+f"(acc[mi][ni][1]),
                          "+f"(acc[mi][ni][2]), "+f"(acc[mi][ni][3])
                        : "r"(a[mi][0]), "r"(a[mi][1]), "r"(a[mi][2]), "r"(a[mi][3]),
                          "r"(b[ni][0]), "r"(b[ni][1]));
                }
        }
        buf ^= 1;
        __syncthreads();
    }
    #pragma unroll
    for (int mi = 0; mi < MI; mi++) {
        int mrow = m0 + wm * (BM / 2) + mi * 16 + g;
        #pragma unroll
        for (int ni = 0; ni < 4; ni++) {
            int ncol = n0 + wn * 32 + ni * 8 + 2 * t;
            #pragma unroll
            for (int half = 0; half < 2; half++) {
                int row = mrow + half * 8;
                float v0 = acc[mi][ni][half * 2 + 0];
                float v1 = acc[mi][ni][half * 2 + 1];
                if (BIAS) { v0 += bias[ncol]; v1 += bias[ncol + 1]; }
                if (GELU) { v0 = gelu_f(v0); v1 = gelu_f(v1); }
                if (RES) {
                    const float2 r = *(const float2*)&res[(size_t)row * N + ncol];
                    v0 += r.x; v1 += r.y;
                }
                if (HOUT) {
                    __half2 h = __floats2half2_rn(v0, v1);
                    *(__half2*)&((__half*)Cv)[(size_t)row * N + ncol] = h;
                } else {
                    float2 o; o.x = v0; o.y = v1;
                    *(float2*)&((float*)Cv)[(size_t)row * N + ncol] = o;
                }
            }
        }
    }
}

template <int BM, bool BIAS, bool GELU, bool RES, bool HOUT>
__global__ __launch_bounds__(256, 2)
void k_hgemm(const __half* __restrict__ A, const __half* __restrict__ B,
             const float* __restrict__ bias, const float* __restrict__ res,
             void* __restrict__ C, int N, int K) {
    hgemm_body<BM, BIAS, GELU, RES, HOUT>(A, B, bias, res, C, N, K,
                                          blockIdx.y * BM, blockIdx.x * 128);
}

// ---------------- KV projection with in-kernel fp32->fp16 A convert ----------
// A fp32 [NS, K]; blockIdx.z selects (Wk->Kf) or (Wv->Vf). BM=128.
// Smem: A32 double-buffered fp32 stage, A16 single-buffered fp16 tile
// (the post-wait barrier orders prior mma reads before the next convert),
// Bs double-buffered fp16.
__global__ __launch_bounds__(256, 2)
void k_hgemm_kvf(const float* __restrict__ A,
                 const __half* __restrict__ B0, const __half* __restrict__ B1,
                 __half* __restrict__ C0, __half* __restrict__ C1, int N, int K) {
    constexpr int BM = 128, SA32 = 36, SA = 40, SB = 136, MI = 4;
    extern __shared__ __align__(16) char smraw[];
    float  (*A32)[BM][SA32] = reinterpret_cast<float(*)[BM][SA32]>(smraw);
    __half (*A16)[SA]       = reinterpret_cast<__half(*)[SA]>(smraw + 2 * BM * SA32 * 4);
    __half (*Bs)[32][SB]    = reinterpret_cast<__half(*)[32][SB]>(
                                  smraw + 2 * BM * SA32 * 4 + BM * SA * 2);
    const __half* B = blockIdx.z ? B1 : B0;
    __half* C = blockIdx.z ? C1 : C0;
    int m0 = blockIdx.y * BM, n0 = blockIdx.x * 128;

    int tid = threadIdx.x;
    int warp = tid >> 5, lane = tid & 31;
    int wm = warp & 1, wn = warp >> 1;
    int g = lane >> 2, t = lane & 3;

    float acc[MI][4][4];
    #pragma unroll
    for (int i = 0; i < MI; i++)
        #pragma unroll
        for (int j = 0; j < 4; j++)
            #pragma unroll
            for (int c = 0; c < 4; c++) acc[i][j][c] = 0.f;

    int KT = K >> 5;
    // stage 0: A32 (128x32 fp32 = 1024 16B chunks), B (32x128 half = 512 chunks)
    #pragma unroll
    for (int i = 0; i < 4; i++) {
        int lin = tid + i * 256;
        int row = lin >> 3, colq = (lin & 7) * 4;
        cpa16(&A32[0][row][colq], &A[(size_t)(m0 + row) * K + colq]);
    }
    #pragma unroll
    for (int i = 0; i < 2; i++) {
        int lin = tid + i * 256;
        int row = lin >> 4, col = (lin & 15) * 8;
        cpa16(&Bs[0][row][col], &B[(size_t)row * N + n0 + col]);
    }
    asm volatile("cp.async.commit_group;");

    int buf = 0;
    for (int kt = 0; kt < KT; kt++) {
        if (kt + 1 < KT) {
            int k0 = (kt + 1) << 5;
            #pragma unroll
            for (int i = 0; i < 4; i++) {
                int lin = tid + i * 256;
                int row = lin >> 3, colq = (lin & 7) * 4;
                cpa16(&A32[buf ^ 1][row][colq], &A[(size_t)(m0 + row) * K + k0 + colq]);
            }
            #pragma unroll
            for (int i = 0; i < 2; i++) {
                int lin = tid + i * 256;
                int row = lin >> 4, col = (lin & 15) * 8;
                cpa16(&Bs[buf ^ 1][row][col], &B[(size_t)(k0 + row) * N + n0 + col]);
            }
            asm volatile("cp.async.commit_group;");
            asm volatile("cp.async.wait_group 1;");
        } else {
            asm volatile("cp.async.wait_group 0;");
        }
        __syncthreads();   // A32[buf]/Bs[buf] ready; ALL warps done with prior A16 reads
        // convert: thread handles row = tid>>1, 16 cols at (tid&1)*16
        {
            int row = tid >> 1, c0 = (tid & 1) * 16;
            const float* src = &A32[buf][row][c0];
            float4 f0 = *(const float4*)(src + 0);
            float4 f1 = *(const float4*)(src + 4);
            float4 f2 = *(const float4*)(src + 8);
            float4 f3 = *(const float4*)(src + 12);
            __half2 h0 = __floats2half2_rn(f0.x, f0.y);
            __half2 h1 = __floats2half2_rn(f0.z, f0.w);
            __half2 h2 = __floats2half2_rn(f1.x, f1.y);
            __half2 h3 = __floats2half2_rn(f1.z, f1.w);
            __half2 h4 = __floats2half2_rn(f2.x, f2.y);
            __half2 h5 = __floats2half2_rn(f2.z, f2.w);
            __half2 h6 = __floats2half2_rn(f3.x, f3.y);
            __half2 h7 = __floats2half2_rn(f3.z, f3.w);
            uint4 u0, u1;
            u0.x = *(unsigned*)&h0; u0.y = *(unsigned*)&h1;
            u0.z = *(unsigned*)&h2; u0.w = *(unsigned*)&h3;
            u1.x = *(unsigned*)&h4; u1.y = *(unsigned*)&h5;
            u1.z = *(unsigned*)&h6; u1.w = *(unsigned*)&h7;
            *(uint4*)&A16[row][c0 + 0] = u0;
            *(uint4*)&A16[row][c0 + 8] = u1;
        }
        __syncthreads();   // A16 ready
        #pragma unroll
        for (int ks = 0; ks < 32; ks += 16) {
            unsigned a[MI][4], b[4][2];
            #pragma unroll
            for (int mi = 0; mi < MI; mi++) {
                int row = wm * (BM / 2) + mi * 16 + (lane & 7) + ((lane >> 3) & 1) * 8;
                int col = ks + (lane >> 4) * 8;
                unsigned addr = smem_u32(&A16[row][col]);
                asm volatile(
                    "ldmatrix.sync.aligned.m8n8.x4.shared.b16 {%0,%1,%2,%3}, [%4];"
                    : "=r"(a[mi][0]), "=r"(a[mi][1]), "=r"(a[mi][2]), "=r"(a[mi][3])
                    : "r"(addr));
            }
            #pragma unroll
            for (int p = 0; p < 2; p++) {
                int krow = ks + (lane & 7) + ((lane >> 3) & 1) * 8;
                int ncol = wn * 32 + p * 16 + (lane >> 4) * 8;
                unsigned addr = smem_u32(&Bs[buf][krow][ncol]);
                unsigned r0, r1, r2, r3;
                asm volatile(
                    "ldmatrix.sync.aligned.m8n8.x4.trans.shared.b16 {%0,%1,%2,%3}, [%4];"
                    : "=r"(r0), "=r"(r1), "=r"(r2), "=r"(r3) : "r"(addr));
                b[2 * p][0] = r0; b[2 * p][1] = r1;
                b[2 * p + 1][0] = r2; b[2 * p + 1][1] = r3;
            }
            #pragma unroll
            for (int mi = 0; mi < MI; mi++)
                #pragma unroll
                for (int ni = 0; ni < 4; ni++) {
                    asm volatile(
                        "mma.sync.aligned.m16n8k16.row.col.f32.f16.f16.f32 "
                        "{%0,%1,%2,%3}, {%4,%5,%6,%7}, {%8,%9}, {%0,%1,%2,%3};"
                        : "+f"(acc[mi][ni][0]), "+f"(acc[mi][ni][1]),
                          "+f"(acc[mi][ni][2]), "+f"(acc[mi][ni][3])
                        : "r"(a[mi][0]), "r"(a[mi][1]), "r"(a[mi][2]), "r"(a[mi][3]),
                          "r"(b[ni][0]), "r"(b[ni][1]));
                }
        }
        buf ^= 1;
    }
    #pragma unroll
    for (int mi = 0; mi < MI; mi++) {
        int mrow = m0 + wm * (BM / 2) + mi * 16 + g;
        #pragma unroll
        for (int ni = 0; ni < 4; ni++) {
            int ncol = n0 + wn * 32 + ni * 8 + 2 * t;
            #pragma unroll
            for (int half = 0; half < 2; half++) {
                int row = mrow + half * 8;
                __half2 h = __floats2half2_rn(acc[mi][ni][half * 2 + 0],
                                              acc[mi][ni][half * 2 + 1]);
                *(__half2*)&C[(size_t)row * N + ncol] = h;
            }
        }
    }
}

// ---------------- fused edge attention: warp per query, online softmax ----------
__global__ void k_attn(const int* __restrict__ sidx,
                       const float* __restrict__ log_tau) {
    int warp = (blockIdx.x * blockDim.x + threadIdx.x) >> 5;
    int lane = threadIdx.x & 31;
    if (warp >= NQ) return;
    int q = warp;
    int st = g_rowptr[q], en = g_rowptr[q + 1];
    float scale = 0.17677669529663689f * expf(-log_tau[0]);

    float qv[8];
    unpack8(((const uint4*)(g_Qf_h + (size_t)q * DD))[lane], qv);

    float m = 0.0f;   // reference: smax = max(0, segment max)
    float ssum = 0.0f;
    float a[8] = {0.f, 0.f, 0.f, 0.f, 0.f, 0.f, 0.f, 0.f};

    int e = st;
    for (; e + 1 < en; e += 2) {
        int sA = sidx[e], sB = sidx[e + 1];
        float kA[8], kB[8], vA[8], vB[8];
        unpack8(((const uint4*)(g_Kf_h + (size_t)sA * DD))[lane], kA);
        unpack8(((const uint4*)(g_Kf_h + (size_t)sB * DD))[lane], kB);
        unpack8(((const uint4*)(g_Vf_h + (size_t)sA * DD))[lane], vA);
        unpack8(((const uint4*)(g_Vf_h + (size_t)sB * DD))[lane], vB);
        float dA = 0.f, dB = 0.f;
        #pragma unroll
        for (int j = 0; j < 8; j++) { dA += qv[j] * kA[j]; dB += qv[j] * kB[j]; }
        dA += __shfl_xor_sync(0xffffffffu, dA, 1);
        dA += __shfl_xor_sync(0xffffffffu, dA, 2);
        dB += __shfl_xor_sync(0xffffffffu, dB, 1);
        dB += __shfl_xor_sync(0xffffffffu, dB, 2);
        dA *= scale; dB *= scale;
        float mn = fmaxf(m, fmaxf(dA, dB));
        float c = __expf(m - mn);
        float rA = __expf(dA - mn);
        float rB = __expf(dB - mn);
        #pragma unroll
        for (int j = 0; j < 8; j++) a[j] = a[j] * c + rA * vA[j] + rB * vB[j];
        ssum = ssum * c + rA + rB;
        m = mn;
    }
    if (e < en) {
        int s = sidx[e];
        float kv[8], vv[8];
        unpack8(((const uint4*)(g_Kf_h + (size_t)s * DD))[lane], kv);
        unpack8(((const uint4*)(g_Vf_h + (size_t)s * DD))[lane], vv);
        float d = 0.f;
        #pragma unroll
        for (int j = 0; j < 8; j++) d += qv[j] * kv[j];
        d += __shfl_xor_sync(0xffffffffu, d, 1);
        d += __shfl_xor_sync(0xffffffffu, d, 2);
        d *= scale;
        float mn = fmaxf(m, d);
        float c = __expf(m - mn);
        float r = __expf(d - mn);
        #pragma unroll
        for (int j = 0; j < 8; j++) a[j] = a[j] * c + r * vv[j];
        ssum = ssum * c + r;
        m = mn;
    }

    float inv = 1.0f / fmaxf(ssum, 1e-8f);
    float gsc = ssum * inv;
    float gv[8];
    unpack8(((const uint4*)(g_Gf_h + (size_t)q * DD))[lane], gv);
    float o[8];
    #pragma unroll
    for (int j = 0; j < 8; j++) o[j] = a[j] * inv + gv[j] * gsc;
    __half2 h0 = __floats2half2_rn(o[0], o[1]);
    __half2 h1 = __floats2half2_rn(o[2], o[3]);
    __half2 h2 = __floats2half2_rn(o[4], o[5]);
    __half2 h3 = __floats2half2_rn(o[6], o[7]);
    uint4 u;
    u.x = *(unsigned*)&h0; u.y = *(unsigned*)&h1;
    u.z = *(unsigned*)&h2; u.w = *(unsigned*)&h3;
    ((uint4*)(g_out_h + (size_t)q * DD))[lane] = u;
}

// ---------------- host ----------------
template <typename T>
static T* symp(const void* sym) {
    void* p = nullptr;
    cudaGetSymbolAddress(&p, sym);
    return (T*)p;
}

#define SMEM_H(BM) ((2 * (BM) * 40 + 2 * 32 * 136) * (int)sizeof(__half))
#define SMEM_KVF (2 * 128 * 36 * 4 + 128 * 40 * 2 + 2 * 32 * 136 * 2)

struct Ctx {
    cudaStream_t s1, s2;
    cudaEvent_t evRoot, evKV, evG;
    Ctx() {
        cudaStreamCreateWithFlags(&s1, cudaStreamNonBlocking);
        cudaStreamCreateWithFlags(&s2, cudaStreamNonBlocking);
        cudaEventCreateWithFlags(&evRoot, cudaEventDisableTiming);
        cudaEventCreateWithFlags(&evKV, cudaEventDisableTiming);
        cudaEventCreateWithFlags(&evG, cudaEventDisableTiming);
        cudaFuncSetAttribute((const void*)k_hgemm_kvf,
            cudaFuncAttributeMaxDynamicSharedMemorySize, SMEM_KVF);
        cudaFuncSetAttribute((const void*)k_hgemm<64, false, false, false, true>,
            cudaFuncAttributeMaxDynamicSharedMemorySize, SMEM_H(64));
        cudaFuncSetAttribute((const void*)k_hgemm<64, true, true, false, true>,
            cudaFuncAttributeMaxDynamicSharedMemorySize, SMEM_H(64));
        cudaFuncSetAttribute((const void*)k_hgemm<64, true, false, true, false>,
            cudaFuncAttributeMaxDynamicSharedMemorySize, SMEM_H(64));
    }
};

extern "C" void kernel_launch(void* const* d_in, const int* in_sizes, int n_in,
                              void* d_out, int out_size) {
    const float* query_tokens  = (const float*)d_in[0];
    const float* query_pos     = (const float*)d_in[1];
    const float* support_feats = (const float*)d_in[2];
    const float* support_pos   = (const float*)d_in[3];
    const float* Wq   = (const float*)d_in[4];
    const float* Wk   = (const float*)d_in[5];
    const float* Wv   = (const float*)d_in[6];
    const float* Wg   = (const float*)d_in[7];
    const float* Wo   = (const float*)d_in[8];
    const float* bo   = (const float*)d_in[9];
    const float* log_tau = (const float*)d_in[10];
    const float* ln1_g = (const float*)d_in[11];
    const float* ln1_b = (const float*)d_in[12];
    const float* ln2_g = (const float*)d_in[13];
    const float* ln2_b = (const float*)d_in[14];
    const float* Wf1  = (const float*)d_in[15];
    const float* bf1  = (const float*)d_in[16];
    const float* Wf2  = (const float*)d_in[17];
    const float* bf2  = (const float*)d_in[18];
    const float* Gw1  = (const float*)d_in[19];
    const float* Gb1  = (const float*)d_in[20];
    const float* Gw2  = (const float*)d_in[21];
    const float* Gb2  = (const float*)d_in[22];
    const int* q_idx  = (const int*)d_in[23];
    const int* s_idx  = (const int*)d_in[24];
    float* out = (float*)d_out;

    float*  p_raw   = symp<float>(g_raw);
    float*  p_x     = symp<float>(g_x);
    __half* p_qt    = symp<__half>(g_qt_h);
    __half* p_geoh  = symp<__half>(g_geoh_h);
    __half* p_geo   = symp<__half>(g_geo_h);
    __half* p_Qf    = symp<__half>(g_Qf_h);
    __half* p_Kf    = symp<__half>(g_Kf_h);
    __half* p_Vf    = symp<__half>(g_Vf_h);
    __half* p_Gf    = symp<__half>(g_Gf_h);
    __half* p_outh  = symp<__half>(g_out_h);
    __half* p_h1    = symp<__half>(g_h1_h);
    __half* p_Wq    = symp<__half>(g_Wq_h);
    __half* p_Wk    = symp<__half>(g_Wk_h);
    __half* p_Wv    = symp<__half>(g_Wv_h);
    __half* p_Wg    = symp<__half>(g_Wg_h);
    __half* p_Wo    = symp<__half>(g_Wo_h);
    __half* p_Wf1   = symp<__half>(g_Wf1_h);
    __half* p_Wf2   = symp<__half>(g_Wf2_h);
    __half* p_Gw2   = symp<__half>(g_Gw2_h);

    static Ctx ctx;

    // fork
    cudaEventRecord(ctx.evRoot, 0);
    cudaStreamWaitEvent(ctx.s1, ctx.evRoot, 0);
    cudaStreamWaitEvent(ctx.s2, ctx.evRoot, 0);

    // s1: weight converts + merged K/V projection (A converted in-kernel)
    k_cvt<<<(DD * DD / 4 + 255) / 256, 256, 0, ctx.s1>>>(Wk, p_Wk, DD * DD / 4);
    k_cvt<<<(DD * DD / 4 + 255) / 256, 256, 0, ctx.s1>>>(Wv, p_Wv, DD * DD / 4);
    k_hgemm_kvf<<<dim3(DD / 128, NS / 128, 2), 256, SMEM_KVF, ctx.s1>>>(
        support_feats, p_Wk, p_Wv, p_Kf, p_Vf, DD, DD);
    cudaEventRecord(ctx.evKV, ctx.s1);

    // s2: geo chain
    k_rowptr<<<(NQ + 1 + 255) / 256, 256, 0, ctx.s2>>>(q_idx);
    k_geostats<<<NQ / 8, 256, 0, ctx.s2>>>(query_pos, support_pos, s_idx);
    k_cvt<<<(NGEO * NGEO / 4 + 255) / 256, 256, 0, ctx.s2>>>(Gw2, p_Gw2, NGEO * NGEO / 4);
    k_cvt<<<(NGEO * DD / 4 + 255) / 256, 256, 0, ctx.s2>>>(Wg, p_Wg, NGEO * DD / 4);
    k_gemm12<<<dim3(NGEO / 64, NQ / 64), 256, 0, ctx.s2>>>(
        p_raw, Gw1, Gb1, p_geoh, NQ, NGEO, 12);
    k_hgemm<64, true, true, false, true><<<dim3(NGEO / 128, NQ / 64), 256, SMEM_H(64), ctx.s2>>>(
        p_geoh, p_Gw2, Gb2, nullptr, p_geo, NGEO, NGEO);
    k_hgemm<64, false, false, false, true><<<dim3(DD / 128, NQ / 64), 256, SMEM_H(64), ctx.s2>>>(
        p_geo, p_Wg, nullptr, nullptr, p_Gf, DD, NGEO);
    cudaEventRecord(ctx.evG, ctx.s2);

    // s0 (default): query chain + remaining weight converts
    k_cvt<<<(DD * DD / 4 + 255) / 256, 256>>>(Wq, p_Wq, DD * DD / 4);
    k_ln<<<NQ / 8, 256>>>(query_tokens, ln1_g, ln1_b, p_qt);
    k_hgemm<64, false, false, false, true><<<dim3(DD / 128, NQ / 64), 256, SMEM_H(64)>>>(
        p_qt, p_Wq, nullptr, nullptr, p_Qf, DD, DD);
    k_cvt<<<(DD * DD / 4 + 255) / 256, 256>>>(Wo, p_Wo, DD * DD / 4);
    k_cvt<<<(DD * NFFN / 4 + 255) / 256, 256>>>(Wf1, p_Wf1, DD * NFFN / 4);
    k_cvt<<<(NFFN * DD / 4 + 255) / 256, 256>>>(Wf2, p_Wf2, NFFN * DD / 4);

    // join, fused edge attention
    cudaStreamWaitEvent(0, ctx.evKV, 0);
    cudaStreamWaitEvent(0, ctx.evG, 0);
    k_attn<<<NQ / 8, 256>>>(s_idx, log_tau);

    // tail
    k_hgemm<64, true, false, true, false><<<dim3(DD / 128, NQ / 64), 256, SMEM_H(64)>>>(
        p_outh, p_Wo, bo, query_tokens, p_x, DD, DD);
    k_ln<<<NQ / 8, 256>>>(p_x, ln2_g, ln2_b, p_qt);
    k_hgemm<64, true, true, false, true><<<dim3(NFFN / 128, NQ / 64), 256, SMEM_H(64)>>>(
        p_qt, p_Wf1, bf1, nullptr, p_h1, NFFN, DD);
    k_hgemm<64, true, false, true, false><<<dim3(DD / 128, NQ / 64), 256, SMEM_H(64)>>>(
        p_h1, p_Wf2, bf2, p_x, out, DD, NFFN);
}

// round 9
// speedup vs baseline: 4.8299x; 1.0007x over previous
#include <cuda_runtime.h>
#include <cuda_fp16.h>
#include <math.h>

#define NQ 8192
#define NS 32768
#define NE 131072
#define DD 256
#define NH 8
#define HDIM 32
#define NGEO 128
#define NFFN 512

// ---------------- scratch (device globals; no allocation) ----------------
__device__ float  g_raw[NQ * 12];
__device__ float  g_x[NQ * DD];
__device__ int    g_rowptr[NQ + 1];

// half activations / weights
__device__ __half g_qt_h[NQ * DD];
__device__ __half g_geoh_h[NQ * NGEO];
__device__ __half g_geo_h[NQ * NGEO];
__device__ __half g_Qf_h[NQ * DD];
__device__ __half g_Kf_h[NS * DD];
__device__ __half g_Vf_h[NS * DD];
__device__ __half g_Gf_h[NQ * DD];
__device__ __half g_out_h[NQ * DD];
__device__ __half g_h1_h[NQ * NFFN];
__device__ __half g_Wq_h[DD * DD];
__device__ __half g_Wk_h[DD * DD];
__device__ __half g_Wv_h[DD * DD];
__device__ __half g_Wg_h[NGEO * DD];
__device__ __half g_Wo_h[DD * DD];
__device__ __half g_Wf1_h[DD * NFFN];
__device__ __half g_Wf2_h[NFFN * DD];
__device__ __half g_Gw2_h[NGEO * NGEO];

__device__ __forceinline__ float gelu_f(float x) {
    return 0.5f * x * (1.0f + erff(x * 0.7071067811865475f));
}

__device__ __forceinline__ void cpa16(void* dst, const void* src) {
    unsigned d = (unsigned)__cvta_generic_to_shared(dst);
    asm volatile("cp.async.cg.shared.global [%0], [%1], 16;" :: "r"(d), "l"(src));
}
__device__ __forceinline__ unsigned smem_u32(const void* p) {
    return (unsigned)__cvta_generic_to_shared(p);
}
__device__ __forceinline__ void unpack8(uint4 u, float* f) {
    float2 a = __half22float2(*(const __half2*)&u.x);
    float2 b = __half22float2(*(const __half2*)&u.y);
    float2 c = __half22float2(*(const __half2*)&u.z);
    float2 d = __half22float2(*(const __half2*)&u.w);
    f[0] = a.x; f[1] = a.y; f[2] = b.x; f[3] = b.y;
    f[4] = c.x; f[5] = c.y; f[6] = d.x; f[7] = d.y;
}

// ---------------- fused fp32 -> fp16 weight converts ----------------
struct CvtJobs {
    const float* src[8];
    __half* dst[8];
    int n4[8];
};
__global__ void k_cvt_all(CvtJobs j) {
    int w = blockIdx.y;
    int i = blockIdx.x * blockDim.x + threadIdx.x;
    if (i >= j.n4[w]) return;
    float4 v = ((const float4*)j.src[w])[i];
    __half2 h0 = __floats2half2_rn(v.x, v.y);
    __half2 h1 = __floats2half2_rn(v.z, v.w);
    uint2 u;
    u.x = *(unsigned*)&h0;
    u.y = *(unsigned*)&h1;
    ((uint2*)j.dst[w])[i] = u;
}

// ---------------- row_ptr via boundary scan (q_idx sorted) ----------------
__global__ void k_bounds(const int* __restrict__ qidx) {
    int e = blockIdx.x * blockDim.x + threadIdx.x;
    if (e >= NE) return;
    int v = qidx[e];
    int prev = (e == 0) ? -1 : qidx[e - 1];
    for (int q = prev + 1; q <= v; q++) g_rowptr[q] = e;
    if (e == NE - 1) {
        for (int q = v + 1; q <= NQ; q++) g_rowptr[q] = NE;
    }
}

// ---------------- geo stats: warp per query ----------------
__global__ void k_geostats(const float* __restrict__ qpos,
                           const float* __restrict__ spos,
                           const int* __restrict__ sidx) {
    int warp = (blockIdx.x * blockDim.x + threadIdx.x) >> 5;
    int lane = threadIdx.x & 31;
    if (warp >= NQ) return;
    int q = warp;
    int st = g_rowptr[q], en = g_rowptr[q + 1];
    float qp0 = qpos[q * 3 + 0], qp1 = qpos[q * 3 + 1], qp2 = qpos[q * 3 + 2];
    float s0 = 0.f, s1 = 0.f, s2 = 0.f;
    float ss0 = 0.f, ss1 = 0.f, ss2 = 0.f;
    float mn0 = 1e30f, mn1 = 1e30f, mn2 = 1e30f;
    float mx0 = -1e30f, mx1 = -1e30f, mx2 = -1e30f;
    for (int e = st + lane; e < en; e += 32) {
        int s = sidx[e];
        float r0 = spos[s * 3 + 0] - qp0;
        float r1 = spos[s * 3 + 1] - qp1;
        float r2 = spos[s * 3 + 2] - qp2;
        s0 += r0; s1 += r1; s2 += r2;
        ss0 += r0 * r0; ss1 += r1 * r1; ss2 += r2 * r2;
        mn0 = fminf(mn0, r0); mn1 = fminf(mn1, r1); mn2 = fminf(mn2, r2);
        mx0 = fmaxf(mx0, r0); mx1 = fmaxf(mx1, r1); mx2 = fmaxf(mx2, r2);
    }
    #pragma unroll
    for (int off = 16; off > 0; off >>= 1) {
        s0 += __shfl_xor_sync(0xffffffffu, s0, off);
        s1 += __shfl_xor_sync(0xffffffffu, s1, off);
        s2 += __shfl_xor_sync(0xffffffffu, s2, off);
        ss0 += __shfl_xor_sync(0xffffffffu, ss0, off);
        ss1 += __shfl_xor_sync(0xffffffffu, ss1, off);
        ss2 += __shfl_xor_sync(0xffffffffu, ss2, off);
        mn0 = fminf(mn0, __shfl_xor_sync(0xffffffffu, mn0, off));
        mn1 = fminf(mn1, __shfl_xor_sync(0xffffffffu, mn1, off));
        mn2 = fminf(mn2, __shfl_xor_sync(0xffffffffu, mn2, off));
        mx0 = fmaxf(mx0, __shfl_xor_sync(0xffffffffu, mx0, off));
        mx1 = fmaxf(mx1, __shfl_xor_sync(0xffffffffu, mx1, off));
        mx2 = fmaxf(mx2, __shfl_xor_sync(0xffffffffu, mx2, off));
    }
    if (lane == 0) {
        float cnt = fmaxf((float)(en - st), 1.0f);
        float m0 = s0 / cnt, m1 = s1 / cnt, m2 = s2 / cnt;
        float v0 = fmaxf(ss0 / cnt - m0 * m0, 0.f);
        float v1 = fmaxf(ss1 / cnt - m1 * m1, 0.f);
        float v2 = fmaxf(ss2 / cnt - m2 * m2, 0.f);
        float* r = g_raw + q * 12;
        r[0] = m0; r[1] = m1; r[2] = m2;
        r[3] = sqrtf(v0); r[4] = sqrtf(v1); r[5] = sqrtf(v2);
        r[6] = fminf(fmaxf(mn0, -100.f), 100.f);
        r[7] = fminf(fmaxf(mn1, -100.f), 100.f);
        r[8] = fminf(fmaxf(mn2, -100.f), 100.f);
        r[9]  = fminf(fmaxf(mx0, -100.f), 100.f);
        r[10] = fminf(fmaxf(mx1, -100.f), 100.f);
        r[11] = fminf(fmaxf(mx2, -100.f), 100.f);
    }
}

// ---------------- LayerNorm: warp per row, fp32 in, fp16 out ----------------
__global__ void k_ln(const float* __restrict__ x, const float* __restrict__ g,
                     const float* __restrict__ b, __half* __restrict__ y) {
    int warp = (blockIdx.x * blockDim.x + threadIdx.x) >> 5;
    int lane = threadIdx.x & 31;
    if (warp >= NQ) return;
    const float4* xr = (const float4*)(x + warp * DD);
    float4 a = xr[lane * 2], c = xr[lane * 2 + 1];
    float sum = a.x + a.y + a.z + a.w + c.x + c.y + c.z + c.w;
    float ss = a.x * a.x + a.y * a.y + a.z * a.z + a.w * a.w +
               c.x * c.x + c.y * c.y + c.z * c.z + c.w * c.w;
    #pragma unroll
    for (int off = 16; off > 0; off >>= 1) {
        sum += __shfl_xor_sync(0xffffffffu, sum, off);
        ss  += __shfl_xor_sync(0xffffffffu, ss, off);
    }
    float mean = sum * (1.0f / 256.0f);
    float var = ss * (1.0f / 256.0f) - mean * mean;
    float rstd = rsqrtf(var + 1e-5f);
    const float4* gr = (const float4*)g;
    const float4* br = (const float4*)b;
    float4 g0 = gr[lane * 2], g1 = gr[lane * 2 + 1];
    float4 b0 = br[lane * 2], b1 = br[lane * 2 + 1];
    float o[8];
    o[0] = (a.x - mean) * rstd * g0.x + b0.x;
    o[1] = (a.y - mean) * rstd * g0.y + b0.y;
    o[2] = (a.z - mean) * rstd * g0.z + b0.z;
    o[3] = (a.w - mean) * rstd * g0.w + b0.w;
    o[4] = (c.x - mean) * rstd * g1.x + b1.x;
    o[5] = (c.y - mean) * rstd * g1.y + b1.y;
    o[6] = (c.z - mean) * rstd * g1.z + b1.z;
    o[7] = (c.w - mean) * rstd * g1.w + b1.w;
    __half2 h0 = __floats2half2_rn(o[0], o[1]);
    __half2 h1 = __floats2half2_rn(o[2], o[3]);
    __half2 h2 = __floats2half2_rn(o[4], o[5]);
    __half2 h3 = __floats2half2_rn(o[6], o[7]);
    uint4 u;
    u.x = *(unsigned*)&h0; u.y = *(unsigned*)&h1;
    u.z = *(unsigned*)&h2; u.w = *(unsigned*)&h3;
    ((uint4*)(y + (size_t)warp * DD))[lane] = u;
}

// ---------------- fp32 GEMM (K=12 geo1), half output ----------------
__global__ void k_gemm12(const float* __restrict__ A, const float* __restrict__ B,
                         const float* __restrict__ bias, __half* __restrict__ C,
                         int M, int N, int K) {
    __shared__ float As[64][17];
    __shared__ float Bs[16][64];
    int tid = threadIdx.x;
    int tx = tid & 15, ty = tid >> 4;
    int m0 = blockIdx.y * 64, n0 = blockIdx.x * 64;
    float acc[4][4] = {};
    int KT = (K + 15) >> 4;
    for (int kt = 0; kt < KT; kt++) {
        int k0 = kt << 4;
        #pragma unroll
        for (int i = 0; i < 4; i++) {
            int lin = tid + i * 256;
            int ar = lin >> 4, ac = lin & 15;
            int gk = k0 + ac;
            As[ar][ac] = (gk < K) ? A[(size_t)(m0 + ar) * K + gk] : 0.f;
        }
        #pragma unroll
        for (int i = 0; i < 4; i++) {
            int lin = tid + i * 256;
            int br = lin >> 6, bc = lin & 63;
            int gk = k0 + br;
            Bs[br][bc] = (gk < K) ? B[(size_t)gk * N + n0 + bc] : 0.f;
        }
        __syncthreads();
        #pragma unroll
        for (int kk = 0; kk < 16; kk++) {
            float av[4];
            #pragma unroll
            for (int i = 0; i < 4; i++) av[i] = As[ty * 4 + i][kk];
            float4 bv = *(const float4*)&Bs[kk][tx * 4];
            float bvv[4] = {bv.x, bv.y, bv.z, bv.w};
            #pragma unroll
            for (int i = 0; i < 4; i++)
                #pragma unroll
                for (int j = 0; j < 4; j++)
                    acc[i][j] = fmaf(av[i], bvv[j], acc[i][j]);
        }
        __syncthreads();
    }
    #pragma unroll
    for (int i = 0; i < 4; i++) {
        int row = m0 + ty * 4 + i;
        #pragma unroll
        for (int j = 0; j < 4; j++) {
            int col = n0 + tx * 4 + j;
            float v = acc[i][j] + bias[col];
            v = gelu_f(v);
            C[(size_t)row * N + col] = __float2half_rn(v);
        }
    }
}

// ---------------- FP16 tensor-core GEMM, BK=32, cp.async 2-stage ----------------
template <int BM, bool BIAS, bool GELU, bool RES, bool HOUT>
__device__ __forceinline__ void hgemm_body(
    const __half* __restrict__ A, const __half* __restrict__ B,
    const float* __restrict__ bias, const float* __restrict__ res,
    void* __restrict__ Cv, int N, int K, int m0, int n0) {
    constexpr int SA = 40, SB = 136;
    constexpr int MI = BM / 32;
    extern __shared__ __half smem[];
    __half (*As)[BM][SA] = reinterpret_cast<__half(*)[BM][SA]>(smem);
    __half (*Bs)[32][SB] = reinterpret_cast<__half(*)[32][SB]>(smem + 2 * BM * SA);

    int tid = threadIdx.x;
    int warp = tid >> 5, lane = tid & 31;
    int wm = warp & 1, wn = warp >> 1;
    int g = lane >> 2, t = lane & 3;

    float acc[MI][4][4];
    #pragma unroll
    for (int i = 0; i < MI; i++)
        #pragma unroll
        for (int j = 0; j < 4; j++)
            #pragma unroll
            for (int c = 0; c < 4; c++) acc[i][j][c] = 0.f;

    int KT = K >> 5;
    #pragma unroll
    for (int i = 0; i < BM / 64; i++) {
        int lin = tid + i * 256;
        int row = lin >> 2, col = (lin & 3) * 8;
        cpa16(&As[0][row][col], &A[(size_t)(m0 + row) * K + col]);
    }
    #pragma unroll
    for (int i = 0; i < 2; i++) {
        int lin = tid + i * 256;
        int row = lin >> 4, col = (lin & 15) * 8;
        cpa16(&Bs[0][row][col], &B[(size_t)row * N + n0 + col]);
    }
    asm volatile("cp.async.commit_group;");

    int buf = 0;
    for (int kt = 0; kt < KT; kt++) {
        if (kt + 1 < KT) {
            int k0 = (kt + 1) << 5;
            #pragma unroll
            for (int i = 0; i < BM / 64; i++) {
                int lin = tid + i * 256;
                int row = lin >> 2, col = (lin & 3) * 8;
                cpa16(&As[buf ^ 1][row][col], &A[(size_t)(m0 + row) * K + k0 + col]);
            }
            #pragma unroll
            for (int i = 0; i < 2; i++) {
                int lin = tid + i * 256;
                int row = lin >> 4, col = (lin & 15) * 8;
                cpa16(&Bs[buf ^ 1][row][col], &B[(size_t)(k0 + row) * N + n0 + col]);
            }
            asm volatile("cp.async.commit_group;");
            asm volatile("cp.async.wait_group 1;");
        } else {
            asm volatile("cp.async.wait_group 0;");
        }
        __syncthreads();
        #pragma unroll
        for (int ks = 0; ks < 32; ks += 16) {
            unsigned a[MI][4], b[4][2];
            #pragma unroll
            for (int mi = 0; mi < MI; mi++) {
                int row = wm * (BM / 2) + mi * 16 + (lane & 7) + ((lane >> 3) & 1) * 8;
                int col = ks + (lane >> 4) * 8;
                unsigned addr = smem_u32(&As[buf][row][col]);
                asm volatile(
                    "ldmatrix.sync.aligned.m8n8.x4.shared.b16 {%0,%1,%2,%3}, [%4];"
                    : "=r"(a[mi][0]), "=r"(a[mi][1]), "=r"(a[mi][2]), "=r"(a[mi][3])
                    : "r"(addr));
            }
            #pragma unroll
            for (int p = 0; p < 2; p++) {
                int krow = ks + (lane & 7) + ((lane >> 3) & 1) * 8;
                int ncol = wn * 32 + p * 16 + (lane >> 4) * 8;
                unsigned addr = smem_u32(&Bs[buf][krow][ncol]);
                unsigned r0, r1, r2, r3;
                asm volatile(
                    "ldmatrix.sync.aligned.m8n8.x4.trans.shared.b16 {%0,%1,%2,%3}, [%4];"
                    : "=r"(r0), "=r"(r1), "=r"(r2), "=r"(r3) : "r"(addr));
                b[2 * p][0] = r0; b[2 * p][1] = r1;
                b[2 * p + 1][0] = r2; b[2 * p + 1][1] = r3;
            }
            #pragma unroll
            for (int mi = 0; mi < MI; mi++)
                #pragma unroll
                for (int ni = 0; ni < 4; ni++) {
                    asm volatile(
                        "mma.sync.aligned.m16n8k16.row.col.f32.f16.f16.f32 "
                        "{%0,%1,%2,%3}, {%4,%5,%6,%7}, {%8,%9}, {%0,%1,%2,%3};"
                        : "+f"(acc[mi][ni][0]), "+f"(acc[mi][ni][1]),
                          "+f"(acc[mi][ni][2]), "+f"(acc[mi][ni][3])
                        : "r"(a[mi][0]), "r"(a[mi][1]), "r"(a[mi][2]), "r"(a[mi][3]),
                          "r"(b[ni][0]), "r"(b[ni][1]));
                }
        }
        buf ^= 1;
        __syncthreads();
    }
    #pragma unroll
    for (int mi = 0; mi < MI; mi++) {
        int mrow = m0 + wm * (BM / 2) + mi * 16 + g;
        #pragma unroll
        for (int ni = 0; ni < 4; ni++) {
            int ncol = n0 + wn * 32 + ni * 8 + 2 * t;
            #pragma unroll
            for (int half = 0; half < 2; half++) {
                int row = mrow + half * 8;
                float v0 = acc[mi][ni][half * 2 + 0];
                float v1 = acc[mi][ni][half * 2 + 1];
                if (BIAS) { v0 += bias[ncol]; v1 += bias[ncol + 1]; }
                if (GELU) { v0 = gelu_f(v0); v1 = gelu_f(v1); }
                if (RES) {
                    const float2 r = *(const float2*)&res[(size_t)row * N + ncol];
                    v0 += r.x; v1 += r.y;
                }
                if (HOUT) {
                    __half2 h = __floats2half2_rn(v0, v1);
                    *(__half2*)&((__half*)Cv)[(size_t)row * N + ncol] = h;
                } else {
                    float2 o; o.x = v0; o.y = v1;
                    *(float2*)&((float*)Cv)[(size_t)row * N + ncol] = o;
                }
            }
        }
    }
}

template <int BM, bool BIAS, bool GELU, bool RES, bool HOUT>
__global__ __launch_bounds__(256, 2)
void k_hgemm(const __half* __restrict__ A, const __half* __restrict__ B,
             const float* __restrict__ bias, const float* __restrict__ res,
             void* __restrict__ C, int N, int K) {
    hgemm_body<BM, BIAS, GELU, RES, HOUT>(A, B, bias, res, C, N, K,
                                          blockIdx.y * BM, blockIdx.x * 128);
}

// ---------------- KV projection with in-kernel fp32->fp16 A convert, BM=64 ------
// A fp32 [NS, K]; blockIdx.z selects (Wk->Kf) or (Wv->Vf).
// Smem: A32 double-buffered fp32 stage, A16 single-buffered fp16 tile, Bs
// double-buffered fp16 -> 40 KB total, 2 CTAs/SM.
__global__ __launch_bounds__(256, 2)
void k_hgemm_kvf(const float* __restrict__ A,
                 const __half* __restrict__ B0, const __half* __restrict__ B1,
                 __half* __restrict__ C0, __half* __restrict__ C1, int N, int K) {
    constexpr int BM = 64, SA32 = 36, SA = 40, SB = 136, MI = 2;
    extern __shared__ __align__(16) char smraw[];
    float  (*A32)[BM][SA32] = reinterpret_cast<float(*)[BM][SA32]>(smraw);
    __half (*A16)[SA]       = reinterpret_cast<__half(*)[SA]>(smraw + 2 * BM * SA32 * 4);
    __half (*Bs)[32][SB]    = reinterpret_cast<__half(*)[32][SB]>(
                                  smraw + 2 * BM * SA32 * 4 + BM * SA * 2);
    const __half* B = blockIdx.z ? B1 : B0;
    __half* C = blockIdx.z ? C1 : C0;
    int m0 = blockIdx.y * BM, n0 = blockIdx.x * 128;

    int tid = threadIdx.x;
    int warp = tid >> 5, lane = tid & 31;
    int wm = warp & 1, wn = warp >> 1;
    int g = lane >> 2, t = lane & 3;

    float acc[MI][4][4];
    #pragma unroll
    for (int i = 0; i < MI; i++)
        #pragma unroll
        for (int j = 0; j < 4; j++)
            #pragma unroll
            for (int c = 0; c < 4; c++) acc[i][j][c] = 0.f;

    int KT = K >> 5;
    // stage 0: A32 64x32 fp32 = 512 16B chunks; B 32x128 half = 512 chunks
    #pragma unroll
    for (int i = 0; i < 2; i++) {
        int lin = tid + i * 256;
        int row = lin >> 3, colq = (lin & 7) * 4;
        cpa16(&A32[0][row][colq], &A[(size_t)(m0 + row) * K + colq]);
    }
    #pragma unroll
    for (int i = 0; i < 2; i++) {
        int lin = tid + i * 256;
        int row = lin >> 4, col = (lin & 15) * 8;
        cpa16(&Bs[0][row][col], &B[(size_t)row * N + n0 + col]);
    }
    asm volatile("cp.async.commit_group;");

    int buf = 0;
    for (int kt = 0; kt < KT; kt++) {
        if (kt + 1 < KT) {
            int k0 = (kt + 1) << 5;
            #pragma unroll
            for (int i = 0; i < 2; i++) {
                int lin = tid + i * 256;
                int row = lin >> 3, colq = (lin & 7) * 4;
                cpa16(&A32[buf ^ 1][row][colq], &A[(size_t)(m0 + row) * K + k0 + colq]);
            }
            #pragma unroll
            for (int i = 0; i < 2; i++) {
                int lin = tid + i * 256;
                int row = lin >> 4, col = (lin & 15) * 8;
                cpa16(&Bs[buf ^ 1][row][col], &B[(size_t)(k0 + row) * N + n0 + col]);
            }
            asm volatile("cp.async.commit_group;");
            asm volatile("cp.async.wait_group 1;");
        } else {
            asm volatile("cp.async.wait_group 0;");
        }
        __syncthreads();   // A32[buf]/Bs[buf] ready; all warps done with prior A16 reads
        // convert: thread handles row = tid>>2, 8 cols at (tid&3)*8
        {
            int row = tid >> 2, c0 = (tid & 3) * 8;
            const float* src = &A32[buf][row][c0];
            float4 f0 = *(const float4*)(src + 0);
            float4 f1 = *(const float4*)(src + 4);
            __half2 h0 = __floats2half2_rn(f0.x, f0.y);
            __half2 h1 = __floats2half2_rn(f0.z, f0.w);
            __half2 h2 = __floats2half2_rn(f1.x, f1.y);
            __half2 h3 = __floats2half2_rn(f1.z, f1.w);
            uint4 u;
            u.x = *(unsigned*)&h0; u.y = *(unsigned*)&h1;
            u.z = *(unsigned*)&h2; u.w = *(unsigned*)&h3;
            *(uint4*)&A16[row][c0] = u;
        }
        __syncthreads();   // A16 ready
        #pragma unroll
        for (int ks = 0; ks < 32; ks += 16) {
            unsigned a[MI][4], b[4][2];
            #pragma unroll
            for (int mi = 0; mi < MI; mi++) {
                int row = wm * (BM / 2) + mi * 16 + (lane & 7) + ((lane >> 3) & 1) * 8;
                int col = ks + (lane >> 4) * 8;
                unsigned addr = smem_u32(&A16[row][col]);
                asm volatile(
                    "ldmatrix.sync.aligned.m8n8.x4.shared.b16 {%0,%1,%2,%3}, [%4];"
                    : "=r"(a[mi][0]), "=r"(a[mi][1]), "=r"(a[mi][2]), "=r"(a[mi][3])
                    : "r"(addr));
            }
            #pragma unroll
            for (int p = 0; p < 2; p++) {
                int krow = ks + (lane & 7) + ((lane >> 3) & 1) * 8;
                int ncol = wn * 32 + p * 16 + (lane >> 4) * 8;
                unsigned addr = smem_u32(&Bs[buf][krow][ncol]);
                unsigned r0, r1, r2, r3;
                asm volatile(
                    "ldmatrix.sync.aligned.m8n8.x4.trans.shared.b16 {%0,%1,%2,%3}, [%4];"
                    : "=r"(r0), "=r"(r1), "=r"(r2), "=r"(r3) : "r"(addr));
                b[2 * p][0] = r0; b[2 * p][1] = r1;
                b[2 * p + 1][0] = r2; b[2 * p + 1][1] = r3;
            }
            #pragma unroll
            for (int mi = 0; mi < MI; mi++)
                #pragma unroll
                for (int ni = 0; ni < 4; ni++) {
                    asm volatile(
                        "mma.sync.aligned.m16n8k16.row.col.f32.f16.f16.f32 "
                        "{%0,%1,%2,%3}, {%4,%5,%6,%7}, {%8,%9}, {%0,%1,%2,%3};"
                        : "+f"(acc[mi][ni][0]), "+f"(acc[mi][ni][1]),
                          "+f"(acc[mi][ni][2]), "+f"(acc[mi][ni][3])
                        : "r"(a[mi][0]), "r"(a[mi][1]), "r"(a[mi][2]), "r"(a[mi][3]),
                          "r"(b[ni][0]), "r"(b[ni][1]));
                }
        }
        buf ^= 1;
    }
    #pragma unroll
    for (int mi = 0; mi < MI; mi++) {
        int mrow = m0 + wm * (BM / 2) + mi * 16 + g;
        #pragma unroll
        for (int ni = 0; ni < 4; ni++) {
            int ncol = n0 + wn * 32 + ni * 8 + 2 * t;
            #pragma unroll
            for (int half = 0; half < 2; half++) {
                int row = mrow + half * 8;
                __half2 h = __floats2half2_rn(acc[mi][ni][half * 2 + 0],
                                              acc[mi][ni][half * 2 + 1]);
                *(__half2*)&C[(size_t)row * N + ncol] = h;
            }
        }
    }
}

// ---------------- fused edge attention: warp per query, online softmax ----------
__global__ void k_attn(const int* __restrict__ sidx,
                       const float* __restrict__ log_tau) {
    int warp = (blockIdx.x * blockDim.x + threadIdx.x) >> 5;
    int lane = threadIdx.x & 31;
    if (warp >= NQ) return;
    int q = warp;
    int st = g_rowptr[q], en = g_rowptr[q + 1];
    float scale = 0.17677669529663689f * expf(-log_tau[0]);

    float qv[8];
    unpack8(((const uint4*)(g_Qf_h + (size_t)q * DD))[lane], qv);

    float m = 0.0f;   // reference: smax = max(0, segment max)
    float ssum = 0.0f;
    float a[8] = {0.f, 0.f, 0.f, 0.f, 0.f, 0.f, 0.f, 0.f};

    int e = st;
    for (; e + 1 < en; e += 2) {
        int sA = sidx[e], sB = sidx[e + 1];
        float kA[8], kB[8], vA[8], vB[8];
        unpack8(((const uint4*)(g_Kf_h + (size_t)sA * DD))[lane], kA);
        unpack8(((const uint4*)(g_Kf_h + (size_t)sB * DD))[lane], kB);
        unpack8(((const uint4*)(g_Vf_h + (size_t)sA * DD))[lane], vA);
        unpack8(((const uint4*)(g_Vf_h + (size_t)sB * DD))[lane], vB);
        float dA = 0.f, dB = 0.f;
        #pragma unroll
        for (int j = 0; j < 8; j++) { dA += qv[j] * kA[j]; dB += qv[j] * kB[j]; }
        dA += __shfl_xor_sync(0xffffffffu, dA, 1);
        dA += __shfl_xor_sync(0xffffffffu, dA, 2);
        dB += __shfl_xor_sync(0xffffffffu, dB, 1);
        dB += __shfl_xor_sync(0xffffffffu, dB, 2);
        dA *= scale; dB *= scale;
        float mn = fmaxf(m, fmaxf(dA, dB));
        float c = __expf(m - mn);
        float rA = __expf(dA - mn);
        float rB = __expf(dB - mn);
        #pragma unroll
        for (int j = 0; j < 8; j++) a[j] = a[j] * c + rA * vA[j] + rB * vB[j];
        ssum = ssum * c + rA + rB;
        m = mn;
    }
    if (e < en) {
        int s = sidx[e];
        float kv[8], vv[8];
        unpack8(((const uint4*)(g_Kf_h + (size_t)s * DD))[lane], kv);
        unpack8(((const uint4*)(g_Vf_h + (size_t)s * DD))[lane], vv);
        float d = 0.f;
        #pragma unroll
        for (int j = 0; j < 8; j++) d += qv[j] * kv[j];
        d += __shfl_xor_sync(0xffffffffu, d, 1);
        d += __shfl_xor_sync(0xffffffffu, d, 2);
        d *= scale;
        float mn = fmaxf(m, d);
        float c = __expf(m - mn);
        float r = __expf(d - mn);
        #pragma unroll
        for (int j = 0; j < 8; j++) a[j] = a[j] * c + r * vv[j];
        ssum = ssum * c + r;
        m = mn;
    }

    float inv = 1.0f / fmaxf(ssum, 1e-8f);
    float gsc = ssum * inv;
    float gv[8];
    unpack8(((const uint4*)(g_Gf_h + (size_t)q * DD))[lane], gv);
    float o[8];
    #pragma unroll
    for (int j = 0; j < 8; j++) o[j] = a[j] * inv + gv[j] * gsc;
    __half2 h0 = __floats2half2_rn(o[0], o[1]);
    __half2 h1 = __floats2half2_rn(o[2], o[3]);
    __half2 h2 = __floats2half2_rn(o[4], o[5]);
    __half2 h3 = __floats2half2_rn(o[6], o[7]);
    uint4 u;
    u.x = *(unsigned*)&h0; u.y = *(unsigned*)&h1;
    u.z = *(unsigned*)&h2; u.w = *(unsigned*)&h3;
    ((uint4*)(g_out_h + (size_t)q * DD))[lane] = u;
}

// ---------------- host ----------------
template <typename T>
static T* symp(const void* sym) {
    void* p = nullptr;
    cudaGetSymbolAddress(&p, sym);
    return (T*)p;
}

#define SMEM_H(BM) ((2 * (BM) * 40 + 2 * 32 * 136) * (int)sizeof(__half))
#define SMEM_KVF (2 * 64 * 36 * 4 + 64 * 40 * 2 + 2 * 32 * 136 * 2)

struct Ctx {
    cudaStream_t s1, s2;
    cudaEvent_t evRoot, evKV, evG;
    Ctx() {
        cudaStreamCreateWithFlags(&s1, cudaStreamNonBlocking);
        cudaStreamCreateWithFlags(&s2, cudaStreamNonBlocking);
        cudaEventCreateWithFlags(&evRoot, cudaEventDisableTiming);
        cudaEventCreateWithFlags(&evKV, cudaEventDisableTiming);
        cudaEventCreateWithFlags(&evG, cudaEventDisableTiming);
        cudaFuncSetAttribute((const void*)k_hgemm_kvf,
            cudaFuncAttributeMaxDynamicSharedMemorySize, SMEM_KVF);
        cudaFuncSetAttribute((const void*)k_hgemm<64, false, false, false, true>,
            cudaFuncAttributeMaxDynamicSharedMemorySize, SMEM_H(64));
        cudaFuncSetAttribute((const void*)k_hgemm<64, true, true, false, true>,
            cudaFuncAttributeMaxDynamicSharedMemorySize, SMEM_H(64));
        cudaFuncSetAttribute((const void*)k_hgemm<64, true, false, true, false>,
            cudaFuncAttributeMaxDynamicSharedMemorySize, SMEM_H(64));
    }
};

extern "C" void kernel_launch(void* const* d_in, const int* in_sizes, int n_in,
                              void* d_out, int out_size) {
    const float* query_tokens  = (const float*)d_in[0];
    const float* query_pos     = (const float*)d_in[1];
    const float* support_feats = (const float*)d_in[2];
    const float* support_pos   = (const float*)d_in[3];
    const float* Wq   = (const float*)d_in[4];
    const float* Wk   = (const float*)d_in[5];
    const float* Wv   = (const float*)d_in[6];
    const float* Wg   = (const float*)d_in[7];
    const float* Wo   = (const float*)d_in[8];
    const float* bo   = (const float*)d_in[9];
    const float* log_tau = (const float*)d_in[10];
    const float* ln1_g = (const float*)d_in[11];
    const float* ln1_b = (const float*)d_in[12];
    const float* ln2_g = (const float*)d_in[13];
    const float* ln2_b = (const float*)d_in[14];
    const float* Wf1  = (const float*)d_in[15];
    const float* bf1  = (const float*)d_in[16];
    const float* Wf2  = (const float*)d_in[17];
    const float* bf2  = (const float*)d_in[18];
    const float* Gw1  = (const float*)d_in[19];
    const float* Gb1  = (const float*)d_in[20];
    const float* Gw2  = (const float*)d_in[21];
    const float* Gb2  = (const float*)d_in[22];
    const int* q_idx  = (const int*)d_in[23];
    const int* s_idx  = (const int*)d_in[24];
    float* out = (float*)d_out;

    float*  p_raw   = symp<float>(g_raw);
    float*  p_x     = symp<float>(g_x);
    __half* p_qt    = symp<__half>(g_qt_h);
    __half* p_geoh  = symp<__half>(g_geoh_h);
    __half* p_geo   = symp<__half>(g_geo_h);
    __half* p_Qf    = symp<__half>(g_Qf_h);
    __half* p_Kf    = symp<__half>(g_Kf_h);
    __half* p_Vf    = symp<__half>(g_Vf_h);
    __half* p_Gf    = symp<__half>(g_Gf_h);
    __half* p_outh  = symp<__half>(g_out_h);
    __half* p_h1    = symp<__half>(g_h1_h);
    __half* p_Wq    = symp<__half>(g_Wq_h);
    __half* p_Wk    = symp<__half>(g_Wk_h);
    __half* p_Wv    = symp<__half>(g_Wv_h);
    __half* p_Wg    = symp<__half>(g_Wg_h);
    __half* p_Wo    = symp<__half>(g_Wo_h);
    __half* p_Wf1   = symp<__half>(g_Wf1_h);
    __half* p_Wf2   = symp<__half>(g_Wf2_h);
    __half* p_Gw2   = symp<__half>(g_Gw2_h);

    static Ctx ctx;

    // all weight converts in one launch, pre-fork (everything depends on it)
    CvtJobs jobs;
    jobs.src[0] = Wq;  jobs.dst[0] = p_Wq;  jobs.n4[0] = DD * DD / 4;
    jobs.src[1] = Wk;  jobs.dst[1] = p_Wk;  jobs.n4[1] = DD * DD / 4;
    jobs.src[2] = Wv;  jobs.dst[2] = p_Wv;  jobs.n4[2] = DD * DD / 4;
    jobs.src[3] = Wo;  jobs.dst[3] = p_Wo;  jobs.n4[3] = DD * DD / 4;
    jobs.src[4] = Wg;  jobs.dst[4] = p_Wg;  jobs.n4[4] = NGEO * DD / 4;
    jobs.src[5] = Gw2; jobs.dst[5] = p_Gw2; jobs.n4[5] = NGEO * NGEO / 4;
    jobs.src[6] = Wf1; jobs.dst[6] = p_Wf1; jobs.n4[6] = DD * NFFN / 4;
    jobs.src[7] = Wf2; jobs.dst[7] = p_Wf2; jobs.n4[7] = NFFN * DD / 4;
    k_cvt_all<<<dim3(DD * NFFN / 4 / 256, 8), 256>>>(jobs);

    // fork
    cudaEventRecord(ctx.evRoot, 0);
    cudaStreamWaitEvent(ctx.s1, ctx.evRoot, 0);
    cudaStreamWaitEvent(ctx.s2, ctx.evRoot, 0);

    // s1: merged K/V projection (A converted in-kernel), BM=64, 2 CTAs/SM
    k_hgemm_kvf<<<dim3(DD / 128, NS / 64, 2), 256, SMEM_KVF, ctx.s1>>>(
        support_feats, p_Wk, p_Wv, p_Kf, p_Vf, DD, DD);
    cudaEventRecord(ctx.evKV, ctx.s1);

    // s2: geo chain
    k_bounds<<<NE / 256, 256, 0, ctx.s2>>>(q_idx);
    k_geostats<<<NQ / 8, 256, 0, ctx.s2>>>(query_pos, support_pos, s_idx);
    k_gemm12<<<dim3(NGEO / 64, NQ / 64), 256, 0, ctx.s2>>>(
        p_raw, Gw1, Gb1, p_geoh, NQ, NGEO, 12);
    k_hgemm<64, true, true, false, true><<<dim3(NGEO / 128, NQ / 64), 256, SMEM_H(64), ctx.s2>>>(
        p_geoh, p_Gw2, Gb2, nullptr, p_geo, NGEO, NGEO);
    k_hgemm<64, false, false, false, true><<<dim3(DD / 128, NQ / 64), 256, SMEM_H(64), ctx.s2>>>(
        p_geo, p_Wg, nullptr, nullptr, p_Gf, DD, NGEO);
    cudaEventRecord(ctx.evG, ctx.s2);

    // s0 (default): query chain
    k_ln<<<NQ / 8, 256>>>(query_tokens, ln1_g, ln1_b, p_qt);
    k_hgemm<64, false, false, false, true><<<dim3(DD / 128, NQ / 64), 256, SMEM_H(64)>>>(
        p_qt, p_Wq, nullptr, nullptr, p_Qf, DD, DD);

    // join, fused edge attention
    cudaStreamWaitEvent(0, ctx.evKV, 0);
    cudaStreamWaitEvent(0, ctx.evG, 0);
    k_attn<<<NQ / 8, 256>>>(s_idx, log_tau);

    // tail
    k_hgemm<64, true, false, true, false><<<dim3(DD / 128, NQ / 64), 256, SMEM_H(64)>>>(
        p_outh, p_Wo, bo, query_tokens, p_x, DD, DD);
    k_ln<<<NQ / 8, 256>>>(p_x, ln2_g, ln2_b, p_qt);
    k_hgemm<64, true, true, false, true><<<dim3(NFFN / 128, NQ / 64), 256, SMEM_H(64)>>>(
        p_qt, p_Wf1, bf1, nullptr, p_h1, NFFN, DD);
    k_hgemm<64, true, false, true, false><<<dim3(DD / 128, NQ / 64), 256, SMEM_H(64)>>>(
        p_h1, p_Wf2, bf2, p_x, out, DD, NFFN);
}

// round 10
// speedup vs baseline: 4.9066x; 1.0159x over previous
#include <cuda_runtime.h>
#include <cuda_fp16.h>
#include <math.h>

#define NQ 8192
#define NS 32768
#define NE 131072
#define DD 256
#define NH 8
#define HDIM 32
#define NGEO 128
#define NFFN 512

// ---------------- scratch (device globals; no allocation) ----------------
__device__ float  g_raw[NQ * 12];
__device__ float  g_x[NQ * DD];
__device__ int    g_rowptr[NQ + 1];

// half activations / weights
__device__ __half g_qt_h[NQ * DD];
__device__ __half g_geoh_h[NQ * NGEO];
__device__ __half g_geo_h[NQ * NGEO];
__device__ __half g_Qf_h[NQ * DD];
__device__ __half g_Kf_h[NS * DD];
__device__ __half g_Vf_h[NS * DD];
__device__ __half g_Gf_h[NQ * DD];
__device__ __half g_out_h[NQ * DD];
__device__ __half g_h1_h[NQ * NFFN];
__device__ __half g_Wq_h[DD * DD];
__device__ __half g_Wk_h[DD * DD];
__device__ __half g_Wv_h[DD * DD];
__device__ __half g_Wg_h[NGEO * DD];
__device__ __half g_Wo_h[DD * DD];
__device__ __half g_Wf1_h[DD * NFFN];
__device__ __half g_Wf2_h[NFFN * DD];
__device__ __half g_Gw2_h[NGEO * NGEO];

__device__ __forceinline__ float gelu_f(float x) {
    return 0.5f * x * (1.0f + erff(x * 0.7071067811865475f));
}

__device__ __forceinline__ void cpa16(void* dst, const void* src) {
    unsigned d = (unsigned)__cvta_generic_to_shared(dst);
    asm volatile("cp.async.cg.shared.global [%0], [%1], 16;" :: "r"(d), "l"(src));
}
__device__ __forceinline__ unsigned smem_u32(const void* p) {
    return (unsigned)__cvta_generic_to_shared(p);
}
__device__ __forceinline__ void unpack8(uint4 u, float* f) {
    float2 a = __half22float2(*(const __half2*)&u.x);
    float2 b = __half22float2(*(const __half2*)&u.y);
    float2 c = __half22float2(*(const __half2*)&u.z);
    float2 d = __half22float2(*(const __half2*)&u.w);
    f[0] = a.x; f[1] = a.y; f[2] = b.x; f[3] = b.y;
    f[4] = c.x; f[5] = c.y; f[6] = d.x; f[7] = d.y;
}
__device__ __forceinline__ float dot8(const float* q, uint4 u) {
    float k[8];
    unpack8(u, k);
    float d = 0.f;
    #pragma unroll
    for (int j = 0; j < 8; j++) d += q[j] * k[j];
    return d;
}

// ---------------- fused fp32 -> fp16 weight converts ----------------
struct CvtJobs {
    const float* src[8];
    __half* dst[8];
    int n4[8];
};
__global__ void k_cvt_all(CvtJobs j) {
    int w = blockIdx.y;
    int i = blockIdx.x * blockDim.x + threadIdx.x;
    if (i >= j.n4[w]) return;
    float4 v = ((const float4*)j.src[w])[i];
    __half2 h0 = __floats2half2_rn(v.x, v.y);
    __half2 h1 = __floats2half2_rn(v.z, v.w);
    uint2 u;
    u.x = *(unsigned*)&h0;
    u.y = *(unsigned*)&h1;
    ((uint2*)j.dst[w])[i] = u;
}

// ---------------- row_ptr via boundary scan (q_idx sorted) ----------------
__global__ void k_bounds(const int* __restrict__ qidx) {
    int e = blockIdx.x * blockDim.x + threadIdx.x;
    if (e >= NE) return;
    int v = qidx[e];
    int prev = (e == 0) ? -1 : qidx[e - 1];
    for (int q = prev + 1; q <= v; q++) g_rowptr[q] = e;
    if (e == NE - 1) {
        for (int q = v + 1; q <= NQ; q++) g_rowptr[q] = NE;
    }
}

// ---------------- geo stats: warp per query ----------------
__global__ void k_geostats(const float* __restrict__ qpos,
                           const float* __restrict__ spos,
                           const int* __restrict__ sidx) {
    int warp = (blockIdx.x * blockDim.x + threadIdx.x) >> 5;
    int lane = threadIdx.x & 31;
    if (warp >= NQ) return;
    int q = warp;
    int st = g_rowptr[q], en = g_rowptr[q + 1];
    float qp0 = qpos[q * 3 + 0], qp1 = qpos[q * 3 + 1], qp2 = qpos[q * 3 + 2];
    float s0 = 0.f, s1 = 0.f, s2 = 0.f;
    float ss0 = 0.f, ss1 = 0.f, ss2 = 0.f;
    float mn0 = 1e30f, mn1 = 1e30f, mn2 = 1e30f;
    float mx0 = -1e30f, mx1 = -1e30f, mx2 = -1e30f;
    for (int e = st + lane; e < en; e += 32) {
        int s = sidx[e];
        float r0 = spos[s * 3 + 0] - qp0;
        float r1 = spos[s * 3 + 1] - qp1;
        float r2 = spos[s * 3 + 2] - qp2;
        s0 += r0; s1 += r1; s2 += r2;
        ss0 += r0 * r0; ss1 += r1 * r1; ss2 += r2 * r2;
        mn0 = fminf(mn0, r0); mn1 = fminf(mn1, r1); mn2 = fminf(mn2, r2);
        mx0 = fmaxf(mx0, r0); mx1 = fmaxf(mx1, r1); mx2 = fmaxf(mx2, r2);
    }
    #pragma unroll
    for (int off = 16; off > 0; off >>= 1) {
        s0 += __shfl_xor_sync(0xffffffffu, s0, off);
        s1 += __shfl_xor_sync(0xffffffffu, s1, off);
        s2 += __shfl_xor_sync(0xffffffffu, s2, off);
        ss0 += __shfl_xor_sync(0xffffffffu, ss0, off);
        ss1 += __shfl_xor_sync(0xffffffffu, ss1, off);
        ss2 += __shfl_xor_sync(0xffffffffu, ss2, off);
        mn0 = fminf(mn0, __shfl_xor_sync(0xffffffffu, mn0, off));
        mn1 = fminf(mn1, __shfl_xor_sync(0xffffffffu, mn1, off));
        mn2 = fminf(mn2, __shfl_xor_sync(0xffffffffu, mn2, off));
        mx0 = fmaxf(mx0, __shfl_xor_sync(0xffffffffu, mx0, off));
        mx1 = fmaxf(mx1, __shfl_xor_sync(0xffffffffu, mx1, off));
        mx2 = fmaxf(mx2, __shfl_xor_sync(0xffffffffu, mx2, off));
    }
    if (lane == 0) {
        float cnt = fmaxf((float)(en - st), 1.0f);
        float m0 = s0 / cnt, m1 = s1 / cnt, m2 = s2 / cnt;
        float v0 = fmaxf(ss0 / cnt - m0 * m0, 0.f);
        float v1 = fmaxf(ss1 / cnt - m1 * m1, 0.f);
        float v2 = fmaxf(ss2 / cnt - m2 * m2, 0.f);
        float* r = g_raw + q * 12;
        r[0] = m0; r[1] = m1; r[2] = m2;
        r[3] = sqrtf(v0); r[4] = sqrtf(v1); r[5] = sqrtf(v2);
        r[6] = fminf(fmaxf(mn0, -100.f), 100.f);
        r[7] = fminf(fmaxf(mn1, -100.f), 100.f);
        r[8] = fminf(fmaxf(mn2, -100.f), 100.f);
        r[9]  = fminf(fmaxf(mx0, -100.f), 100.f);
        r[10] = fminf(fmaxf(mx1, -100.f), 100.f);
        r[11] = fminf(fmaxf(mx2, -100.f), 100.f);
    }
}

// ---------------- LayerNorm: warp per row, fp32 in, fp16 out ----------------
__global__ void k_ln(const float* __restrict__ x, const float* __restrict__ g,
                     const float* __restrict__ b, __half* __restrict__ y) {
    int warp = (blockIdx.x * blockDim.x + threadIdx.x) >> 5;
    int lane = threadIdx.x & 31;
    if (warp >= NQ) return;
    const float4* xr = (const float4*)(x + warp * DD);
    float4 a = xr[lane * 2], c = xr[lane * 2 + 1];
    float sum = a.x + a.y + a.z + a.w + c.x + c.y + c.z + c.w;
    float ss = a.x * a.x + a.y * a.y + a.z * a.z + a.w * a.w +
               c.x * c.x + c.y * c.y + c.z * c.z + c.w * c.w;
    #pragma unroll
    for (int off = 16; off > 0; off >>= 1) {
        sum += __shfl_xor_sync(0xffffffffu, sum, off);
        ss  += __shfl_xor_sync(0xffffffffu, ss, off);
    }
    float mean = sum * (1.0f / 256.0f);
    float var = ss * (1.0f / 256.0f) - mean * mean;
    float rstd = rsqrtf(var + 1e-5f);
    const float4* gr = (const float4*)g;
    const float4* br = (const float4*)b;
    float4 g0 = gr[lane * 2], g1 = gr[lane * 2 + 1];
    float4 b0 = br[lane * 2], b1 = br[lane * 2 + 1];
    float o[8];
    o[0] = (a.x - mean) * rstd * g0.x + b0.x;
    o[1] = (a.y - mean) * rstd * g0.y + b0.y;
    o[2] = (a.z - mean) * rstd * g0.z + b0.z;
    o[3] = (a.w - mean) * rstd * g0.w + b0.w;
    o[4] = (c.x - mean) * rstd * g1.x + b1.x;
    o[5] = (c.y - mean) * rstd * g1.y + b1.y;
    o[6] = (c.z - mean) * rstd * g1.z + b1.z;
    o[7] = (c.w - mean) * rstd * g1.w + b1.w;
    __half2 h0 = __floats2half2_rn(o[0], o[1]);
    __half2 h1 = __floats2half2_rn(o[2], o[3]);
    __half2 h2 = __floats2half2_rn(o[4], o[5]);
    __half2 h3 = __floats2half2_rn(o[6], o[7]);
    uint4 u;
    u.x = *(unsigned*)&h0; u.y = *(unsigned*)&h1;
    u.z = *(unsigned*)&h2; u.w = *(unsigned*)&h3;
    ((uint4*)(y + (size_t)warp * DD))[lane] = u;
}

// ---------------- fp32 GEMM (K=12 geo1), half output ----------------
__global__ void k_gemm12(const float* __restrict__ A, const float* __restrict__ B,
                         const float* __restrict__ bias, __half* __restrict__ C,
                         int M, int N, int K) {
    __shared__ float As[64][17];
    __shared__ float Bs[16][64];
    int tid = threadIdx.x;
    int tx = tid & 15, ty = tid >> 4;
    int m0 = blockIdx.y * 64, n0 = blockIdx.x * 64;
    float acc[4][4] = {};
    int KT = (K + 15) >> 4;
    for (int kt = 0; kt < KT; kt++) {
        int k0 = kt << 4;
        #pragma unroll
        for (int i = 0; i < 4; i++) {
            int lin = tid + i * 256;
            int ar = lin >> 4, ac = lin & 15;
            int gk = k0 + ac;
            As[ar][ac] = (gk < K) ? A[(size_t)(m0 + ar) * K + gk] : 0.f;
        }
        #pragma unroll
        for (int i = 0; i < 4; i++) {
            int lin = tid + i * 256;
            int br = lin >> 6, bc = lin & 63;
            int gk = k0 + br;
            Bs[br][bc] = (gk < K) ? B[(size_t)gk * N + n0 + bc] : 0.f;
        }
        __syncthreads();
        #pragma unroll
        for (int kk = 0; kk < 16; kk++) {
            float av[4];
            #pragma unroll
            for (int i = 0; i < 4; i++) av[i] = As[ty * 4 + i][kk];
            float4 bv = *(const float4*)&Bs[kk][tx * 4];
            float bvv[4] = {bv.x, bv.y, bv.z, bv.w};
            #pragma unroll
            for (int i = 0; i < 4; i++)
                #pragma unroll
                for (int j = 0; j < 4; j++)
                    acc[i][j] = fmaf(av[i], bvv[j], acc[i][j]);
        }
        __syncthreads();
    }
    #pragma unroll
    for (int i = 0; i < 4; i++) {
        int row = m0 + ty * 4 + i;
        #pragma unroll
        for (int j = 0; j < 4; j++) {
            int col = n0 + tx * 4 + j;
            float v = acc[i][j] + bias[col];
            v = gelu_f(v);
            C[(size_t)row * N + col] = __float2half_rn(v);
        }
    }
}

// ---------------- FP16 tensor-core GEMM, BK=32, cp.async 2-stage ----------------
template <int BM, bool BIAS, bool GELU, bool RES, bool HOUT>
__device__ __forceinline__ void hgemm_body(
    const __half* __restrict__ A, const __half* __restrict__ B,
    const float* __restrict__ bias, const float* __restrict__ res,
    void* __restrict__ Cv, int N, int K, int m0, int n0) {
    constexpr int SA = 40, SB = 136;
    constexpr int MI = BM / 32;
    extern __shared__ __half smem[];
    __half (*As)[BM][SA] = reinterpret_cast<__half(*)[BM][SA]>(smem);
    __half (*Bs)[32][SB] = reinterpret_cast<__half(*)[32][SB]>(smem + 2 * BM * SA);

    int tid = threadIdx.x;
    int warp = tid >> 5, lane = tid & 31;
    int wm = warp & 1, wn = warp >> 1;
    int g = lane >> 2, t = lane & 3;

    float acc[MI][4][4];
    #pragma unroll
    for (int i = 0; i < MI; i++)
        #pragma unroll
        for (int j = 0; j < 4; j++)
            #pragma unroll
            for (int c = 0; c < 4; c++) acc[i][j][c] = 0.f;

    int KT = K >> 5;
    #pragma unroll
    for (int i = 0; i < BM / 64; i++) {
        int lin = tid + i * 256;
        int row = lin >> 2, col = (lin & 3) * 8;
        cpa16(&As[0][row][col], &A[(size_t)(m0 + row) * K + col]);
    }
    #pragma unroll
    for (int i = 0; i < 2; i++) {
        int lin = tid + i * 256;
        int row = lin >> 4, col = (lin & 15) * 8;
        cpa16(&Bs[0][row][col], &B[(size_t)row * N + n0 + col]);
    }
    asm volatile("cp.async.commit_group;");

    int buf = 0;
    for (int kt = 0; kt < KT; kt++) {
        if (kt + 1 < KT) {
            int k0 = (kt + 1) << 5;
            #pragma unroll
            for (int i = 0; i < BM / 64; i++) {
                int lin = tid + i * 256;
                int row = lin >> 2, col = (lin & 3) * 8;
                cpa16(&As[buf ^ 1][row][col], &A[(size_t)(m0 + row) * K + k0 + col]);
            }
            #pragma unroll
            for (int i = 0; i < 2; i++) {
                int lin = tid + i * 256;
                int row = lin >> 4, col = (lin & 15) * 8;
                cpa16(&Bs[buf ^ 1][row][col], &B[(size_t)(k0 + row) * N + n0 + col]);
            }
            asm volatile("cp.async.commit_group;");
            asm volatile("cp.async.wait_group 1;");
        } else {
            asm volatile("cp.async.wait_group 0;");
        }
        __syncthreads();
        #pragma unroll
        for (int ks = 0; ks < 32; ks += 16) {
            unsigned a[MI][4], b[4][2];
            #pragma unroll
            for (int mi = 0; mi < MI; mi++) {
                int row = wm * (BM / 2) + mi * 16 + (lane & 7) + ((lane >> 3) & 1) * 8;
                int col = ks + (lane >> 4) * 8;
                unsigned addr = smem_u32(&As[buf][row][col]);
                asm volatile(
                    "ldmatrix.sync.aligned.m8n8.x4.shared.b16 {%0,%1,%2,%3}, [%4];"
                    : "=r"(a[mi][0]), "=r"(a[mi][1]), "=r"(a[mi][2]), "=r"(a[mi][3])
                    : "r"(addr));
            }
            #pragma unroll
            for (int p = 0; p < 2; p++) {
                int krow = ks + (lane & 7) + ((lane >> 3) & 1) * 8;
                int ncol = wn * 32 + p * 16 + (lane >> 4) * 8;
                unsigned addr = smem_u32(&Bs[buf][krow][ncol]);
                unsigned r0, r1, r2, r3;
                asm volatile(
                    "ldmatrix.sync.aligned.m8n8.x4.trans.shared.b16 {%0,%1,%2,%3}, [%4];"
                    : "=r"(r0), "=r"(r1), "=r"(r2), "=r"(r3) : "r"(addr));
                b[2 * p][0] = r0; b[2 * p][1] = r1;
                b[2 * p + 1][0] = r2; b[2 * p + 1][1] = r3;
            }
            #pragma unroll
            for (int mi = 0; mi < MI; mi++)
                #pragma unroll
                for (int ni = 0; ni < 4; ni++) {
                    asm volatile(
                        "mma.sync.aligned.m16n8k16.row.col.f32.f16.f16.f32 "
                        "{%0,%1,%2,%3}, {%4,%5,%6,%7}, {%8,%9}, {%0,%1,%2,%3};"
                        : "+f"(acc[mi][ni][0]), "+f"(acc[mi][ni][1]),
                          "+f"(acc[mi][ni][2]), "+f"(acc[mi][ni][3])
                        : "r"(a[mi][0]), "r"(a[mi][1]), "r"(a[mi][2]), "r"(a[mi][3]),
                          "r"(b[ni][0]), "r"(b[ni][1]));
                }
        }
        buf ^= 1;
        __syncthreads();
    }
    #pragma unroll
    for (int mi = 0; mi < MI; mi++) {
        int mrow = m0 + wm * (BM / 2) + mi * 16 + g;
        #pragma unroll
        for (int ni = 0; ni < 4; ni++) {
            int ncol = n0 + wn * 32 + ni * 8 + 2 * t;
            #pragma unroll
            for (int half = 0; half < 2; half++) {
                int row = mrow + half * 8;
                float v0 = acc[mi][ni][half * 2 + 0];
                float v1 = acc[mi][ni][half * 2 + 1];
                if (BIAS) { v0 += bias[ncol]; v1 += bias[ncol + 1]; }
                if (GELU) { v0 = gelu_f(v0); v1 = gelu_f(v1); }
                if (RES) {
                    const float2 r = *(const float2*)&res[(size_t)row * N + ncol];
                    v0 += r.x; v1 += r.y;
                }
                if (HOUT) {
                    __half2 h = __floats2half2_rn(v0, v1);
                    *(__half2*)&((__half*)Cv)[(size_t)row * N + ncol] = h;
                } else {
                    float2 o; o.x = v0; o.y = v1;
                    *(float2*)&((float*)Cv)[(size_t)row * N + ncol] = o;
                }
            }
        }
    }
}

template <int BM, bool BIAS, bool GELU, bool RES, bool HOUT>
__global__ __launch_bounds__(256, 2)
void k_hgemm(const __half* __restrict__ A, const __half* __restrict__ B,
             const float* __restrict__ bias, const float* __restrict__ res,
             void* __restrict__ C, int N, int K) {
    hgemm_body<BM, BIAS, GELU, RES, HOUT>(A, B, bias, res, C, N, K,
                                          blockIdx.y * BM, blockIdx.x * 128);
}

// ---------------- KV projection with in-kernel fp32->fp16 A convert, BM=64 ------
__global__ __launch_bounds__(256, 2)
void k_hgemm_kvf(const float* __restrict__ A,
                 const __half* __restrict__ B0, const __half* __restrict__ B1,
                 __half* __restrict__ C0, __half* __restrict__ C1, int N, int K) {
    constexpr int BM = 64, SA32 = 36, SA = 40, SB = 136, MI = 2;
    extern __shared__ __align__(16) char smraw[];
    float  (*A32)[BM][SA32] = reinterpret_cast<float(*)[BM][SA32]>(smraw);
    __half (*A16)[SA]       = reinterpret_cast<__half(*)[SA]>(smraw + 2 * BM * SA32 * 4);
    __half (*Bs)[32][SB]    = reinterpret_cast<__half(*)[32][SB]>(
                                  smraw + 2 * BM * SA32 * 4 + BM * SA * 2);
    const __half* B = blockIdx.z ? B1 : B0;
    __half* C = blockIdx.z ? C1 : C0;
    int m0 = blockIdx.y * BM, n0 = blockIdx.x * 128;

    int tid = threadIdx.x;
    int warp = tid >> 5, lane = tid & 31;
    int wm = warp & 1, wn = warp >> 1;
    int g = lane >> 2, t = lane & 3;

    float acc[MI][4][4];
    #pragma unroll
    for (int i = 0; i < MI; i++)
        #pragma unroll
        for (int j = 0; j < 4; j++)
            #pragma unroll
            for (int c = 0; c < 4; c++) acc[i][j][c] = 0.f;

    int KT = K >> 5;
    #pragma unroll
    for (int i = 0; i < 2; i++) {
        int lin = tid + i * 256;
        int row = lin >> 3, colq = (lin & 7) * 4;
        cpa16(&A32[0][row][colq], &A[(size_t)(m0 + row) * K + colq]);
    }
    #pragma unroll
    for (int i = 0; i < 2; i++) {
        int lin = tid + i * 256;
        int row = lin >> 4, col = (lin & 15) * 8;
        cpa16(&Bs[0][row][col], &B[(size_t)row * N + n0 + col]);
    }
    asm volatile("cp.async.commit_group;");

    int buf = 0;
    for (int kt = 0; kt < KT; kt++) {
        if (kt + 1 < KT) {
            int k0 = (kt + 1) << 5;
            #pragma unroll
            for (int i = 0; i < 2; i++) {
                int lin = tid + i * 256;
                int row = lin >> 3, colq = (lin & 7) * 4;
                cpa16(&A32[buf ^ 1][row][colq], &A[(size_t)(m0 + row) * K + k0 + colq]);
            }
            #pragma unroll
            for (int i = 0; i < 2; i++) {
                int lin = tid + i * 256;
                int row = lin >> 4, col = (lin & 15) * 8;
                cpa16(&Bs[buf ^ 1][row][col], &B[(size_t)(k0 + row) * N + n0 + col]);
            }
            asm volatile("cp.async.commit_group;");
            asm volatile("cp.async.wait_group 1;");
        } else {
            asm volatile("cp.async.wait_group 0;");
        }
        __syncthreads();
        {
            int row = tid >> 2, c0 = (tid & 3) * 8;
            const float* src = &A32[buf][row][c0];
            float4 f0 = *(const float4*)(src + 0);
            float4 f1 = *(const float4*)(src + 4);
            __half2 h0 = __floats2half2_rn(f0.x, f0.y);
            __half2 h1 = __floats2half2_rn(f0.z, f0.w);
            __half2 h2 = __floats2half2_rn(f1.x, f1.y);
            __half2 h3 = __floats2half2_rn(f1.z, f1.w);
            uint4 u;
            u.x = *(unsigned*)&h0; u.y = *(unsigned*)&h1;
            u.z = *(unsigned*)&h2; u.w = *(unsigned*)&h3;
            *(uint4*)&A16[row][c0] = u;
        }
        __syncthreads();
        #pragma unroll
        for (int ks = 0; ks < 32; ks += 16) {
            unsigned a[MI][4], b[4][2];
            #pragma unroll
            for (int mi = 0; mi < MI; mi++) {
                int row = wm * (BM / 2) + mi * 16 + (lane & 7) + ((lane >> 3) & 1) * 8;
                int col = ks + (lane >> 4) * 8;
                unsigned addr = smem_u32(&A16[row][col]);
                asm volatile(
                    "ldmatrix.sync.aligned.m8n8.x4.shared.b16 {%0,%1,%2,%3}, [%4];"
                    : "=r"(a[mi][0]), "=r"(a[mi][1]), "=r"(a[mi][2]), "=r"(a[mi][3])
                    : "r"(addr));
            }
            #pragma unroll
            for (int p = 0; p < 2; p++) {
                int krow = ks + (lane & 7) + ((lane >> 3) & 1) * 8;
                int ncol = wn * 32 + p * 16 + (lane >> 4) * 8;
                unsigned addr = smem_u32(&Bs[buf][krow][ncol]);
                unsigned r0, r1, r2, r3;
                asm volatile(
                    "ldmatrix.sync.aligned.m8n8.x4.trans.shared.b16 {%0,%1,%2,%3}, [%4];"
                    : "=r"(r0), "=r"(r1), "=r"(r2), "=r"(r3) : "r"(addr));
                b[2 * p][0] = r0; b[2 * p][1] = r1;
                b[2 * p + 1][0] = r2; b[2 * p + 1][1] = r3;
            }
            #pragma unroll
            for (int mi = 0; mi < MI; mi++)
                #pragma unroll
                for (int ni = 0; ni < 4; ni++) {
                    asm volatile(
                        "mma.sync.aligned.m16n8k16.row.col.f32.f16.f16.f32 "
                        "{%0,%1,%2,%3}, {%4,%5,%6,%7}, {%8,%9}, {%0,%1,%2,%3};"
                        : "+f"(acc[mi][ni][0]), "+f"(acc[mi][ni][1]),
                          "+f"(acc[mi][ni][2]), "+f"(acc[mi][ni][3])
                        : "r"(a[mi][0]), "r"(a[mi][1]), "r"(a[mi][2]), "r"(a[mi][3]),
                          "r"(b[ni][0]), "r"(b[ni][1]));
                }
        }
        buf ^= 1;
    }
    #pragma unroll
    for (int mi = 0; mi < MI; mi++) {
        int mrow = m0 + wm * (BM / 2) + mi * 16 + g;
        #pragma unroll
        for (int ni = 0; ni < 4; ni++) {
            int ncol = n0 + wn * 32 + ni * 8 + 2 * t;
            #pragma unroll
            for (int half = 0; half < 2; half++) {
                int row = mrow + half * 8;
                __half2 h = __floats2half2_rn(acc[mi][ni][half * 2 + 0],
                                              acc[mi][ni][half * 2 + 1]);
                *(__half2*)&C[(size_t)row * N + ncol] = h;
            }
        }
    }
}

// ---------------- fused edge attention v3: warp/query, prefetched idx, 4-wide ----
__global__ void __launch_bounds__(256)
k_attn(const int* __restrict__ sidx, const float* __restrict__ log_tau) {
    int warp = (blockIdx.x * blockDim.x + threadIdx.x) >> 5;
    int lane = threadIdx.x & 31;
    if (warp >= NQ) return;
    int q = warp;
    int st = g_rowptr[q], en = g_rowptr[q + 1];
    float scale = 0.17677669529663689f * expf(-log_tau[0]);

    float qv[8];
    unpack8(((const uint4*)(g_Qf_h + (size_t)q * DD))[lane], qv);

    const uint4* Kf = (const uint4*)g_Kf_h;
    const uint4* Vf = (const uint4*)g_Vf_h;

    float m = 0.0f;   // reference: smax = max(0, segment max)
    float ssum = 0.0f;
    float a[8] = {0.f, 0.f, 0.f, 0.f, 0.f, 0.f, 0.f, 0.f};

    for (int base = st; base < en; base += 32) {
        int n = min(32, en - base);
        // one coalesced load of up to 32 edge indices for this warp
        int myidx = (lane < n) ? sidx[base + lane] : 0;
        int i = 0;
        for (; i + 4 <= n; i += 4) {
            int s0 = __shfl_sync(0xffffffffu, myidx, i + 0);
            int s1 = __shfl_sync(0xffffffffu, myidx, i + 1);
            int s2 = __shfl_sync(0xffffffffu, myidx, i + 2);
            int s3 = __shfl_sync(0xffffffffu, myidx, i + 3);
            // issue all 8 row loads before any use (MLP=8)
            uint4 k0 = Kf[(size_t)s0 * 32 + lane];
            uint4 k1 = Kf[(size_t)s1 * 32 + lane];
            uint4 k2 = Kf[(size_t)s2 * 32 + lane];
            uint4 k3 = Kf[(size_t)s3 * 32 + lane];
            uint4 v0 = Vf[(size_t)s0 * 32 + lane];
            uint4 v1 = Vf[(size_t)s1 * 32 + lane];
            uint4 v2 = Vf[(size_t)s2 * 32 + lane];
            uint4 v3 = Vf[(size_t)s3 * 32 + lane];
            float d0 = dot8(qv, k0);
            float d1 = dot8(qv, k1);
            float d2 = dot8(qv, k2);
            float d3 = dot8(qv, k3);
            d0 += __shfl_xor_sync(0xffffffffu, d0, 1);
            d0 += __shfl_xor_sync(0xffffffffu, d0, 2);
            d1 += __shfl_xor_sync(0xffffffffu, d1, 1);
            d1 += __shfl_xor_sync(0xffffffffu, d1, 2);
            d2 += __shfl_xor_sync(0xffffffffu, d2, 1);
            d2 += __shfl_xor_sync(0xffffffffu, d2, 2);
            d3 += __shfl_xor_sync(0xffffffffu, d3, 1);
            d3 += __shfl_xor_sync(0xffffffffu, d3, 2);
            d0 *= scale; d1 *= scale; d2 *= scale; d3 *= scale;
            float mn = fmaxf(m, fmaxf(fmaxf(d0, d1), fmaxf(d2, d3)));
            float c  = __expf(m - mn);
            float r0 = __expf(d0 - mn);
            float r1 = __expf(d1 - mn);
            float r2 = __expf(d2 - mn);
            float r3 = __expf(d3 - mn);
            float vv0[8], vv1[8], vv2[8], vv3[8];
            unpack8(v0, vv0); unpack8(v1, vv1);
            unpack8(v2, vv2); unpack8(v3, vv3);
            #pragma unroll
            for (int j = 0; j < 8; j++)
                a[j] = a[j] * c + r0 * vv0[j] + r1 * vv1[j] + r2 * vv2[j] + r3 * vv3[j];
            ssum = ssum * c + r0 + r1 + r2 + r3;
            m = mn;
        }
        for (; i < n; i++) {
            int s = __shfl_sync(0xffffffffu, myidx, i);
            uint4 ku = Kf[(size_t)s * 32 + lane];
            uint4 vu = Vf[(size_t)s * 32 + lane];
            float d = dot8(qv, ku);
            d += __shfl_xor_sync(0xffffffffu, d, 1);
            d += __shfl_xor_sync(0xffffffffu, d, 2);
            d *= scale;
            float mn = fmaxf(m, d);
            float c = __expf(m - mn);
            float r = __expf(d - mn);
            float vv[8];
            unpack8(vu, vv);
            #pragma unroll
            for (int j = 0; j < 8; j++) a[j] = a[j] * c + r * vv[j];
            ssum = ssum * c + r;
            m = mn;
        }
    }

    float inv = 1.0f / fmaxf(ssum, 1e-8f);
    float gsc = ssum * inv;
    float gv[8];
    unpack8(((const uint4*)(g_Gf_h + (size_t)q * DD))[lane], gv);
    float o[8];
    #pragma unroll
    for (int j = 0; j < 8; j++) o[j] = a[j] * inv + gv[j] * gsc;
    __half2 h0 = __floats2half2_rn(o[0], o[1]);
    __half2 h1 = __floats2half2_rn(o[2], o[3]);
    __half2 h2 = __floats2half2_rn(o[4], o[5]);
    __half2 h3 = __floats2half2_rn(o[6], o[7]);
    uint4 u;
    u.x = *(unsigned*)&h0; u.y = *(unsigned*)&h1;
    u.z = *(unsigned*)&h2; u.w = *(unsigned*)&h3;
    ((uint4*)(g_out_h + (size_t)q * DD))[lane] = u;
}

// ---------------- host ----------------
template <typename T>
static T* symp(const void* sym) {
    void* p = nullptr;
    cudaGetSymbolAddress(&p, sym);
    return (T*)p;
}

#define SMEM_H(BM) ((2 * (BM) * 40 + 2 * 32 * 136) * (int)sizeof(__half))
#define SMEM_KVF (2 * 64 * 36 * 4 + 64 * 40 * 2 + 2 * 32 * 136 * 2)

struct Ctx {
    cudaStream_t s1, s2;
    cudaEvent_t evRoot, evKV, evG;
    Ctx() {
        cudaStreamCreateWithFlags(&s1, cudaStreamNonBlocking);
        cudaStreamCreateWithFlags(&s2, cudaStreamNonBlocking);
        cudaEventCreateWithFlags(&evRoot, cudaEventDisableTiming);
        cudaEventCreateWithFlags(&evKV, cudaEventDisableTiming);
        cudaEventCreateWithFlags(&evG, cudaEventDisableTiming);
        cudaFuncSetAttribute((const void*)k_hgemm_kvf,
            cudaFuncAttributeMaxDynamicSharedMemorySize, SMEM_KVF);
        cudaFuncSetAttribute((const void*)k_hgemm<64, false, false, false, true>,
            cudaFuncAttributeMaxDynamicSharedMemorySize, SMEM_H(64));
        cudaFuncSetAttribute((const void*)k_hgemm<64, true, true, false, true>,
            cudaFuncAttributeMaxDynamicSharedMemorySize, SMEM_H(64));
        cudaFuncSetAttribute((const void*)k_hgemm<64, true, false, true, false>,
            cudaFuncAttributeMaxDynamicSharedMemorySize, SMEM_H(64));
    }
};

extern "C" void kernel_launch(void* const* d_in, const int* in_sizes, int n_in,
                              void* d_out, int out_size) {
    const float* query_tokens  = (const float*)d_in[0];
    const float* query_pos     = (const float*)d_in[1];
    const float* support_feats = (const float*)d_in[2];
    const float* support_pos   = (const float*)d_in[3];
    const float* Wq   = (const float*)d_in[4];
    const float* Wk   = (const float*)d_in[5];
    const float* Wv   = (const float*)d_in[6];
    const float* Wg   = (const float*)d_in[7];
    const float* Wo   = (const float*)d_in[8];
    const float* bo   = (const float*)d_in[9];
    const float* log_tau = (const float*)d_in[10];
    const float* ln1_g = (const float*)d_in[11];
    const float* ln1_b = (const float*)d_in[12];
    const float* ln2_g = (const float*)d_in[13];
    const float* ln2_b = (const float*)d_in[14];
    const float* Wf1  = (const float*)d_in[15];
    const float* bf1  = (const float*)d_in[16];
    const float* Wf2  = (const float*)d_in[17];
    const float* bf2  = (const float*)d_in[18];
    const float* Gw1  = (const float*)d_in[19];
    const float* Gb1  = (const float*)d_in[20];
    const float* Gw2  = (const float*)d_in[21];
    const float* Gb2  = (const float*)d_in[22];
    const int* q_idx  = (const int*)d_in[23];
    const int* s_idx  = (const int*)d_in[24];
    float* out = (float*)d_out;

    float*  p_raw   = symp<float>(g_raw);
    float*  p_x     = symp<float>(g_x);
    __half* p_qt    = symp<__half>(g_qt_h);
    __half* p_geoh  = symp<__half>(g_geoh_h);
    __half* p_geo   = symp<__half>(g_geo_h);
    __half* p_Qf    = symp<__half>(g_Qf_h);
    __half* p_Kf    = symp<__half>(g_Kf_h);
    __half* p_Vf    = symp<__half>(g_Vf_h);
    __half* p_Gf    = symp<__half>(g_Gf_h);
    __half* p_outh  = symp<__half>(g_out_h);
    __half* p_h1    = symp<__half>(g_h1_h);
    __half* p_Wq    = symp<__half>(g_Wq_h);
    __half* p_Wk    = symp<__half>(g_Wk_h);
    __half* p_Wv    = symp<__half>(g_Wv_h);
    __half* p_Wg    = symp<__half>(g_Wg_h);
    __half* p_Wo    = symp<__half>(g_Wo_h);
    __half* p_Wf1   = symp<__half>(g_Wf1_h);
    __half* p_Wf2   = symp<__half>(g_Wf2_h);
    __half* p_Gw2   = symp<__half>(g_Gw2_h);

    static Ctx ctx;

    // all weight converts in one launch, pre-fork
    CvtJobs jobs;
    jobs.src[0] = Wq;  jobs.dst[0] = p_Wq;  jobs.n4[0] = DD * DD / 4;
    jobs.src[1] = Wk;  jobs.dst[1] = p_Wk;  jobs.n4[1] = DD * DD / 4;
    jobs.src[2] = Wv;  jobs.dst[2] = p_Wv;  jobs.n4[2] = DD * DD / 4;
    jobs.src[3] = Wo;  jobs.dst[3] = p_Wo;  jobs.n4[3] = DD * DD / 4;
    jobs.src[4] = Wg;  jobs.dst[4] = p_Wg;  jobs.n4[4] = NGEO * DD / 4;
    jobs.src[5] = Gw2; jobs.dst[5] = p_Gw2; jobs.n4[5] = NGEO * NGEO / 4;
    jobs.src[6] = Wf1; jobs.dst[6] = p_Wf1; jobs.n4[6] = DD * NFFN / 4;
    jobs.src[7] = Wf2; jobs.dst[7] = p_Wf2; jobs.n4[7] = NFFN * DD / 4;
    k_cvt_all<<<dim3(DD * NFFN / 4 / 256, 8), 256>>>(jobs);

    // fork
    cudaEventRecord(ctx.evRoot, 0);
    cudaStreamWaitEvent(ctx.s1, ctx.evRoot, 0);
    cudaStreamWaitEvent(ctx.s2, ctx.evRoot, 0);

    // s1: merged K/V projection (A converted in-kernel)
    k_hgemm_kvf<<<dim3(DD / 128, NS / 64, 2), 256, SMEM_KVF, ctx.s1>>>(
        support_feats, p_Wk, p_Wv, p_Kf, p_Vf, DD, DD);
    cudaEventRecord(ctx.evKV, ctx.s1);

    // s2: geo chain
    k_bounds<<<NE / 256, 256, 0, ctx.s2>>>(q_idx);
    k_geostats<<<NQ / 8, 256, 0, ctx.s2>>>(query_pos, support_pos, s_idx);
    k_gemm12<<<dim3(NGEO / 64, NQ / 64), 256, 0, ctx.s2>>>(
        p_raw, Gw1, Gb1, p_geoh, NQ, NGEO, 12);
    k_hgemm<64, true, true, false, true><<<dim3(NGEO / 128, NQ / 64), 256, SMEM_H(64), ctx.s2>>>(
        p_geoh, p_Gw2, Gb2, nullptr, p_geo, NGEO, NGEO);
    k_hgemm<64, false, false, false, true><<<dim3(DD / 128, NQ / 64), 256, SMEM_H(64), ctx.s2>>>(
        p_geo, p_Wg, nullptr, nullptr, p_Gf, DD, NGEO);
    cudaEventRecord(ctx.evG, ctx.s2);

    // s0 (default): query chain
    k_ln<<<NQ / 8, 256>>>(query_tokens, ln1_g, ln1_b, p_qt);
    k_hgemm<64, false, false, false, true><<<dim3(DD / 128, NQ / 64), 256, SMEM_H(64)>>>(
        p_qt, p_Wq, nullptr, nullptr, p_Qf, DD, DD);

    // join, fused edge attention
    cudaStreamWaitEvent(0, ctx.evKV, 0);
    cudaStreamWaitEvent(0, ctx.evG, 0);
    k_attn<<<NQ / 8, 256>>>(s_idx, log_tau);

    // tail
    k_hgemm<64, true, false, true, false><<<dim3(DD / 128, NQ / 64), 256, SMEM_H(64)>>>(
        p_outh, p_Wo, bo, query_tokens, p_x, DD, DD);
    k_ln<<<NQ / 8, 256>>>(p_x, ln2_g, ln2_b, p_qt);
    k_hgemm<64, true, true, false, true><<<dim3(NFFN / 128, NQ / 64), 256, SMEM_H(64)>>>(
        p_qt, p_Wf1, bf1, nullptr, p_h1, NFFN, DD);
    k_hgemm<64, true, false, true, false><<<dim3(DD / 128, NQ / 64), 256, SMEM_H(64)>>>(
        p_h1, p_Wf2, bf2, p_x, out, DD, NFFN);
}

// round 11
// speedup vs baseline: 5.0441x; 1.0280x over previous
#include <cuda_runtime.h>
#include <cuda_fp16.h>
#include <math.h>

#define NQ 8192
#define NS 32768
#define NE 131072
#define DD 256
#define NH 8
#define HDIM 32
#define NGEO 128
#define NFFN 512

// ---------------- scratch (device globals; no allocation) ----------------
__device__ float  g_raw[NQ * 12];
__device__ float  g_x[NQ * DD];
__device__ int    g_rowptr[NQ + 1];

// half activations / weights
__device__ __half g_qt_h[NQ * DD];
__device__ __half g_geoh_h[NQ * NGEO];
__device__ __half g_geo_h[NQ * NGEO];
__device__ __half g_Qf_h[NQ * DD];
__device__ __half g_Kf_h[NS * DD];
__device__ __half g_Vf_h[NS * DD];
__device__ __half g_Gf_h[NQ * DD];
__device__ __half g_out_h[NQ * DD];
__device__ __half g_h1_h[NQ * NFFN];
__device__ __half g_Wq_h[DD * DD];
__device__ __half g_Wk_h[DD * DD];
__device__ __half g_Wv_h[DD * DD];
__device__ __half g_Wg_h[NGEO * DD];
__device__ __half g_Wo_h[DD * DD];
__device__ __half g_Wf1_h[DD * NFFN];
__device__ __half g_Wf2_h[NFFN * DD];
__device__ __half g_Gw2_h[NGEO * NGEO];

__device__ __forceinline__ float gelu_f(float x) {
    return 0.5f * x * (1.0f + erff(x * 0.7071067811865475f));
}

__device__ __forceinline__ void cpa16(void* dst, const void* src) {
    unsigned d = (unsigned)__cvta_generic_to_shared(dst);
    asm volatile("cp.async.cg.shared.global [%0], [%1], 16;" :: "r"(d), "l"(src));
}
__device__ __forceinline__ unsigned smem_u32(const void* p) {
    return (unsigned)__cvta_generic_to_shared(p);
}
__device__ __forceinline__ void unpack8(uint4 u, float* f) {
    float2 a = __half22float2(*(const __half2*)&u.x);
    float2 b = __half22float2(*(const __half2*)&u.y);
    float2 c = __half22float2(*(const __half2*)&u.z);
    float2 d = __half22float2(*(const __half2*)&u.w);
    f[0] = a.x; f[1] = a.y; f[2] = b.x; f[3] = b.y;
    f[4] = c.x; f[5] = c.y; f[6] = d.x; f[7] = d.y;
}
__device__ __forceinline__ float dot8(const float* q, uint4 u) {
    float k[8];
    unpack8(u, k);
    float d = 0.f;
    #pragma unroll
    for (int j = 0; j < 8; j++) d += q[j] * k[j];
    return d;
}

// ---------------- fused fp32 -> fp16 weight converts ----------------
struct CvtJobs {
    const float* src[8];
    __half* dst[8];
    int n4[8];
};
__global__ void k_cvt_all(CvtJobs j) {
    int w = blockIdx.y;
    int i = blockIdx.x * blockDim.x + threadIdx.x;
    if (i >= j.n4[w]) return;
    float4 v = ((const float4*)j.src[w])[i];
    __half2 h0 = __floats2half2_rn(v.x, v.y);
    __half2 h1 = __floats2half2_rn(v.z, v.w);
    uint2 u;
    u.x = *(unsigned*)&h0;
    u.y = *(unsigned*)&h1;
    ((uint2*)j.dst[w])[i] = u;
}

// ---------------- row_ptr via boundary scan (q_idx sorted) ----------------
__global__ void k_bounds(const int* __restrict__ qidx) {
    int e = blockIdx.x * blockDim.x + threadIdx.x;
    if (e >= NE) return;
    int v = qidx[e];
    int prev = (e == 0) ? -1 : qidx[e - 1];
    for (int q = prev + 1; q <= v; q++) g_rowptr[q] = e;
    if (e == NE - 1) {
        for (int q = v + 1; q <= NQ; q++) g_rowptr[q] = NE;
    }
}

// ---------------- geo stats: warp per query ----------------
__global__ void k_geostats(const float* __restrict__ qpos,
                           const float* __restrict__ spos,
                           const int* __restrict__ sidx) {
    int warp = (blockIdx.x * blockDim.x + threadIdx.x) >> 5;
    int lane = threadIdx.x & 31;
    if (warp >= NQ) return;
    int q = warp;
    int st = g_rowptr[q], en = g_rowptr[q + 1];
    float qp0 = qpos[q * 3 + 0], qp1 = qpos[q * 3 + 1], qp2 = qpos[q * 3 + 2];
    float s0 = 0.f, s1 = 0.f, s2 = 0.f;
    float ss0 = 0.f, ss1 = 0.f, ss2 = 0.f;
    float mn0 = 1e30f, mn1 = 1e30f, mn2 = 1e30f;
    float mx0 = -1e30f, mx1 = -1e30f, mx2 = -1e30f;
    for (int e = st + lane; e < en; e += 32) {
        int s = sidx[e];
        float r0 = spos[s * 3 + 0] - qp0;
        float r1 = spos[s * 3 + 1] - qp1;
        float r2 = spos[s * 3 + 2] - qp2;
        s0 += r0; s1 += r1; s2 += r2;
        ss0 += r0 * r0; ss1 += r1 * r1; ss2 += r2 * r2;
        mn0 = fminf(mn0, r0); mn1 = fminf(mn1, r1); mn2 = fminf(mn2, r2);
        mx0 = fmaxf(mx0, r0); mx1 = fmaxf(mx1, r1); mx2 = fmaxf(mx2, r2);
    }
    #pragma unroll
    for (int off = 16; off > 0; off >>= 1) {
        s0 += __shfl_xor_sync(0xffffffffu, s0, off);
        s1 += __shfl_xor_sync(0xffffffffu, s1, off);
        s2 += __shfl_xor_sync(0xffffffffu, s2, off);
        ss0 += __shfl_xor_sync(0xffffffffu, ss0, off);
        ss1 += __shfl_xor_sync(0xffffffffu, ss1, off);
        ss2 += __shfl_xor_sync(0xffffffffu, ss2, off);
        mn0 = fminf(mn0, __shfl_xor_sync(0xffffffffu, mn0, off));
        mn1 = fminf(mn1, __shfl_xor_sync(0xffffffffu, mn1, off));
        mn2 = fminf(mn2, __shfl_xor_sync(0xffffffffu, mn2, off));
        mx0 = fmaxf(mx0, __shfl_xor_sync(0xffffffffu, mx0, off));
        mx1 = fmaxf(mx1, __shfl_xor_sync(0xffffffffu, mx1, off));
        mx2 = fmaxf(mx2, __shfl_xor_sync(0xffffffffu, mx2, off));
    }
    if (lane == 0) {
        float cnt = fmaxf((float)(en - st), 1.0f);
        float m0 = s0 / cnt, m1 = s1 / cnt, m2 = s2 / cnt;
        float v0 = fmaxf(ss0 / cnt - m0 * m0, 0.f);
        float v1 = fmaxf(ss1 / cnt - m1 * m1, 0.f);
        float v2 = fmaxf(ss2 / cnt - m2 * m2, 0.f);
        float* r = g_raw + q * 12;
        r[0] = m0; r[1] = m1; r[2] = m2;
        r[3] = sqrtf(v0); r[4] = sqrtf(v1); r[5] = sqrtf(v2);
        r[6] = fminf(fmaxf(mn0, -100.f), 100.f);
        r[7] = fminf(fmaxf(mn1, -100.f), 100.f);
        r[8] = fminf(fmaxf(mn2, -100.f), 100.f);
        r[9]  = fminf(fmaxf(mx0, -100.f), 100.f);
        r[10] = fminf(fmaxf(mx1, -100.f), 100.f);
        r[11] = fminf(fmaxf(mx2, -100.f), 100.f);
    }
}

// ---------------- LayerNorm: warp per row, fp32 in, fp16 out ----------------
__global__ void k_ln(const float* __restrict__ x, const float* __restrict__ g,
                     const float* __restrict__ b, __half* __restrict__ y) {
    int warp = (blockIdx.x * blockDim.x + threadIdx.x) >> 5;
    int lane = threadIdx.x & 31;
    if (warp >= NQ) return;
    const float4* xr = (const float4*)(x + warp * DD);
    float4 a = xr[lane * 2], c = xr[lane * 2 + 1];
    float sum = a.x + a.y + a.z + a.w + c.x + c.y + c.z + c.w;
    float ss = a.x * a.x + a.y * a.y + a.z * a.z + a.w * a.w +
               c.x * c.x + c.y * c.y + c.z * c.z + c.w * c.w;
    #pragma unroll
    for (int off = 16; off > 0; off >>= 1) {
        sum += __shfl_xor_sync(0xffffffffu, sum, off);
        ss  += __shfl_xor_sync(0xffffffffu, ss, off);
    }
    float mean = sum * (1.0f / 256.0f);
    float var = ss * (1.0f / 256.0f) - mean * mean;
    float rstd = rsqrtf(var + 1e-5f);
    const float4* gr = (const float4*)g;
    const float4* br = (const float4*)b;
    float4 g0 = gr[lane * 2], g1 = gr[lane * 2 + 1];
    float4 b0 = br[lane * 2], b1 = br[lane * 2 + 1];
    float o[8];
    o[0] = (a.x - mean) * rstd * g0.x + b0.x;
    o[1] = (a.y - mean) * rstd * g0.y + b0.y;
    o[2] = (a.z - mean) * rstd * g0.z + b0.z;
    o[3] = (a.w - mean) * rstd * g0.w + b0.w;
    o[4] = (c.x - mean) * rstd * g1.x + b1.x;
    o[5] = (c.y - mean) * rstd * g1.y + b1.y;
    o[6] = (c.z - mean) * rstd * g1.z + b1.z;
    o[7] = (c.w - mean) * rstd * g1.w + b1.w;
    __half2 h0 = __floats2half2_rn(o[0], o[1]);
    __half2 h1 = __floats2half2_rn(o[2], o[3]);
    __half2 h2 = __floats2half2_rn(o[4], o[5]);
    __half2 h3 = __floats2half2_rn(o[6], o[7]);
    uint4 u;
    u.x = *(unsigned*)&h0; u.y = *(unsigned*)&h1;
    u.z = *(unsigned*)&h2; u.w = *(unsigned*)&h3;
    ((uint4*)(y + (size_t)warp * DD))[lane] = u;
}

// ---------------- fp32 GEMM (K=12 geo1), half output ----------------
__global__ void k_gemm12(const float* __restrict__ A, const float* __restrict__ B,
                         const float* __restrict__ bias, __half* __restrict__ C,
                         int M, int N, int K) {
    __shared__ float As[64][17];
    __shared__ float Bs[16][64];
    int tid = threadIdx.x;
    int tx = tid & 15, ty = tid >> 4;
    int m0 = blockIdx.y * 64, n0 = blockIdx.x * 64;
    float acc[4][4] = {};
    int KT = (K + 15) >> 4;
    for (int kt = 0; kt < KT; kt++) {
        int k0 = kt << 4;
        #pragma unroll
        for (int i = 0; i < 4; i++) {
            int lin = tid + i * 256;
            int ar = lin >> 4, ac = lin & 15;
            int gk = k0 + ac;
            As[ar][ac] = (gk < K) ? A[(size_t)(m0 + ar) * K + gk] : 0.f;
        }
        #pragma unroll
        for (int i = 0; i < 4; i++) {
            int lin = tid + i * 256;
            int br = lin >> 6, bc = lin & 63;
            int gk = k0 + br;
            Bs[br][bc] = (gk < K) ? B[(size_t)gk * N + n0 + bc] : 0.f;
        }
        __syncthreads();
        #pragma unroll
        for (int kk = 0; kk < 16; kk++) {
            float av[4];
            #pragma unroll
            for (int i = 0; i < 4; i++) av[i] = As[ty * 4 + i][kk];
            float4 bv = *(const float4*)&Bs[kk][tx * 4];
            float bvv[4] = {bv.x, bv.y, bv.z, bv.w};
            #pragma unroll
            for (int i = 0; i < 4; i++)
                #pragma unroll
                for (int j = 0; j < 4; j++)
                    acc[i][j] = fmaf(av[i], bvv[j], acc[i][j]);
        }
        __syncthreads();
    }
    #pragma unroll
    for (int i = 0; i < 4; i++) {
        int row = m0 + ty * 4 + i;
        #pragma unroll
        for (int j = 0; j < 4; j++) {
            int col = n0 + tx * 4 + j;
            float v = acc[i][j] + bias[col];
            v = gelu_f(v);
            C[(size_t)row * N + col] = __float2half_rn(v);
        }
    }
}

// ---------------- FP16 tensor-core GEMM, BK=64, cp.async 2-stage ----------------
// A[M,K], B[K,N] half; K%64==0, N%128==0, M%BM==0.
// 8 warps (2m x 4n); warp tile (BM/2)x32; 4 mma k-groups per barrier pair.
template <int BM, bool BIAS, bool GELU, bool RES, bool HOUT>
__device__ __forceinline__ void hgemm_body(
    const __half* __restrict__ A, const __half* __restrict__ B,
    const float* __restrict__ bias, const float* __restrict__ res,
    void* __restrict__ Cv, int N, int K, int m0, int n0) {
    constexpr int SA = 72, SB = 136;  // halves per row (pads: 72,136 -> stride mod 32 words == 4)
    constexpr int MI = BM / 32;
    extern __shared__ __half smem[];
    __half (*As)[BM][SA] = reinterpret_cast<__half(*)[BM][SA]>(smem);
    __half (*Bs)[64][SB] = reinterpret_cast<__half(*)[64][SB]>(smem + 2 * BM * SA);

    int tid = threadIdx.x;
    int warp = tid >> 5, lane = tid & 31;
    int wm = warp & 1, wn = warp >> 1;
    int g = lane >> 2, t = lane & 3;

    float acc[MI][4][4];
    #pragma unroll
    for (int i = 0; i < MI; i++)
        #pragma unroll
        for (int j = 0; j < 4; j++)
            #pragma unroll
            for (int c = 0; c < 4; c++) acc[i][j][c] = 0.f;

    int KT = K >> 6;
    // stage loads: A BM x 64 halves (BM*8 chunks); B 64 x 128 halves (1024 chunks)
    #pragma unroll
    for (int i = 0; i < BM / 32; i++) {
        int lin = tid + i * 256;
        int row = lin >> 3, col = (lin & 7) * 8;
        cpa16(&As[0][row][col], &A[(size_t)(m0 + row) * K + col]);
    }
    #pragma unroll
    for (int i = 0; i < 4; i++) {
        int lin = tid + i * 256;
        int row = lin >> 4, col = (lin & 15) * 8;
        cpa16(&Bs[0][row][col], &B[(size_t)row * N + n0 + col]);
    }
    asm volatile("cp.async.commit_group;");

    int buf = 0;
    for (int kt = 0; kt < KT; kt++) {
        if (kt + 1 < KT) {
            int k0 = (kt + 1) << 6;
            #pragma unroll
            for (int i = 0; i < BM / 32; i++) {
                int lin = tid + i * 256;
                int row = lin >> 3, col = (lin & 7) * 8;
                cpa16(&As[buf ^ 1][row][col], &A[(size_t)(m0 + row) * K + k0 + col]);
            }
            #pragma unroll
            for (int i = 0; i < 4; i++) {
                int lin = tid + i * 256;
                int row = lin >> 4, col = (lin & 15) * 8;
                cpa16(&Bs[buf ^ 1][row][col], &B[(size_t)(k0 + row) * N + n0 + col]);
            }
            asm volatile("cp.async.commit_group;");
            asm volatile("cp.async.wait_group 1;");
        } else {
            asm volatile("cp.async.wait_group 0;");
        }
        __syncthreads();
        #pragma unroll
        for (int ks = 0; ks < 64; ks += 16) {
            unsigned a[MI][4], b[4][2];
            #pragma unroll
            for (int mi = 0; mi < MI; mi++) {
                int row = wm * (BM / 2) + mi * 16 + (lane & 7) + ((lane >> 3) & 1) * 8;
                int col = ks + (lane >> 4) * 8;
                unsigned addr = smem_u32(&As[buf][row][col]);
                asm volatile(
                    "ldmatrix.sync.aligned.m8n8.x4.shared.b16 {%0,%1,%2,%3}, [%4];"
                    : "=r"(a[mi][0]), "=r"(a[mi][1]), "=r"(a[mi][2]), "=r"(a[mi][3])
                    : "r"(addr));
            }
            #pragma unroll
            for (int p = 0; p < 2; p++) {
                int krow = ks + (lane & 7) + ((lane >> 3) & 1) * 8;
                int ncol = wn * 32 + p * 16 + (lane >> 4) * 8;
                unsigned addr = smem_u32(&Bs[buf][krow][ncol]);
                unsigned r0, r1, r2, r3;
                asm volatile(
                    "ldmatrix.sync.aligned.m8n8.x4.trans.shared.b16 {%0,%1,%2,%3}, [%4];"
                    : "=r"(r0), "=r"(r1), "=r"(r2), "=r"(r3) : "r"(addr));
                b[2 * p][0] = r0; b[2 * p][1] = r1;
                b[2 * p + 1][0] = r2; b[2 * p + 1][1] = r3;
            }
            #pragma unroll
            for (int mi = 0; mi < MI; mi++)
                #pragma unroll
                for (int ni = 0; ni < 4; ni++) {
                    asm volatile(
                        "mma.sync.aligned.m16n8k16.row.col.f32.f16.f16.f32 "
                        "{%0,%1,%2,%3}, {%4,%5,%6,%7}, {%8,%9}, {%0,%1,%2,%3};"
                        : "+f"(acc[mi][ni][0]), "+f"(acc[mi][ni][1]),
                          "+f"(acc[mi][ni][2]), "+f"(acc[mi][ni][3])
                        : "r"(a[mi][0]), "r"(a[mi][1]), "r"(a[mi][2]), "r"(a[mi][3]),
                          "r"(b[ni][0]), "r"(b[ni][1]));
                }
        }
        buf ^= 1;
        __syncthreads();
    }
    #pragma unroll
    for (int mi = 0; mi < MI; mi++) {
        int mrow = m0 + wm * (BM / 2) + mi * 16 + g;
        #pragma unroll
        for (int ni = 0; ni < 4; ni++) {
            int ncol = n0 + wn * 32 + ni * 8 + 2 * t;
            #pragma unroll
            for (int half = 0; half < 2; half++) {
                int row = mrow + half * 8;
                float v0 = acc[mi][ni][half * 2 + 0];
                float v1 = acc[mi][ni][half * 2 + 1];
                if (BIAS) { v0 += bias[ncol]; v1 += bias[ncol + 1]; }
                if (GELU) { v0 = gelu_f(v0); v1 = gelu_f(v1); }
                if (RES) {
                    const float2 r = *(const float2*)&res[(size_t)row * N + ncol];
                    v0 += r.x; v1 += r.y;
                }
                if (HOUT) {
                    __half2 h = __floats2half2_rn(v0, v1);
                    *(__half2*)&((__half*)Cv)[(size_t)row * N + ncol] = h;
                } else {
                    float2 o; o.x = v0; o.y = v1;
                    *(float2*)&((float*)Cv)[(size_t)row * N + ncol] = o;
                }
            }
        }
    }
}

template <int BM, bool BIAS, bool GELU, bool RES, bool HOUT>
__global__ __launch_bounds__(256, 2)
void k_hgemm(const __half* __restrict__ A, const __half* __restrict__ B,
             const float* __restrict__ bias, const float* __restrict__ res,
             void* __restrict__ C, int N, int K) {
    hgemm_body<BM, BIAS, GELU, RES, HOUT>(A, B, bias, res, C, N, K,
                                          blockIdx.y * BM, blockIdx.x * 128);
}

// ---------------- KV projection with in-kernel fp32->fp16 A convert, BK=32 ------
__global__ __launch_bounds__(256, 2)
void k_hgemm_kvf(const float* __restrict__ A,
                 const __half* __restrict__ B0, const __half* __restrict__ B1,
                 __half* __restrict__ C0, __half* __restrict__ C1, int N, int K) {
    constexpr int BM = 64, SA32 = 36, SA = 40, SB = 136, MI = 2;
    extern __shared__ __align__(16) char smraw[];
    float  (*A32)[BM][SA32] = reinterpret_cast<float(*)[BM][SA32]>(smraw);
    __half (*A16)[SA]       = reinterpret_cast<__half(*)[SA]>(smraw + 2 * BM * SA32 * 4);
    __half (*Bs)[32][SB]    = reinterpret_cast<__half(*)[32][SB]>(
                                  smraw + 2 * BM * SA32 * 4 + BM * SA * 2);
    const __half* B = blockIdx.z ? B1 : B0;
    __half* C = blockIdx.z ? C1 : C0;
    int m0 = blockIdx.y * BM, n0 = blockIdx.x * 128;

    int tid = threadIdx.x;
    int warp = tid >> 5, lane = tid & 31;
    int wm = warp & 1, wn = warp >> 1;
    int g = lane >> 2, t = lane & 3;

    float acc[MI][4][4];
    #pragma unroll
    for (int i = 0; i < MI; i++)
        #pragma unroll
        for (int j = 0; j < 4; j++)
            #pragma unroll
            for (int c = 0; c < 4; c++) acc[i][j][c] = 0.f;

    int KT = K >> 5;
    #pragma unroll
    for (int i = 0; i < 2; i++) {
        int lin = tid + i * 256;
        int row = lin >> 3, colq = (lin & 7) * 4;
        cpa16(&A32[0][row][colq], &A[(size_t)(m0 + row) * K + colq]);
    }
    #pragma unroll
    for (int i = 0; i < 2; i++) {
        int lin = tid + i * 256;
        int row = lin >> 4, col = (lin & 15) * 8;
        cpa16(&Bs[0][row][col], &B[(size_t)row * N + n0 + col]);
    }
    asm volatile("cp.async.commit_group;");

    int buf = 0;
    for (int kt = 0; kt < KT; kt++) {
        if (kt + 1 < KT) {
            int k0 = (kt + 1) << 5;
            #pragma unroll
            for (int i = 0; i < 2; i++) {
                int lin = tid + i * 256;
                int row = lin >> 3, colq = (lin & 7) * 4;
                cpa16(&A32[buf ^ 1][row][colq], &A[(size_t)(m0 + row) * K + k0 + colq]);
            }
            #pragma unroll
            for (int i = 0; i < 2; i++) {
                int lin = tid + i * 256;
                int row = lin >> 4, col = (lin & 15) * 8;
                cpa16(&Bs[buf ^ 1][row][col], &B[(size_t)(k0 + row) * N + n0 + col]);
            }
            asm volatile("cp.async.commit_group;");
            asm volatile("cp.async.wait_group 1;");
        } else {
            asm volatile("cp.async.wait_group 0;");
        }
        __syncthreads();
        {
            int row = tid >> 2, c0 = (tid & 3) * 8;
            const float* src = &A32[buf][row][c0];
            float4 f0 = *(const float4*)(src + 0);
            float4 f1 = *(const float4*)(src + 4);
            __half2 h0 = __floats2half2_rn(f0.x, f0.y);
            __half2 h1 = __floats2half2_rn(f0.z, f0.w);
            __half2 h2 = __floats2half2_rn(f1.x, f1.y);
            __half2 h3 = __floats2half2_rn(f1.z, f1.w);
            uint4 u;
            u.x = *(unsigned*)&h0; u.y = *(unsigned*)&h1;
            u.z = *(unsigned*)&h2; u.w = *(unsigned*)&h3;
            *(uint4*)&A16[row][c0] = u;
        }
        __syncthreads();
        #pragma unroll
        for (int ks = 0; ks < 32; ks += 16) {
            unsigned a[MI][4], b[4][2];
            #pragma unroll
            for (int mi = 0; mi < MI; mi++) {
                int row = wm * (BM / 2) + mi * 16 + (lane & 7) + ((lane >> 3) & 1) * 8;
                int col = ks + (lane >> 4) * 8;
                unsigned addr = smem_u32(&A16[row][col]);
                asm volatile(
                    "ldmatrix.sync.aligned.m8n8.x4.shared.b16 {%0,%1,%2,%3}, [%4];"
                    : "=r"(a[mi][0]), "=r"(a[mi][1]), "=r"(a[mi][2]), "=r"(a[mi][3])
                    : "r"(addr));
            }
            #pragma unroll
            for (int p = 0; p < 2; p++) {
                int krow = ks + (lane & 7) + ((lane >> 3) & 1) * 8;
                int ncol = wn * 32 + p * 16 + (lane >> 4) * 8;
                unsigned addr = smem_u32(&Bs[buf][krow][ncol]);
                unsigned r0, r1, r2, r3;
                asm volatile(
                    "ldmatrix.sync.aligned.m8n8.x4.trans.shared.b16 {%0,%1,%2,%3}, [%4];"
                    : "=r"(r0), "=r"(r1), "=r"(r2), "=r"(r3) : "r"(addr));
                b[2 * p][0] = r0; b[2 * p][1] = r1;
                b[2 * p + 1][0] = r2; b[2 * p + 1][1] = r3;
            }
            #pragma unroll
            for (int mi = 0; mi < MI; mi++)
                #pragma unroll
                for (int ni = 0; ni < 4; ni++) {
                    asm volatile(
                        "mma.sync.aligned.m16n8k16.row.col.f32.f16.f16.f32 "
                        "{%0,%1,%2,%3}, {%4,%5,%6,%7}, {%8,%9}, {%0,%1,%2,%3};"
                        : "+f"(acc[mi][ni][0]), "+f"(acc[mi][ni][1]),
                          "+f"(acc[mi][ni][2]), "+f"(acc[mi][ni][3])
                        : "r"(a[mi][0]), "r"(a[mi][1]), "r"(a[mi][2]), "r"(a[mi][3]),
                          "r"(b[ni][0]), "r"(b[ni][1]));
                }
        }
        buf ^= 1;
    }
    #pragma unroll
    for (int mi = 0; mi < MI; mi++) {
        int mrow = m0 + wm * (BM / 2) + mi * 16 + g;
        #pragma unroll
        for (int ni = 0; ni < 4; ni++) {
            int ncol = n0 + wn * 32 + ni * 8 + 2 * t;
            #pragma unroll
            for (int half = 0; half < 2; half++) {
                int row = mrow + half * 8;
                __half2 h = __floats2half2_rn(acc[mi][ni][half * 2 + 0],
                                              acc[mi][ni][half * 2 + 1]);
                *(__half2*)&C[(size_t)row * N + ncol] = h;
            }
        }
    }
}

// ---------------- fused edge attention: warp/query, prefetched idx, 4-wide ------
__global__ void __launch_bounds__(256)
k_attn(const int* __restrict__ sidx, const float* __restrict__ log_tau) {
    int warp = (blockIdx.x * blockDim.x + threadIdx.x) >> 5;
    int lane = threadIdx.x & 31;
    if (warp >= NQ) return;
    int q = warp;
    int st = g_rowptr[q], en = g_rowptr[q + 1];
    float scale = 0.17677669529663689f * expf(-log_tau[0]);

    float qv[8];
    unpack8(((const uint4*)(g_Qf_h + (size_t)q * DD))[lane], qv);

    const uint4* Kf = (const uint4*)g_Kf_h;
    const uint4* Vf = (const uint4*)g_Vf_h;

    float m = 0.0f;   // reference: smax = max(0, segment max)
    float ssum = 0.0f;
    float a[8] = {0.f, 0.f, 0.f, 0.f, 0.f, 0.f, 0.f, 0.f};

    for (int base = st; base < en; base += 32) {
        int n = min(32, en - base);
        int myidx = (lane < n) ? sidx[base + lane] : 0;
        int i = 0;
        for (; i + 4 <= n; i += 4) {
            int s0 = __shfl_sync(0xffffffffu, myidx, i + 0);
            int s1 = __shfl_sync(0xffffffffu, myidx, i + 1);
            int s2 = __shfl_sync(0xffffffffu, myidx, i + 2);
            int s3 = __shfl_sync(0xffffffffu, myidx, i + 3);
            uint4 k0 = Kf[(size_t)s0 * 32 + lane];
            uint4 k1 = Kf[(size_t)s1 * 32 + lane];
            uint4 k2 = Kf[(size_t)s2 * 32 + lane];
            uint4 k3 = Kf[(size_t)s3 * 32 + lane];
            uint4 v0 = Vf[(size_t)s0 * 32 + lane];
            uint4 v1 = Vf[(size_t)s1 * 32 + lane];
            uint4 v2 = Vf[(size_t)s2 * 32 + lane];
            uint4 v3 = Vf[(size_t)s3 * 32 + lane];
            float d0 = dot8(qv, k0);
            float d1 = dot8(qv, k1);
            float d2 = dot8(qv, k2);
            float d3 = dot8(qv, k3);
            d0 += __shfl_xor_sync(0xffffffffu, d0, 1);
            d0 += __shfl_xor_sync(0xffffffffu, d0, 2);
            d1 += __shfl_xor_sync(0xffffffffu, d1, 1);
            d1 += __shfl_xor_sync(0xffffffffu, d1, 2);
            d2 += __shfl_xor_sync(0xffffffffu, d2, 1);
            d2 += __shfl_xor_sync(0xffffffffu, d2, 2);
            d3 += __shfl_xor_sync(0xffffffffu, d3, 1);
            d3 += __shfl_xor_sync(0xffffffffu, d3, 2);
            d0 *= scale; d1 *= scale; d2 *= scale; d3 *= scale;
            float mn = fmaxf(m, fmaxf(fmaxf(d0, d1), fmaxf(d2, d3)));
            float c  = __expf(m - mn);
            float r0 = __expf(d0 - mn);
            float r1 = __expf(d1 - mn);
            float r2 = __expf(d2 - mn);
            float r3 = __expf(d3 - mn);
            float vv0[8], vv1[8], vv2[8], vv3[8];
            unpack8(v0, vv0); unpack8(v1, vv1);
            unpack8(v2, vv2); unpack8(v3, vv3);
            #pragma unroll
            for (int j = 0; j < 8; j++)
                a[j] = a[j] * c + r0 * vv0[j] + r1 * vv1[j] + r2 * vv2[j] + r3 * vv3[j];
            ssum = ssum * c + r0 + r1 + r2 + r3;
            m = mn;
        }
        for (; i < n; i++) {
            int s = __shfl_sync(0xffffffffu, myidx, i);
            uint4 ku = Kf[(size_t)s * 32 + lane];
            uint4 vu = Vf[(size_t)s * 32 + lane];
            float d = dot8(qv, ku);
            d += __shfl_xor_sync(0xffffffffu, d, 1);
            d += __shfl_xor_sync(0xffffffffu, d, 2);
            d *= scale;
            float mn = fmaxf(m, d);
            float c = __expf(m - mn);
            float r = __expf(d - mn);
            float vv[8];
            unpack8(vu, vv);
            #pragma unroll
            for (int j = 0; j < 8; j++) a[j] = a[j] * c + r * vv[j];
            ssum = ssum * c + r;
            m = mn;
        }
    }

    float inv = 1.0f / fmaxf(ssum, 1e-8f);
    float gsc = ssum * inv;
    float gv[8];
    unpack8(((const uint4*)(g_Gf_h + (size_t)q * DD))[lane], gv);
    float o[8];
    #pragma unroll
    for (int j = 0; j < 8; j++) o[j] = a[j] * inv + gv[j] * gsc;
    __half2 h0 = __floats2half2_rn(o[0], o[1]);
    __half2 h1 = __floats2half2_rn(o[2], o[3]);
    __half2 h2 = __floats2half2_rn(o[4], o[5]);
    __half2 h3 = __floats2half2_rn(o[6], o[7]);
    uint4 u;
    u.x = *(unsigned*)&h0; u.y = *(unsigned*)&h1;
    u.z = *(unsigned*)&h2; u.w = *(unsigned*)&h3;
    ((uint4*)(g_out_h + (size_t)q * DD))[lane] = u;
}

// ---------------- host ----------------
template <typename T>
static T* symp(const void* sym) {
    void* p = nullptr;
    cudaGetSymbolAddress(&p, sym);
    return (T*)p;
}

#define SMEM_H64(BM) ((2 * (BM) * 72 + 2 * 64 * 136) * (int)sizeof(__half))
#define SMEM_KVF (2 * 64 * 36 * 4 + 64 * 40 * 2 + 2 * 32 * 136 * 2)

struct Ctx {
    cudaStream_t s1, s2;
    cudaEvent_t evRoot, evKV, evG;
    Ctx() {
        cudaStreamCreateWithFlags(&s1, cudaStreamNonBlocking);
        cudaStreamCreateWithFlags(&s2, cudaStreamNonBlocking);
        cudaEventCreateWithFlags(&evRoot, cudaEventDisableTiming);
        cudaEventCreateWithFlags(&evKV, cudaEventDisableTiming);
        cudaEventCreateWithFlags(&evG, cudaEventDisableTiming);
        cudaFuncSetAttribute((const void*)k_hgemm_kvf,
            cudaFuncAttributeMaxDynamicSharedMemorySize, SMEM_KVF);
        cudaFuncSetAttribute((const void*)k_hgemm<64, false, false, false, true>,
            cudaFuncAttributeMaxDynamicSharedMemorySize, SMEM_H64(64));
        cudaFuncSetAttribute((const void*)k_hgemm<64, true, true, false, true>,
            cudaFuncAttributeMaxDynamicSharedMemorySize, SMEM_H64(64));
        cudaFuncSetAttribute((const void*)k_hgemm<64, true, false, true, false>,
            cudaFuncAttributeMaxDynamicSharedMemorySize, SMEM_H64(64));
    }
};

extern "C" void kernel_launch(void* const* d_in, const int* in_sizes, int n_in,
                              void* d_out, int out_size) {
    const float* query_tokens  = (const float*)d_in[0];
    const float* query_pos     = (const float*)d_in[1];
    const float* support_feats = (const float*)d_in[2];
    const float* support_pos   = (const float*)d_in[3];
    const float* Wq   = (const float*)d_in[4];
    const float* Wk   = (const float*)d_in[5];
    const float* Wv   = (const float*)d_in[6];
    const float* Wg   = (const float*)d_in[7];
    const float* Wo   = (const float*)d_in[8];
    const float* bo   = (const float*)d_in[9];
    const float* log_tau = (const float*)d_in[10];
    const float* ln1_g = (const float*)d_in[11];
    const float* ln1_b = (const float*)d_in[12];
    const float* ln2_g = (const float*)d_in[13];
    const float* ln2_b = (const float*)d_in[14];
    const float* Wf1  = (const float*)d_in[15];
    const float* bf1  = (const float*)d_in[16];
    const float* Wf2  = (const float*)d_in[17];
    const float* bf2  = (const float*)d_in[18];
    const float* Gw1  = (const float*)d_in[19];
    const float* Gb1  = (const float*)d_in[20];
    const float* Gw2  = (const float*)d_in[21];
    const float* Gb2  = (const float*)d_in[22];
    const int* q_idx  = (const int*)d_in[23];
    const int* s_idx  = (const int*)d_in[24];
    float* out = (float*)d_out;

    float*  p_raw   = symp<float>(g_raw);
    float*  p_x     = symp<float>(g_x);
    __half* p_qt    = symp<__half>(g_qt_h);
    __half* p_geoh  = symp<__half>(g_geoh_h);
    __half* p_geo   = symp<__half>(g_geo_h);
    __half* p_Qf    = symp<__half>(g_Qf_h);
    __half* p_Kf    = symp<__half>(g_Kf_h);
    __half* p_Vf    = symp<__half>(g_Vf_h);
    __half* p_Gf    = symp<__half>(g_Gf_h);
    __half* p_outh  = symp<__half>(g_out_h);
    __half* p_h1    = symp<__half>(g_h1_h);
    __half* p_Wq    = symp<__half>(g_Wq_h);
    __half* p_Wk    = symp<__half>(g_Wk_h);
    __half* p_Wv    = symp<__half>(g_Wv_h);
    __half* p_Wg    = symp<__half>(g_Wg_h);
    __half* p_Wo    = symp<__half>(g_Wo_h);
    __half* p_Wf1   = symp<__half>(g_Wf1_h);
    __half* p_Wf2   = symp<__half>(g_Wf2_h);
    __half* p_Gw2   = symp<__half>(g_Gw2_h);

    static Ctx ctx;

    // all weight converts in one launch, pre-fork
    CvtJobs jobs;
    jobs.src[0] = Wq;  jobs.dst[0] = p_Wq;  jobs.n4[0] = DD * DD / 4;
    jobs.src[1] = Wk;  jobs.dst[1] = p_Wk;  jobs.n4[1] = DD * DD / 4;
    jobs.src[2] = Wv;  jobs.dst[2] = p_Wv;  jobs.n4[2] = DD * DD / 4;
    jobs.src[3] = Wo;  jobs.dst[3] = p_Wo;  jobs.n4[3] = DD * DD / 4;
    jobs.src[4] = Wg;  jobs.dst[4] = p_Wg;  jobs.n4[4] = NGEO * DD / 4;
    jobs.src[5] = Gw2; jobs.dst[5] = p_Gw2; jobs.n4[5] = NGEO * NGEO / 4;
    jobs.src[6] = Wf1; jobs.dst[6] = p_Wf1; jobs.n4[6] = DD * NFFN / 4;
    jobs.src[7] = Wf2; jobs.dst[7] = p_Wf2; jobs.n4[7] = NFFN * DD / 4;
    k_cvt_all<<<dim3(DD * NFFN / 4 / 256, 8), 256>>>(jobs);

    // fork
    cudaEventRecord(ctx.evRoot, 0);
    cudaStreamWaitEvent(ctx.s1, ctx.evRoot, 0);
    cudaStreamWaitEvent(ctx.s2, ctx.evRoot, 0);

    // s1: merged K/V projection (A converted in-kernel)
    k_hgemm_kvf<<<dim3(DD / 128, NS / 64, 2), 256, SMEM_KVF, ctx.s1>>>(
        support_feats, p_Wk, p_Wv, p_Kf, p_Vf, DD, DD);
    cudaEventRecord(ctx.evKV, ctx.s1);

    // s2: geo chain
    k_bounds<<<NE / 256, 256, 0, ctx.s2>>>(q_idx);
    k_geostats<<<NQ / 8, 256, 0, ctx.s2>>>(query_pos, support_pos, s_idx);
    k_gemm12<<<dim3(NGEO / 64, NQ / 64), 256, 0, ctx.s2>>>(
        p_raw, Gw1, Gb1, p_geoh, NQ, NGEO, 12);
    k_hgemm<64, true, true, false, true><<<dim3(NGEO / 128, NQ / 64), 256, SMEM_H64(64), ctx.s2>>>(
        p_geoh, p_Gw2, Gb2, nullptr, p_geo, NGEO, NGEO);
    k_hgemm<64, false, false, false, true><<<dim3(DD / 128, NQ / 64), 256, SMEM_H64(64), ctx.s2>>>(
        p_geo, p_Wg, nullptr, nullptr, p_Gf, DD, NGEO);
    cudaEventRecord(ctx.evG, ctx.s2);

    // s0 (default): query chain
    k_ln<<<NQ / 8, 256>>>(query_tokens, ln1_g, ln1_b, p_qt);
    k_hgemm<64, false, false, false, true><<<dim3(DD / 128, NQ / 64), 256, SMEM_H64(64)>>>(
        p_qt, p_Wq, nullptr, nullptr, p_Qf, DD, DD);

    // join, fused edge attention
    cudaStreamWaitEvent(0, ctx.evKV, 0);
    cudaStreamWaitEvent(0, ctx.evG, 0);
    k_attn<<<NQ / 8, 256>>>(s_idx, log_tau);

    // tail
    k_hgemm<64, true, false, true, false><<<dim3(DD / 128, NQ / 64), 256, SMEM_H64(64)>>>(
        p_outh, p_Wo, bo, query_tokens, p_x, DD, DD);
    k_ln<<<NQ / 8, 256>>>(p_x, ln2_g, ln2_b, p_qt);
    k_hgemm<64, true, true, false, true><<<dim3(NFFN / 128, NQ / 64), 256, SMEM_H64(64)>>>(
        p_qt, p_Wf1, bf1, nullptr, p_h1, NFFN, DD);
    k_hgemm<64, true, false, true, false><<<dim3(DD / 128, NQ / 64), 256, SMEM_H64(64)>>>(
        p_h1, p_Wf2, bf2, p_x, out, DD, NFFN);
}